// round 2
// baseline (speedup 1.0000x reference)
#include <cuda_runtime.h>

#define B_  2
#define S_  2048
#define D_  1024
#define H_  16
#define DH_ 64

// Scratch (allocation-free rule: device globals)
__device__ float g_q[(size_t)B_ * S_ * D_];
__device__ float g_k[(size_t)B_ * S_ * D_];
__device__ float g_v[(size_t)B_ * S_ * D_];
__device__ float g_ctx[(size_t)B_ * S_ * D_];

// ---------------------------------------------------------------------------
// SGEMM: C[M,N] = A[M,K] @ W[N,K]^T + bias[N]
// Block tile 128x128, K-tile 16, 256 threads, 8x8 per thread.
// ---------------------------------------------------------------------------
__global__ void __launch_bounds__(256) sgemm_bias_kernel(
    const float* __restrict__ A, const float* __restrict__ W,
    const float* __restrict__ bias, float* __restrict__ C,
    int M, int N, int K)
{
    __shared__ float As[16][128];
    __shared__ float Bs[16][128];

    const int tid = threadIdx.x;
    const int tx = tid & 15, ty = tid >> 4;
    const int bm = blockIdx.y * 128, bn = blockIdx.x * 128;
    const int lr = tid >> 2;           // 0..63
    const int lc = (tid & 3) << 2;     // 0,4,8,12

    const float* Ap = A + (size_t)(bm + lr) * K + lc;
    const float* Wp = W + (size_t)(bn + lr) * K + lc;

    float acc[8][8];
#pragma unroll
    for (int i = 0; i < 8; i++)
#pragma unroll
        for (int j = 0; j < 8; j++) acc[i][j] = 0.f;

    for (int kt = 0; kt < K; kt += 16) {
        float4 a0 = *(const float4*)(Ap + kt);
        float4 a1 = *(const float4*)(Ap + (size_t)64 * K + kt);
        float4 w0 = *(const float4*)(Wp + kt);
        float4 w1 = *(const float4*)(Wp + (size_t)64 * K + kt);
        __syncthreads();
        As[lc + 0][lr] = a0.x; As[lc + 1][lr] = a0.y;
        As[lc + 2][lr] = a0.z; As[lc + 3][lr] = a0.w;
        As[lc + 0][lr + 64] = a1.x; As[lc + 1][lr + 64] = a1.y;
        As[lc + 2][lr + 64] = a1.z; As[lc + 3][lr + 64] = a1.w;
        Bs[lc + 0][lr] = w0.x; Bs[lc + 1][lr] = w0.y;
        Bs[lc + 2][lr] = w0.z; Bs[lc + 3][lr] = w0.w;
        Bs[lc + 0][lr + 64] = w1.x; Bs[lc + 1][lr + 64] = w1.y;
        Bs[lc + 2][lr + 64] = w1.z; Bs[lc + 3][lr + 64] = w1.w;
        __syncthreads();
#pragma unroll
        for (int kk = 0; kk < 16; kk++) {
            float a[8], b[8];
            *(float4*)&a[0] = *(const float4*)&As[kk][ty * 8];
            *(float4*)&a[4] = *(const float4*)&As[kk][ty * 8 + 4];
            *(float4*)&b[0] = *(const float4*)&Bs[kk][tx * 8];
            *(float4*)&b[4] = *(const float4*)&Bs[kk][tx * 8 + 4];
#pragma unroll
            for (int i = 0; i < 8; i++)
#pragma unroll
                for (int j = 0; j < 8; j++)
                    acc[i][j] = fmaf(a[i], b[j], acc[i][j]);
        }
    }

    const int row0 = bm + ty * 8;
    const int col0 = bn + tx * 8;
    float bv[8];
    *(float4*)&bv[0] = *(const float4*)&bias[col0];
    *(float4*)&bv[4] = *(const float4*)&bias[col0 + 4];
#pragma unroll
    for (int i = 0; i < 8; i++) {
        float4 o0 = make_float4(acc[i][0] + bv[0], acc[i][1] + bv[1],
                                acc[i][2] + bv[2], acc[i][3] + bv[3]);
        float4 o1 = make_float4(acc[i][4] + bv[4], acc[i][5] + bv[5],
                                acc[i][6] + bv[6], acc[i][7] + bv[7]);
        *(float4*)&C[(size_t)(row0 + i) * N + col0] = o0;
        *(float4*)&C[(size_t)(row0 + i) * N + col0 + 4] = o1;
    }
}

// ---------------------------------------------------------------------------
// Flash attention: one CTA = (batch b, head h, 64 query rows).
// Streams 64-row KV tiles with online softmax. fp32.
// Shared: Qt (Q transposed [k][r]), KP (K transposed, swizzled; later reused
// for P transposed, swizzled), Vs (V natural [j][c]). 48 KB total.
// Thread (tx,ty) owns q-rows ty*4..+3; score cols / output cols tx*4..+3.
// ---------------------------------------------------------------------------
__global__ void __launch_bounds__(256) flash_attn_kernel(
    const int* __restrict__ mask, float* __restrict__ Octx)
{
    __shared__ float Qt[64 * 64];
    __shared__ float KP[64 * 64];
    __shared__ float Vs[64 * 64];

    const int tid = threadIdx.x;
    const int tx = tid & 15, ty = tid >> 4;
    const int h = blockIdx.x, qt = blockIdx.y, b = blockIdx.z;
    const int qbase = qt * 64;
    const int r0 = ty * 4, c0 = tx * 4;

    const float* Qg = g_q + (size_t)b * S_ * D_ + (size_t)h * DH_;
    const float* Kg = g_k + (size_t)b * S_ * D_ + (size_t)h * DH_;
    const float* Vg = g_v + (size_t)b * S_ * D_ + (size_t)h * DH_;

    // Load Q tile transposed: Qt[k][r]
#pragma unroll
    for (int i = 0; i < 4; i++) {
        int f = tid + i * 256;
        int r  = f >> 4;
        int k4 = (f & 15) << 2;
        float4 qv = *(const float4*)&Qg[(size_t)(qbase + r) * D_ + k4];
        Qt[(k4 + 0) * 64 + r] = qv.x;
        Qt[(k4 + 1) * 64 + r] = qv.y;
        Qt[(k4 + 2) * 64 + r] = qv.z;
        Qt[(k4 + 3) * 64 + r] = qv.w;
    }

    float m_i[4], l_i[4], Oacc[4][4];
#pragma unroll
    for (int i = 0; i < 4; i++) {
        m_i[i] = -1e30f;
        l_i[i] = 0.f;
#pragma unroll
        for (int j = 0; j < 4; j++) Oacc[i][j] = 0.f;
    }

    for (int t = 0; t < S_ / 64; t++) {
        const int kvb = t * 64;
        __syncthreads();   // previous iteration finished reading KP/Vs

        // Load K tile transposed+swizzled: element (row k, col c) stored at
        // k*64 + (((c>>2) ^ (k&15))<<2 | (c&3)); V tile natural.
#pragma unroll
        for (int i = 0; i < 4; i++) {
            int f = tid + i * 256;
            int c  = f >> 4;
            int k4 = (f & 15) << 2;
            float4 kv = *(const float4*)&Kg[(size_t)(kvb + c) * D_ + k4];
            int ch = c >> 2, cl = c & 3;
            KP[(k4 + 0) * 64 + (((ch ^ ((k4 + 0) & 15)) << 2) | cl)] = kv.x;
            KP[(k4 + 1) * 64 + (((ch ^ ((k4 + 1) & 15)) << 2) | cl)] = kv.y;
            KP[(k4 + 2) * 64 + (((ch ^ ((k4 + 2) & 15)) << 2) | cl)] = kv.z;
            KP[(k4 + 3) * 64 + (((ch ^ ((k4 + 3) & 15)) << 2) | cl)] = kv.w;
            float4 vv = *(const float4*)&Vg[(size_t)(kvb + c) * D_ + k4];
            *(float4*)&Vs[c * 64 + k4] = vv;
        }
        __syncthreads();

        // S = Q @ K^T  (thread's 4x4 patch)
        float s[4][4];
#pragma unroll
        for (int i = 0; i < 4; i++)
#pragma unroll
            for (int j = 0; j < 4; j++) s[i][j] = 0.f;

#pragma unroll 8
        for (int kk = 0; kk < 64; kk++) {
            float4 aq = *(const float4*)&Qt[kk * 64 + r0];
            float4 bk = *(const float4*)&KP[kk * 64 + ((tx ^ (kk & 15)) << 2)];
            float a[4] = {aq.x, aq.y, aq.z, aq.w};
            float k_[4] = {bk.x, bk.y, bk.z, bk.w};
#pragma unroll
            for (int i = 0; i < 4; i++)
#pragma unroll
                for (int j = 0; j < 4; j++)
                    s[i][j] = fmaf(a[i], k_[j], s[i][j]);
        }

        // Mask + scale + online softmax (row stats reduced over the 16-lane
        // tx group via butterfly; xor offsets <=8 stay inside the half-warp).
        const float scale = 0.125f;  // 1/sqrt(64)
#pragma unroll
        for (int i = 0; i < 4; i++) {
            const int4 mm = *(const int4*)&mask[((size_t)b * S_ + qbase + r0 + i) * S_ + kvb + c0];
            s[i][0] = mm.x ? s[i][0] * scale : -1e9f;
            s[i][1] = mm.y ? s[i][1] * scale : -1e9f;
            s[i][2] = mm.z ? s[i][2] * scale : -1e9f;
            s[i][3] = mm.w ? s[i][3] * scale : -1e9f;
            float mx = fmaxf(fmaxf(s[i][0], s[i][1]), fmaxf(s[i][2], s[i][3]));
            mx = fmaxf(mx, __shfl_xor_sync(0xffffffffu, mx, 1));
            mx = fmaxf(mx, __shfl_xor_sync(0xffffffffu, mx, 2));
            mx = fmaxf(mx, __shfl_xor_sync(0xffffffffu, mx, 4));
            mx = fmaxf(mx, __shfl_xor_sync(0xffffffffu, mx, 8));
            float mnew = fmaxf(m_i[i], mx);
            float alpha = __expf(m_i[i] - mnew);
            m_i[i] = mnew;
            float rs = 0.f;
#pragma unroll
            for (int j = 0; j < 4; j++) {
                s[i][j] = __expf(s[i][j] - mnew);
                rs += s[i][j];
            }
            rs += __shfl_xor_sync(0xffffffffu, rs, 1);
            rs += __shfl_xor_sync(0xffffffffu, rs, 2);
            rs += __shfl_xor_sync(0xffffffffu, rs, 4);
            rs += __shfl_xor_sync(0xffffffffu, rs, 8);
            l_i[i] = l_i[i] * alpha + rs;
#pragma unroll
            for (int j = 0; j < 4; j++) Oacc[i][j] *= alpha;
        }

        __syncthreads();   // done reading KP as K
        // Store P transposed+swizzled into KP: Pt[j][r], rows r0..r0+3 -> float4
#pragma unroll
        for (int jj = 0; jj < 4; jj++) {
            int j = c0 + jj;
            float4 pv = make_float4(s[0][jj], s[1][jj], s[2][jj], s[3][jj]);
            *(float4*)&KP[j * 64 + ((ty ^ (j & 15)) << 2)] = pv;
        }
        __syncthreads();

        // O += P @ V
#pragma unroll 8
        for (int j = 0; j < 64; j++) {
            float4 ap = *(const float4*)&KP[j * 64 + ((ty ^ (j & 15)) << 2)];
            float4 vv = *(const float4*)&Vs[j * 64 + c0];
            float a[4] = {ap.x, ap.y, ap.z, ap.w};
            float v[4] = {vv.x, vv.y, vv.z, vv.w};
#pragma unroll
            for (int i = 0; i < 4; i++)
#pragma unroll
                for (int cc = 0; cc < 4; cc++)
                    Oacc[i][cc] = fmaf(a[i], v[cc], Oacc[i][cc]);
        }
    }

    float* Og = Octx + (size_t)b * S_ * D_ + (size_t)h * DH_;
#pragma unroll
    for (int i = 0; i < 4; i++) {
        float inv = 1.f / l_i[i];
        float4 o = make_float4(Oacc[i][0] * inv, Oacc[i][1] * inv,
                               Oacc[i][2] * inv, Oacc[i][3] * inv);
        *(float4*)&Og[(size_t)(qbase + r0 + i) * D_ + c0] = o;
    }
}

// ---------------------------------------------------------------------------
extern "C" void kernel_launch(void* const* d_in, const int* in_sizes, int n_in,
                              void* d_out, int out_size)
{
    (void)in_sizes; (void)n_in; (void)out_size;
    const float* q_tok = (const float*)d_in[0];
    const float* kv_tok = (const float*)d_in[1];
    const int*   mask   = (const int*)d_in[2];
    const float* Wq = (const float*)d_in[3];
    const float* bq = (const float*)d_in[4];
    const float* Wk = (const float*)d_in[5];
    const float* bk = (const float*)d_in[6];
    const float* Wv = (const float*)d_in[7];
    const float* bv = (const float*)d_in[8];
    const float* Wo = (const float*)d_in[9];
    const float* bo = (const float*)d_in[10];
    float* out = (float*)d_out;

    float *qp, *kp, *vp, *cp;
    cudaGetSymbolAddress((void**)&qp, g_q);
    cudaGetSymbolAddress((void**)&kp, g_k);
    cudaGetSymbolAddress((void**)&vp, g_v);
    cudaGetSymbolAddress((void**)&cp, g_ctx);

    const int M = B_ * S_;
    dim3 gblock(256);
    dim3 ggrid(D_ / 128, M / 128);

    sgemm_bias_kernel<<<ggrid, gblock>>>(q_tok,  Wq, bq, qp, M, D_, D_);
    sgemm_bias_kernel<<<ggrid, gblock>>>(kv_tok, Wk, bk, kp, M, D_, D_);
    sgemm_bias_kernel<<<ggrid, gblock>>>(kv_tok, Wv, bv, vp, M, D_, D_);

    dim3 fgrid(H_, S_ / 64, B_);
    flash_attn_kernel<<<fgrid, 256>>>(mask, cp);

    sgemm_bias_kernel<<<ggrid, gblock>>>(cp, Wo, bo, out, M, D_, D_);
}

// round 4
// speedup vs baseline: 1.3231x; 1.3231x over previous
#include <cuda_runtime.h>
#include <cuda_bf16.h>
#include <cstdint>

#define B_  2
#define S_  2048
#define D_  1024
#define H_  16
#define DH_ 64
#define M_  (B_*S_)   // 4096

// ------------------------------ scratch (allocation-free rule) -------------
__device__ float g_q[(size_t)M_ * D_];
__device__ float g_k[(size_t)M_ * D_];
__device__ float g_v[(size_t)M_ * D_];
__device__ float g_ctx[(size_t)M_ * D_];

__device__ __nv_bfloat16 g_ah[(size_t)M_ * D_];   // q tokens hi
__device__ __nv_bfloat16 g_al[(size_t)M_ * D_];   // q tokens lo
__device__ __nv_bfloat16 g_bh[(size_t)M_ * D_];   // kv tokens hi
__device__ __nv_bfloat16 g_bl[(size_t)M_ * D_];   // kv tokens lo
__device__ __nv_bfloat16 g_ch[(size_t)M_ * D_];   // ctx hi
__device__ __nv_bfloat16 g_cl[(size_t)M_ * D_];   // ctx lo
__device__ __nv_bfloat16 g_wh[(size_t)4 * D_ * D_];  // Wq,Wk,Wv,Wo hi
__device__ __nv_bfloat16 g_wl[(size_t)4 * D_ * D_];  // lo

// ------------------------------ helpers ------------------------------------
__device__ __forceinline__ uint32_t smem_u32(const void* p) {
    uint32_t a;
    asm("{ .reg .u64 t; cvta.to.shared.u64 t, %1; cvt.u32.u64 %0, t; }"
        : "=r"(a) : "l"(p));
    return a;
}

#define LDSM4(r, addr) \
    asm volatile("ldmatrix.sync.aligned.m8n8.x4.shared.b16 {%0,%1,%2,%3}, [%4];" \
        : "=r"((r)[0]), "=r"((r)[1]), "=r"((r)[2]), "=r"((r)[3]) : "r"(addr))

#define MMA16816(d, a, b0, b1) \
    asm volatile("mma.sync.aligned.m16n8k16.row.col.f32.bf16.bf16.f32 " \
        "{%0,%1,%2,%3}, {%4,%5,%6,%7}, {%8,%9}, {%0,%1,%2,%3};" \
        : "+f"((d)[0]), "+f"((d)[1]), "+f"((d)[2]), "+f"((d)[3]) \
        : "r"((a)[0]), "r"((a)[1]), "r"((a)[2]), "r"((a)[3]), "r"(b0), "r"(b1))

// ------------------------------ split fp32 -> bf16 hi/lo -------------------
__global__ void __launch_bounds__(256) split_kernel(
    const float* __restrict__ x, __nv_bfloat16* __restrict__ hi,
    __nv_bfloat16* __restrict__ lo, int n)
{
    int i = (blockIdx.x * 256 + threadIdx.x) * 4;
    if (i >= n) return;
    float4 v = *(const float4*)(x + i);
    float a[4] = {v.x, v.y, v.z, v.w};
    __nv_bfloat16 h[4], l[4];
#pragma unroll
    for (int j = 0; j < 4; j++) {
        h[j] = __float2bfloat16(a[j]);
        l[j] = __float2bfloat16(a[j] - __bfloat162float(h[j]));
    }
    *(uint2*)(hi + i) = *(uint2*)h;
    *(uint2*)(lo + i) = *(uint2*)l;
}

// ------------------------------ HMMA GEMM ----------------------------------
// C[M,1024] = (Ah+Al) @ (Wh+Wl)^T + bias, via D += Ah*Wh + Ah*Wl + Al*Wh.
// CTA: 128x128 tile, 8 warps (2m x 4n), warp tile 64x32. K-tile 64.
// Smem: 4 matrices of 128 rows x 64 bf16 (128 B/row), XOR-swizzled so both
// gmem stores (uint4) and ldmatrix reads are bank-conflict-free.
#define GS_AH 0
#define GS_AL 16384
#define GS_WH 32768
#define GS_WL 49152
#define GEMM_SMEM 65536

__global__ void __launch_bounds__(256) gemm_mma_kernel(
    const __nv_bfloat16* __restrict__ Ah, const __nv_bfloat16* __restrict__ Al,
    const __nv_bfloat16* __restrict__ Wh, const __nv_bfloat16* __restrict__ Wl,
    const float* __restrict__ bias, float* __restrict__ C)
{
    extern __shared__ char sm[];
    const uint32_t sb = smem_u32(sm);
    const int tid = threadIdx.x;
    const int wid = tid >> 5, lane = tid & 31;
    const int wm = wid >> 2, wn = wid & 3;   // 2 x 4 warp grid
    const int bm = blockIdx.y * 128, bn = blockIdx.x * 128;

    // ldmatrix lane address components (x4: four 8x8 mats in m/k order)
    const int lrow = (lane & 7) + ((lane >> 3) & 1) * 8;
    const int lcb  = lane >> 4;

    float acc[4][4][4];
#pragma unroll
    for (int mt = 0; mt < 4; mt++)
#pragma unroll
        for (int nt = 0; nt < 4; nt++)
#pragma unroll
            for (int e = 0; e < 4; e++) acc[mt][nt][e] = 0.f;

    for (int t = 0; t < 16; t++) {
        __syncthreads();   // previous compute done reading smem
#pragma unroll
        for (int i = 0; i < 4; i++) {
            int f = tid + i * 256;          // 0..1023 : 128 rows x 8 chunks
            int r = f >> 3;
            int cb = f & 7;                 // 16B chunk within row
            size_t gA = (size_t)(bm + r) * D_ + (size_t)t * 64 + cb * 8;
            size_t gW = (size_t)(bn + r) * D_ + (size_t)t * 64 + cb * 8;
            uint32_t so = r * 128 + ((cb ^ (r & 7)) << 4);
            *(uint4*)(sm + GS_AH + so) = *(const uint4*)(Ah + gA);
            *(uint4*)(sm + GS_AL + so) = *(const uint4*)(Al + gA);
            *(uint4*)(sm + GS_WH + so) = *(const uint4*)(Wh + gW);
            *(uint4*)(sm + GS_WL + so) = *(const uint4*)(Wl + gW);
        }
        __syncthreads();

#pragma unroll
        for (int ks = 0; ks < 4; ks++) {
            uint32_t ah[4][4], al[4][4], bh[2][4], bl[2][4];
            const int cb = ks * 2 + lcb;
#pragma unroll
            for (int mt = 0; mt < 4; mt++) {
                int r = wm * 64 + mt * 16 + lrow;
                uint32_t ad = sb + r * 128 + ((cb ^ (r & 7)) << 4);
                LDSM4(ah[mt], ad + GS_AH);
                LDSM4(al[mt], ad + GS_AL);
            }
#pragma unroll
            for (int p = 0; p < 2; p++) {
                int r = wn * 32 + p * 16 + lrow;
                uint32_t ad = sb + r * 128 + ((cb ^ (r & 7)) << 4);
                LDSM4(bh[p], ad + GS_WH);
                LDSM4(bl[p], ad + GS_WL);
            }
#pragma unroll
            for (int mt = 0; mt < 4; mt++) {
#pragma unroll
                for (int nt = 0; nt < 4; nt++) {
                    const int p = nt >> 1, o = nt & 1;
                    MMA16816(acc[mt][nt], ah[mt], bh[p][o], bh[p][o + 2]);
                    MMA16816(acc[mt][nt], ah[mt], bl[p][o], bl[p][o + 2]);
                    MMA16816(acc[mt][nt], al[mt], bh[p][o], bh[p][o + 2]);
                }
            }
        }
    }

    // Epilogue: c0,c1 -> (row g, col tig*2,+1); c2,c3 -> row g+8
    const int g = lane >> 2, tig = lane & 3;
#pragma unroll
    for (int mt = 0; mt < 4; mt++) {
#pragma unroll
        for (int nt = 0; nt < 4; nt++) {
            int row = bm + wm * 64 + mt * 16 + g;
            int col = bn + wn * 32 + nt * 8 + tig * 2;
            float2 bv = *(const float2*)&bias[col];
            float2 o0 = make_float2(acc[mt][nt][0] + bv.x, acc[mt][nt][1] + bv.y);
            float2 o1 = make_float2(acc[mt][nt][2] + bv.x, acc[mt][nt][3] + bv.y);
            *(float2*)(C + (size_t)row * D_ + col) = o0;
            *(float2*)(C + (size_t)(row + 8) * D_ + col) = o1;
        }
    }
}

// ---------------------------------------------------------------------------
// Flash attention (unchanged — known good)
// ---------------------------------------------------------------------------
__global__ void __launch_bounds__(256) flash_attn_kernel(
    const int* __restrict__ mask, float* __restrict__ Octx)
{
    __shared__ float Qt[64 * 64];
    __shared__ float KP[64 * 64];
    __shared__ float Vs[64 * 64];

    const int tid = threadIdx.x;
    const int tx = tid & 15, ty = tid >> 4;
    const int h = blockIdx.x, qt = blockIdx.y, b = blockIdx.z;
    const int qbase = qt * 64;
    const int r0 = ty * 4, c0 = tx * 4;

    const float* Qg = g_q + (size_t)b * S_ * D_ + (size_t)h * DH_;
    const float* Kg = g_k + (size_t)b * S_ * D_ + (size_t)h * DH_;
    const float* Vg = g_v + (size_t)b * S_ * D_ + (size_t)h * DH_;

#pragma unroll
    for (int i = 0; i < 4; i++) {
        int f = tid + i * 256;
        int r  = f >> 4;
        int k4 = (f & 15) << 2;
        float4 qv = *(const float4*)&Qg[(size_t)(qbase + r) * D_ + k4];
        Qt[(k4 + 0) * 64 + r] = qv.x;
        Qt[(k4 + 1) * 64 + r] = qv.y;
        Qt[(k4 + 2) * 64 + r] = qv.z;
        Qt[(k4 + 3) * 64 + r] = qv.w;
    }

    float m_i[4], l_i[4], Oacc[4][4];
#pragma unroll
    for (int i = 0; i < 4; i++) {
        m_i[i] = -1e30f;
        l_i[i] = 0.f;
#pragma unroll
        for (int j = 0; j < 4; j++) Oacc[i][j] = 0.f;
    }

    for (int t = 0; t < S_ / 64; t++) {
        const int kvb = t * 64;
        __syncthreads();

#pragma unroll
        for (int i = 0; i < 4; i++) {
            int f = tid + i * 256;
            int c  = f >> 4;
            int k4 = (f & 15) << 2;
            float4 kv = *(const float4*)&Kg[(size_t)(kvb + c) * D_ + k4];
            int ch = c >> 2, cl = c & 3;
            KP[(k4 + 0) * 64 + (((ch ^ ((k4 + 0) & 15)) << 2) | cl)] = kv.x;
            KP[(k4 + 1) * 64 + (((ch ^ ((k4 + 1) & 15)) << 2) | cl)] = kv.y;
            KP[(k4 + 2) * 64 + (((ch ^ ((k4 + 2) & 15)) << 2) | cl)] = kv.z;
            KP[(k4 + 3) * 64 + (((ch ^ ((k4 + 3) & 15)) << 2) | cl)] = kv.w;
            float4 vv = *(const float4*)&Vg[(size_t)(kvb + c) * D_ + k4];
            *(float4*)&Vs[c * 64 + k4] = vv;
        }
        __syncthreads();

        float s[4][4];
#pragma unroll
        for (int i = 0; i < 4; i++)
#pragma unroll
            for (int j = 0; j < 4; j++) s[i][j] = 0.f;

#pragma unroll 8
        for (int kk = 0; kk < 64; kk++) {
            float4 aq = *(const float4*)&Qt[kk * 64 + r0];
            float4 bk = *(const float4*)&KP[kk * 64 + ((tx ^ (kk & 15)) << 2)];
            float a[4] = {aq.x, aq.y, aq.z, aq.w};
            float k_[4] = {bk.x, bk.y, bk.z, bk.w};
#pragma unroll
            for (int i = 0; i < 4; i++)
#pragma unroll
                for (int j = 0; j < 4; j++)
                    s[i][j] = fmaf(a[i], k_[j], s[i][j]);
        }

        const float scale = 0.125f;
#pragma unroll
        for (int i = 0; i < 4; i++) {
            const int4 mm = *(const int4*)&mask[((size_t)b * S_ + qbase + r0 + i) * S_ + kvb + c0];
            s[i][0] = mm.x ? s[i][0] * scale : -1e9f;
            s[i][1] = mm.y ? s[i][1] * scale : -1e9f;
            s[i][2] = mm.z ? s[i][2] * scale : -1e9f;
            s[i][3] = mm.w ? s[i][3] * scale : -1e9f;
            float mx = fmaxf(fmaxf(s[i][0], s[i][1]), fmaxf(s[i][2], s[i][3]));
            mx = fmaxf(mx, __shfl_xor_sync(0xffffffffu, mx, 1));
            mx = fmaxf(mx, __shfl_xor_sync(0xffffffffu, mx, 2));
            mx = fmaxf(mx, __shfl_xor_sync(0xffffffffu, mx, 4));
            mx = fmaxf(mx, __shfl_xor_sync(0xffffffffu, mx, 8));
            float mnew = fmaxf(m_i[i], mx);
            float alpha = __expf(m_i[i] - mnew);
            m_i[i] = mnew;
            float rs = 0.f;
#pragma unroll
            for (int j = 0; j < 4; j++) {
                s[i][j] = __expf(s[i][j] - mnew);
                rs += s[i][j];
            }
            rs += __shfl_xor_sync(0xffffffffu, rs, 1);
            rs += __shfl_xor_sync(0xffffffffu, rs, 2);
            rs += __shfl_xor_sync(0xffffffffu, rs, 4);
            rs += __shfl_xor_sync(0xffffffffu, rs, 8);
            l_i[i] = l_i[i] * alpha + rs;
#pragma unroll
            for (int j = 0; j < 4; j++) Oacc[i][j] *= alpha;
        }

        __syncthreads();
#pragma unroll
        for (int jj = 0; jj < 4; jj++) {
            int j = c0 + jj;
            float4 pv = make_float4(s[0][jj], s[1][jj], s[2][jj], s[3][jj]);
            *(float4*)&KP[j * 64 + ((ty ^ (j & 15)) << 2)] = pv;
        }
        __syncthreads();

#pragma unroll 8
        for (int j = 0; j < 64; j++) {
            float4 ap = *(const float4*)&KP[j * 64 + ((ty ^ (j & 15)) << 2)];
            float4 vv = *(const float4*)&Vs[j * 64 + c0];
            float a[4] = {ap.x, ap.y, ap.z, ap.w};
            float v[4] = {vv.x, vv.y, vv.z, vv.w};
#pragma unroll
            for (int i = 0; i < 4; i++)
#pragma unroll
                for (int cc = 0; cc < 4; cc++)
                    Oacc[i][cc] = fmaf(a[i], v[cc], Oacc[i][cc]);
        }
    }

    float* Og = Octx + (size_t)b * S_ * D_ + (size_t)h * DH_;
#pragma unroll
    for (int i = 0; i < 4; i++) {
        float inv = 1.f / l_i[i];
        float4 o = make_float4(Oacc[i][0] * inv, Oacc[i][1] * inv,
                               Oacc[i][2] * inv, Oacc[i][3] * inv);
        *(float4*)&Og[(size_t)(qbase + r0 + i) * D_ + c0] = o;
    }
}

// ---------------------------------------------------------------------------
extern "C" void kernel_launch(void* const* d_in, const int* in_sizes, int n_in,
                              void* d_out, int out_size)
{
    (void)in_sizes; (void)n_in; (void)out_size;
    const float* q_tok  = (const float*)d_in[0];
    const float* kv_tok = (const float*)d_in[1];
    const int*   mask   = (const int*)d_in[2];
    const float* Wq = (const float*)d_in[3];
    const float* bq = (const float*)d_in[4];
    const float* Wk = (const float*)d_in[5];
    const float* bk = (const float*)d_in[6];
    const float* Wv = (const float*)d_in[7];
    const float* bv = (const float*)d_in[8];
    const float* Wo = (const float*)d_in[9];
    const float* bo = (const float*)d_in[10];
    float* out = (float*)d_out;

    float *qp, *kp, *vp, *cp;
    cudaGetSymbolAddress((void**)&qp, g_q);
    cudaGetSymbolAddress((void**)&kp, g_k);
    cudaGetSymbolAddress((void**)&vp, g_v);
    cudaGetSymbolAddress((void**)&cp, g_ctx);

    __nv_bfloat16 *ah, *al, *bh, *bl, *ch, *cl, *wh, *wl;
    cudaGetSymbolAddress((void**)&ah, g_ah);
    cudaGetSymbolAddress((void**)&al, g_al);
    cudaGetSymbolAddress((void**)&bh, g_bh);
    cudaGetSymbolAddress((void**)&bl, g_bl);
    cudaGetSymbolAddress((void**)&ch, g_ch);
    cudaGetSymbolAddress((void**)&cl, g_cl);
    cudaGetSymbolAddress((void**)&wh, g_wh);
    cudaGetSymbolAddress((void**)&wl, g_wl);

    cudaFuncSetAttribute(gemm_mma_kernel,
                         cudaFuncAttributeMaxDynamicSharedMemorySize, GEMM_SMEM);

    const int nTok = M_ * D_;        // 4194304
    const int nW = D_ * D_;          // 1048576

    split_kernel<<<nTok / 1024, 256>>>(q_tok,  ah, al, nTok);
    split_kernel<<<nTok / 1024, 256>>>(kv_tok, bh, bl, nTok);
    split_kernel<<<nW / 1024, 256>>>(Wq, wh + 0 * (size_t)nW, wl + 0 * (size_t)nW, nW);
    split_kernel<<<nW / 1024, 256>>>(Wk, wh + 1 * (size_t)nW, wl + 1 * (size_t)nW, nW);
    split_kernel<<<nW / 1024, 256>>>(Wv, wh + 2 * (size_t)nW, wl + 2 * (size_t)nW, nW);
    split_kernel<<<nW / 1024, 256>>>(Wo, wh + 3 * (size_t)nW, wl + 3 * (size_t)nW, nW);

    dim3 ggrid(D_ / 128, M_ / 128);  // (8, 32)
    gemm_mma_kernel<<<ggrid, 256, GEMM_SMEM>>>(ah, al, wh + 0 * (size_t)nW, wl + 0 * (size_t)nW, bq, qp);
    gemm_mma_kernel<<<ggrid, 256, GEMM_SMEM>>>(bh, bl, wh + 1 * (size_t)nW, wl + 1 * (size_t)nW, bk, kp);
    gemm_mma_kernel<<<ggrid, 256, GEMM_SMEM>>>(bh, bl, wh + 2 * (size_t)nW, wl + 2 * (size_t)nW, bv, vp);

    dim3 fgrid(H_, S_ / 64, B_);
    flash_attn_kernel<<<fgrid, 256>>>(mask, cp);

    split_kernel<<<nTok / 1024, 256>>>(cp, ch, cl, nTok);
    gemm_mma_kernel<<<ggrid, 256, GEMM_SMEM>>>(ch, cl, wh + 3 * (size_t)nW, wl + 3 * (size_t)nW, bo, out);
}

// round 5
// speedup vs baseline: 2.4167x; 1.8266x over previous
#include <cuda_runtime.h>
#include <cuda_bf16.h>
#include <cstdint>

#define B_  2
#define S_  2048
#define D_  1024
#define H_  16
#define DH_ 64
#define M_  (B_*S_)   // 4096

// ------------------------------ scratch (allocation-free rule) -------------
__device__ __nv_bfloat16 g_ah[(size_t)M_ * D_];   // q tokens hi
__device__ __nv_bfloat16 g_al[(size_t)M_ * D_];   // q tokens lo
__device__ __nv_bfloat16 g_bh[(size_t)M_ * D_];   // kv tokens hi
__device__ __nv_bfloat16 g_bl[(size_t)M_ * D_];   // kv tokens lo
__device__ __nv_bfloat16 g_wh[(size_t)4 * D_ * D_];  // Wq,Wk,Wv,Wo hi
__device__ __nv_bfloat16 g_wl[(size_t)4 * D_ * D_];  // lo
__device__ __nv_bfloat16 g_qh[(size_t)M_ * D_];   // Q proj hi/lo
__device__ __nv_bfloat16 g_ql[(size_t)M_ * D_];
__device__ __nv_bfloat16 g_kh[(size_t)M_ * D_];
__device__ __nv_bfloat16 g_kl[(size_t)M_ * D_];
__device__ __nv_bfloat16 g_vh[(size_t)M_ * D_];
__device__ __nv_bfloat16 g_vl[(size_t)M_ * D_];
__device__ __nv_bfloat16 g_ch[(size_t)M_ * D_];   // ctx hi/lo
__device__ __nv_bfloat16 g_cl[(size_t)M_ * D_];

// ------------------------------ helpers ------------------------------------
__device__ __forceinline__ uint32_t smem_u32(const void* p) {
    uint32_t a;
    asm("{ .reg .u64 t; cvta.to.shared.u64 t, %1; cvt.u32.u64 %0, t; }"
        : "=r"(a) : "l"(p));
    return a;
}

#define LDSM4(r, addr) \
    asm volatile("ldmatrix.sync.aligned.m8n8.x4.shared.b16 {%0,%1,%2,%3}, [%4];" \
        : "=r"((r)[0]), "=r"((r)[1]), "=r"((r)[2]), "=r"((r)[3]) : "r"(addr))

#define LDSM4T(r, addr) \
    asm volatile("ldmatrix.sync.aligned.m8n8.x4.trans.shared.b16 {%0,%1,%2,%3}, [%4];" \
        : "=r"((r)[0]), "=r"((r)[1]), "=r"((r)[2]), "=r"((r)[3]) : "r"(addr))

#define MMA16816(d, a, b0, b1) \
    asm volatile("mma.sync.aligned.m16n8k16.row.col.f32.bf16.bf16.f32 " \
        "{%0,%1,%2,%3}, {%4,%5,%6,%7}, {%8,%9}, {%0,%1,%2,%3};" \
        : "+f"((d)[0]), "+f"((d)[1]), "+f"((d)[2]), "+f"((d)[3]) \
        : "r"((a)[0]), "r"((a)[1]), "r"((a)[2]), "r"((a)[3]), "r"(b0), "r"(b1))

// split two floats into packed bf16x2 hi + bf16x2 lo (x -> low half)
__device__ __forceinline__ void split2(float x, float y, uint32_t& h, uint32_t& l) {
    __nv_bfloat162 hh = __floats2bfloat162_rn(x, y);
    __nv_bfloat162 ll = __floats2bfloat162_rn(x - __bfloat162float(hh.x),
                                              y - __bfloat162float(hh.y));
    h = *(uint32_t*)&hh;
    l = *(uint32_t*)&ll;
}

// ------------------------------ split fp32 -> bf16 hi/lo -------------------
__global__ void __launch_bounds__(256) split_kernel(
    const float* __restrict__ x, __nv_bfloat16* __restrict__ hi,
    __nv_bfloat16* __restrict__ lo, int n)
{
    int i = (blockIdx.x * 256 + threadIdx.x) * 4;
    if (i >= n) return;
    float4 v = *(const float4*)(x + i);
    uint32_t h0, l0, h1, l1;
    split2(v.x, v.y, h0, l0);
    split2(v.z, v.w, h1, l1);
    *(uint2*)((char*)hi + (size_t)i * 2) = make_uint2(h0, h1);
    *(uint2*)((char*)lo + (size_t)i * 2) = make_uint2(l0, l1);
}

// ------------------------------ HMMA GEMM ----------------------------------
// C = (Ah+Al) @ (Wh+Wl)^T + bias via D += Ah*Wh + Ah*Wl + Al*Wh.
// Output: fp32 (Cf) OR split bf16 (Chi/Clo).
#define GS_AH 0
#define GS_AL 16384
#define GS_WH 32768
#define GS_WL 49152
#define GEMM_SMEM 65536

__global__ void __launch_bounds__(256) gemm_mma_kernel(
    const __nv_bfloat16* __restrict__ Ah, const __nv_bfloat16* __restrict__ Al,
    const __nv_bfloat16* __restrict__ Wh, const __nv_bfloat16* __restrict__ Wl,
    const float* __restrict__ bias, float* __restrict__ Cf,
    __nv_bfloat16* __restrict__ Chi, __nv_bfloat16* __restrict__ Clo)
{
    extern __shared__ char sm[];
    const uint32_t sb = smem_u32(sm);
    const int tid = threadIdx.x;
    const int wid = tid >> 5, lane = tid & 31;
    const int wm = wid >> 2, wn = wid & 3;
    const int bm = blockIdx.y * 128, bn = blockIdx.x * 128;

    const int lrow = (lane & 7) + ((lane >> 3) & 1) * 8;
    const int lcb  = lane >> 4;

    float acc[4][4][4];
#pragma unroll
    for (int mt = 0; mt < 4; mt++)
#pragma unroll
        for (int nt = 0; nt < 4; nt++)
#pragma unroll
            for (int e = 0; e < 4; e++) acc[mt][nt][e] = 0.f;

    for (int t = 0; t < 16; t++) {
        __syncthreads();
#pragma unroll
        for (int i = 0; i < 4; i++) {
            int f = tid + i * 256;
            int r = f >> 3;
            int cb = f & 7;
            size_t gA = (size_t)(bm + r) * D_ + (size_t)t * 64 + cb * 8;
            size_t gW = (size_t)(bn + r) * D_ + (size_t)t * 64 + cb * 8;
            uint32_t so = r * 128 + ((cb ^ (r & 7)) << 4);
            *(uint4*)(sm + GS_AH + so) = *(const uint4*)(Ah + gA);
            *(uint4*)(sm + GS_AL + so) = *(const uint4*)(Al + gA);
            *(uint4*)(sm + GS_WH + so) = *(const uint4*)(Wh + gW);
            *(uint4*)(sm + GS_WL + so) = *(const uint4*)(Wl + gW);
        }
        __syncthreads();

#pragma unroll
        for (int ks = 0; ks < 4; ks++) {
            uint32_t ah[4][4], al[4][4], bh[2][4], bl[2][4];
            const int cb = ks * 2 + lcb;
#pragma unroll
            for (int mt = 0; mt < 4; mt++) {
                int r = wm * 64 + mt * 16 + lrow;
                uint32_t ad = sb + r * 128 + ((cb ^ (r & 7)) << 4);
                LDSM4(ah[mt], ad + GS_AH);
                LDSM4(al[mt], ad + GS_AL);
            }
#pragma unroll
            for (int p = 0; p < 2; p++) {
                int r = wn * 32 + p * 16 + lrow;
                uint32_t ad = sb + r * 128 + ((cb ^ (r & 7)) << 4);
                LDSM4(bh[p], ad + GS_WH);
                LDSM4(bl[p], ad + GS_WL);
            }
#pragma unroll
            for (int mt = 0; mt < 4; mt++) {
#pragma unroll
                for (int nt = 0; nt < 4; nt++) {
                    const int p = nt >> 1, o = nt & 1;
                    MMA16816(acc[mt][nt], ah[mt], bh[p][o], bh[p][o + 2]);
                    MMA16816(acc[mt][nt], ah[mt], bl[p][o], bl[p][o + 2]);
                    MMA16816(acc[mt][nt], al[mt], bh[p][o], bh[p][o + 2]);
                }
            }
        }
    }

    const int g = lane >> 2, tig = lane & 3;
#pragma unroll
    for (int mt = 0; mt < 4; mt++) {
#pragma unroll
        for (int nt = 0; nt < 4; nt++) {
            int row = bm + wm * 64 + mt * 16 + g;
            int col = bn + wn * 32 + nt * 8 + tig * 2;
            float2 bv = *(const float2*)&bias[col];
            float v00 = acc[mt][nt][0] + bv.x, v01 = acc[mt][nt][1] + bv.y;
            float v10 = acc[mt][nt][2] + bv.x, v11 = acc[mt][nt][3] + bv.y;
            if (Cf) {
                *(float2*)(Cf + (size_t)row * D_ + col) = make_float2(v00, v01);
                *(float2*)(Cf + (size_t)(row + 8) * D_ + col) = make_float2(v10, v11);
            } else {
                uint32_t hh, ll;
                split2(v00, v01, hh, ll);
                *(uint32_t*)(Chi + (size_t)row * D_ + col) = hh;
                *(uint32_t*)(Clo + (size_t)row * D_ + col) = ll;
                split2(v10, v11, hh, ll);
                *(uint32_t*)(Chi + (size_t)(row + 8) * D_ + col) = hh;
                *(uint32_t*)(Clo + (size_t)(row + 8) * D_ + col) = ll;
            }
        }
    }
}

// ------------------------------ HMMA flash attention ------------------------
// CTA = (head h, 128 q rows, batch b). 8 warps, 16 q rows each.
// KV tiles of 64. QK and PV both split-bf16 (3 MMAs each).
#define FQH 0
#define FQL 16384
#define FKH 32768
#define FKL 40960
#define FVH 49152
#define FVL 57344
#define FLASH_SMEM 65536

__global__ void __launch_bounds__(256) flash_mma_kernel(
    const __nv_bfloat16* __restrict__ Qh_, const __nv_bfloat16* __restrict__ Ql_,
    const __nv_bfloat16* __restrict__ Kh_, const __nv_bfloat16* __restrict__ Kl_,
    const __nv_bfloat16* __restrict__ Vh_, const __nv_bfloat16* __restrict__ Vl_,
    const int* __restrict__ mask,
    __nv_bfloat16* __restrict__ Ohi, __nv_bfloat16* __restrict__ Olo)
{
    extern __shared__ char sm[];
    const uint32_t sb = smem_u32(sm);
    const int tid = threadIdx.x, wid = tid >> 5, lane = tid & 31;
    const int h = blockIdx.x, qt = blockIdx.y, b = blockIdx.z;
    const int qbase = qt * 128;
    const int g = lane >> 2, t4 = lane & 3;

    // Q tile (128 x 64 bf16 hi/lo), swizzled 128B rows
#pragma unroll
    for (int i = 0; i < 4; i++) {
        int f = tid + i * 256;
        int r = f >> 3, c = f & 7;
        size_t go = ((size_t)(b * S_ + qbase + r)) * D_ + h * DH_ + c * 8;
        uint32_t so = r * 128 + ((c ^ (r & 7)) << 4);
        *(uint4*)(sm + FQH + so) = *(const uint4*)(Qh_ + go);
        *(uint4*)(sm + FQL + so) = *(const uint4*)(Ql_ + go);
    }
    __syncthreads();

    // Persistent Q fragments (A operand, 4 k-steps)
    uint32_t qh[4][4], ql[4][4];
    {
        const int lrow = wid * 16 + ((lane >> 3) & 1) * 8 + (lane & 7);
        const int lcb  = lane >> 4;
#pragma unroll
        for (int ks = 0; ks < 4; ks++) {
            uint32_t ad = sb + lrow * 128 + (((2 * ks + lcb) ^ (lrow & 7)) << 4);
            LDSM4(qh[ks], ad + FQH);
            LDSM4(ql[ks], ad + FQL);
        }
    }

    float o[8][4];
#pragma unroll
    for (int n = 0; n < 8; n++)
#pragma unroll
        for (int e = 0; e < 4; e++) o[n][e] = 0.f;
    float m0 = -1e30f, m1 = -1e30f, l0 = 0.f, l1 = 0.f;

    const int qr0 = qbase + wid * 16 + g;
    const size_t mrow0 = ((size_t)b * S_ + qr0) * S_;
    const size_t mrow1 = mrow0 + (size_t)8 * S_;

    for (int t = 0; t < S_ / 64; t++) {
        const int kvb = t * 64;
        __syncthreads();
#pragma unroll
        for (int i = 0; i < 2; i++) {
            int f = tid + i * 256;
            int r = f >> 3, c = f & 7;
            size_t go = ((size_t)(b * S_ + kvb + r)) * D_ + h * DH_ + c * 8;
            uint32_t so = r * 128 + ((c ^ (r & 7)) << 4);
            *(uint4*)(sm + FKH + so) = *(const uint4*)(Kh_ + go);
            *(uint4*)(sm + FKL + so) = *(const uint4*)(Kl_ + go);
            *(uint4*)(sm + FVH + so) = *(const uint4*)(Vh_ + go);
            *(uint4*)(sm + FVL + so) = *(const uint4*)(Vl_ + go);
        }
        __syncthreads();

        // ---- S = Q @ K^T (split) : s[n8 tile][4 regs]
        float s[8][4];
#pragma unroll
        for (int n = 0; n < 8; n++)
#pragma unroll
            for (int e = 0; e < 4; e++) s[n][e] = 0.f;

        {
            const int krow = ((lane >> 4) << 3) + (lane & 7);
            const int kchb = (lane >> 3) & 1;
#pragma unroll
            for (int ks = 0; ks < 4; ks++) {
                const int kch = 2 * ks + kchb;
#pragma unroll
                for (int ng = 0; ng < 4; ng++) {
                    int r = ng * 16 + krow;
                    uint32_t ad = sb + r * 128 + ((kch ^ (r & 7)) << 4);
                    uint32_t kh4[4], kl4[4];
                    LDSM4(kh4, ad + FKH);
                    LDSM4(kl4, ad + FKL);
                    MMA16816(s[2 * ng],     qh[ks], kh4[0], kh4[1]);
                    MMA16816(s[2 * ng],     qh[ks], kl4[0], kl4[1]);
                    MMA16816(s[2 * ng],     ql[ks], kh4[0], kh4[1]);
                    MMA16816(s[2 * ng + 1], qh[ks], kh4[2], kh4[3]);
                    MMA16816(s[2 * ng + 1], qh[ks], kl4[2], kl4[3]);
                    MMA16816(s[2 * ng + 1], ql[ks], kh4[2], kh4[3]);
                }
            }
        }

        // ---- mask + scale + online softmax (rows qr0, qr0+8)
        float mx0 = -1e30f, mx1 = -1e30f;
#pragma unroll
        for (int n = 0; n < 8; n++) {
            const int col = kvb + n * 8 + t4 * 2;
            int2 ma = *(const int2*)(mask + mrow0 + col);
            int2 mb = *(const int2*)(mask + mrow1 + col);
            s[n][0] = ma.x ? s[n][0] * 0.125f : -1e9f;
            s[n][1] = ma.y ? s[n][1] * 0.125f : -1e9f;
            s[n][2] = mb.x ? s[n][2] * 0.125f : -1e9f;
            s[n][3] = mb.y ? s[n][3] * 0.125f : -1e9f;
            mx0 = fmaxf(mx0, fmaxf(s[n][0], s[n][1]));
            mx1 = fmaxf(mx1, fmaxf(s[n][2], s[n][3]));
        }
        mx0 = fmaxf(mx0, __shfl_xor_sync(0xffffffffu, mx0, 1));
        mx0 = fmaxf(mx0, __shfl_xor_sync(0xffffffffu, mx0, 2));
        mx1 = fmaxf(mx1, __shfl_xor_sync(0xffffffffu, mx1, 1));
        mx1 = fmaxf(mx1, __shfl_xor_sync(0xffffffffu, mx1, 2));

        float mn0 = fmaxf(m0, mx0), mn1 = fmaxf(m1, mx1);
        float al0 = __expf(m0 - mn0), al1 = __expf(m1 - mn1);
        m0 = mn0; m1 = mn1;

        float rs0 = 0.f, rs1 = 0.f;
#pragma unroll
        for (int n = 0; n < 8; n++) {
            s[n][0] = __expf(s[n][0] - mn0);
            s[n][1] = __expf(s[n][1] - mn0);
            s[n][2] = __expf(s[n][2] - mn1);
            s[n][3] = __expf(s[n][3] - mn1);
            rs0 += s[n][0] + s[n][1];
            rs1 += s[n][2] + s[n][3];
        }
        rs0 += __shfl_xor_sync(0xffffffffu, rs0, 1);
        rs0 += __shfl_xor_sync(0xffffffffu, rs0, 2);
        rs1 += __shfl_xor_sync(0xffffffffu, rs1, 1);
        rs1 += __shfl_xor_sync(0xffffffffu, rs1, 2);
        l0 = l0 * al0 + rs0;
        l1 = l1 * al1 + rs1;
#pragma unroll
        for (int n = 0; n < 8; n++) {
            o[n][0] *= al0; o[n][1] *= al0;
            o[n][2] *= al1; o[n][3] *= al1;
        }

        // ---- O += P @ V (split). P fragments built from s regs directly.
        {
            const int vrow_b = ((lane >> 3) & 1) * 8 + (lane & 7);
            const int vchb   = lane >> 4;
#pragma unroll
            for (int ks = 0; ks < 4; ks++) {
                uint32_t ah4[4], al4[4];
                split2(s[2 * ks][0],     s[2 * ks][1],     ah4[0], al4[0]);
                split2(s[2 * ks][2],     s[2 * ks][3],     ah4[1], al4[1]);
                split2(s[2 * ks + 1][0], s[2 * ks + 1][1], ah4[2], al4[2]);
                split2(s[2 * ks + 1][2], s[2 * ks + 1][3], ah4[3], al4[3]);
                const int vrow = ks * 16 + vrow_b;
#pragma unroll
                for (int ng = 0; ng < 4; ng++) {
                    uint32_t ad = sb + vrow * 128 + (((2 * ng + vchb) ^ (vrow & 7)) << 4);
                    uint32_t vh4[4], vl4[4];
                    LDSM4T(vh4, ad + FVH);
                    LDSM4T(vl4, ad + FVL);
                    MMA16816(o[2 * ng],     ah4, vh4[0], vh4[1]);
                    MMA16816(o[2 * ng],     ah4, vl4[0], vl4[1]);
                    MMA16816(o[2 * ng],     al4, vh4[0], vh4[1]);
                    MMA16816(o[2 * ng + 1], ah4, vh4[2], vh4[3]);
                    MMA16816(o[2 * ng + 1], ah4, vl4[2], vl4[3]);
                    MMA16816(o[2 * ng + 1], al4, vh4[2], vh4[3]);
                }
            }
        }
    }

    // ---- finalize: O /= l, write split bf16 ctx
    const float inv0 = 1.f / l0, inv1 = 1.f / l1;
#pragma unroll
    for (int n = 0; n < 8; n++) {
        const int col = h * DH_ + n * 8 + t4 * 2;
        size_t o0 = ((size_t)(b * S_ + qr0)) * D_ + col;
        size_t o1 = o0 + (size_t)8 * D_;
        uint32_t hh, ll;
        split2(o[n][0] * inv0, o[n][1] * inv0, hh, ll);
        *(uint32_t*)(Ohi + o0) = hh;
        *(uint32_t*)(Olo + o0) = ll;
        split2(o[n][2] * inv1, o[n][3] * inv1, hh, ll);
        *(uint32_t*)(Ohi + o1) = hh;
        *(uint32_t*)(Olo + o1) = ll;
    }
}

// ---------------------------------------------------------------------------
extern "C" void kernel_launch(void* const* d_in, const int* in_sizes, int n_in,
                              void* d_out, int out_size)
{
    (void)in_sizes; (void)n_in; (void)out_size;
    const float* q_tok  = (const float*)d_in[0];
    const float* kv_tok = (const float*)d_in[1];
    const int*   mask   = (const int*)d_in[2];
    const float* Wq = (const float*)d_in[3];
    const float* bq = (const float*)d_in[4];
    const float* Wk = (const float*)d_in[5];
    const float* bk = (const float*)d_in[6];
    const float* Wv = (const float*)d_in[7];
    const float* bv = (const float*)d_in[8];
    const float* Wo = (const float*)d_in[9];
    const float* bo = (const float*)d_in[10];
    float* out = (float*)d_out;

    __nv_bfloat16 *ah, *al, *bh, *bl, *wh, *wl;
    __nv_bfloat16 *qh, *ql, *kh, *kl, *vh, *vl, *ch, *cl;
    cudaGetSymbolAddress((void**)&ah, g_ah);
    cudaGetSymbolAddress((void**)&al, g_al);
    cudaGetSymbolAddress((void**)&bh, g_bh);
    cudaGetSymbolAddress((void**)&bl, g_bl);
    cudaGetSymbolAddress((void**)&wh, g_wh);
    cudaGetSymbolAddress((void**)&wl, g_wl);
    cudaGetSymbolAddress((void**)&qh, g_qh);
    cudaGetSymbolAddress((void**)&ql, g_ql);
    cudaGetSymbolAddress((void**)&kh, g_kh);
    cudaGetSymbolAddress((void**)&kl, g_kl);
    cudaGetSymbolAddress((void**)&vh, g_vh);
    cudaGetSymbolAddress((void**)&vl, g_vl);
    cudaGetSymbolAddress((void**)&ch, g_ch);
    cudaGetSymbolAddress((void**)&cl, g_cl);

    cudaFuncSetAttribute(gemm_mma_kernel,
                         cudaFuncAttributeMaxDynamicSharedMemorySize, GEMM_SMEM);
    cudaFuncSetAttribute(flash_mma_kernel,
                         cudaFuncAttributeMaxDynamicSharedMemorySize, FLASH_SMEM);

    const int nTok = M_ * D_;
    const int nW = D_ * D_;

    split_kernel<<<nTok / 1024, 256>>>(q_tok,  ah, al, nTok);
    split_kernel<<<nTok / 1024, 256>>>(kv_tok, bh, bl, nTok);
    split_kernel<<<nW / 1024, 256>>>(Wq, wh + 0 * (size_t)nW, wl + 0 * (size_t)nW, nW);
    split_kernel<<<nW / 1024, 256>>>(Wk, wh + 1 * (size_t)nW, wl + 1 * (size_t)nW, nW);
    split_kernel<<<nW / 1024, 256>>>(Wv, wh + 2 * (size_t)nW, wl + 2 * (size_t)nW, nW);
    split_kernel<<<nW / 1024, 256>>>(Wo, wh + 3 * (size_t)nW, wl + 3 * (size_t)nW, nW);

    dim3 ggrid(D_ / 128, M_ / 128);  // (8, 32)
    gemm_mma_kernel<<<ggrid, 256, GEMM_SMEM>>>(ah, al, wh + 0 * (size_t)nW, wl + 0 * (size_t)nW, bq, nullptr, qh, ql);
    gemm_mma_kernel<<<ggrid, 256, GEMM_SMEM>>>(bh, bl, wh + 1 * (size_t)nW, wl + 1 * (size_t)nW, bk, nullptr, kh, kl);
    gemm_mma_kernel<<<ggrid, 256, GEMM_SMEM>>>(bh, bl, wh + 2 * (size_t)nW, wl + 2 * (size_t)nW, bv, nullptr, vh, vl);

    dim3 fgrid(H_, S_ / 128, B_);    // (16, 16, 2)
    flash_mma_kernel<<<fgrid, 256, FLASH_SMEM>>>(qh, ql, kh, kl, vh, vl, mask, ch, cl);

    gemm_mma_kernel<<<ggrid, 256, GEMM_SMEM>>>(ch, cl, wh + 3 * (size_t)nW, wl + 3 * (size_t)nW, bo, out, nullptr, nullptr);
}

// round 6
// speedup vs baseline: 2.6825x; 1.1100x over previous
#include <cuda_runtime.h>
#include <cuda_bf16.h>
#include <cstdint>

#define B_  2
#define S_  2048
#define D_  1024
#define H_  16
#define DH_ 64
#define M_  (B_*S_)   // 4096

// ------------------------------ scratch (allocation-free rule) -------------
__device__ __nv_bfloat16 g_ah[(size_t)M_ * D_];
__device__ __nv_bfloat16 g_al[(size_t)M_ * D_];
__device__ __nv_bfloat16 g_bh[(size_t)M_ * D_];
__device__ __nv_bfloat16 g_bl[(size_t)M_ * D_];
__device__ __nv_bfloat16 g_wh[(size_t)4 * D_ * D_];
__device__ __nv_bfloat16 g_wl[(size_t)4 * D_ * D_];
__device__ __nv_bfloat16 g_qh[(size_t)M_ * D_];
__device__ __nv_bfloat16 g_ql[(size_t)M_ * D_];
__device__ __nv_bfloat16 g_kh[(size_t)M_ * D_];
__device__ __nv_bfloat16 g_kl[(size_t)M_ * D_];
__device__ __nv_bfloat16 g_vh[(size_t)M_ * D_];
__device__ __nv_bfloat16 g_vl[(size_t)M_ * D_];
__device__ __nv_bfloat16 g_ch[(size_t)M_ * D_];
__device__ __nv_bfloat16 g_cl[(size_t)M_ * D_];

// ------------------------------ helpers ------------------------------------
__device__ __forceinline__ uint32_t smem_u32(const void* p) {
    uint32_t a;
    asm("{ .reg .u64 t; cvta.to.shared.u64 t, %1; cvt.u32.u64 %0, t; }"
        : "=r"(a) : "l"(p));
    return a;
}
__device__ __forceinline__ void cp16(uint32_t s, const void* g) {
    asm volatile("cp.async.cg.shared.global [%0], [%1], 16;" :: "r"(s), "l"(g));
}
#define CP_COMMIT() asm volatile("cp.async.commit_group;" ::: "memory")
#define CP_WAIT1()  asm volatile("cp.async.wait_group 1;" ::: "memory")

#define LDSM4(r, addr) \
    asm volatile("ldmatrix.sync.aligned.m8n8.x4.shared.b16 {%0,%1,%2,%3}, [%4];" \
        : "=r"((r)[0]), "=r"((r)[1]), "=r"((r)[2]), "=r"((r)[3]) : "r"(addr))

#define LDSM4T(r, addr) \
    asm volatile("ldmatrix.sync.aligned.m8n8.x4.trans.shared.b16 {%0,%1,%2,%3}, [%4];" \
        : "=r"((r)[0]), "=r"((r)[1]), "=r"((r)[2]), "=r"((r)[3]) : "r"(addr))

#define MMA16816(d, a, b0, b1) \
    asm volatile("mma.sync.aligned.m16n8k16.row.col.f32.bf16.bf16.f32 " \
        "{%0,%1,%2,%3}, {%4,%5,%6,%7}, {%8,%9}, {%0,%1,%2,%3};" \
        : "+f"((d)[0]), "+f"((d)[1]), "+f"((d)[2]), "+f"((d)[3]) \
        : "r"((a)[0]), "r"((a)[1]), "r"((a)[2]), "r"((a)[3]), "r"(b0), "r"(b1))

__device__ __forceinline__ void split2(float x, float y, uint32_t& h, uint32_t& l) {
    __nv_bfloat162 hh = __floats2bfloat162_rn(x, y);
    __nv_bfloat162 ll = __floats2bfloat162_rn(x - __bfloat162float(hh.x),
                                              y - __bfloat162float(hh.y));
    h = *(uint32_t*)&hh;
    l = *(uint32_t*)&ll;
}

// ------------------------------ split kernels -------------------------------
__global__ void __launch_bounds__(256) split_kernel(
    const float* __restrict__ x, __nv_bfloat16* __restrict__ hi,
    __nv_bfloat16* __restrict__ lo, int n)
{
    int i = (blockIdx.x * 256 + threadIdx.x) * 4;
    if (i >= n) return;
    float4 v = *(const float4*)(x + i);
    uint32_t h0, l0, h1, l1;
    split2(v.x, v.y, h0, l0);
    split2(v.z, v.w, h1, l1);
    *(uint2*)((char*)hi + (size_t)i * 2) = make_uint2(h0, h1);
    *(uint2*)((char*)lo + (size_t)i * 2) = make_uint2(l0, l1);
}

__global__ void __launch_bounds__(256) split4_kernel(
    const float* __restrict__ w0, const float* __restrict__ w1,
    const float* __restrict__ w2, const float* __restrict__ w3,
    __nv_bfloat16* __restrict__ hi, __nv_bfloat16* __restrict__ lo, int n)
{
    const float* src = (blockIdx.y == 0) ? w0 : (blockIdx.y == 1) ? w1
                     : (blockIdx.y == 2) ? w2 : w3;
    size_t base = (size_t)blockIdx.y * n;
    int i = (blockIdx.x * 256 + threadIdx.x) * 4;
    if (i >= n) return;
    float4 v = *(const float4*)(src + i);
    uint32_t h0, l0, h1, l1;
    split2(v.x, v.y, h0, l0);
    split2(v.z, v.w, h1, l1);
    *(uint2*)((char*)(hi + base) + (size_t)i * 2) = make_uint2(h0, h1);
    *(uint2*)((char*)(lo + base) + (size_t)i * 2) = make_uint2(l0, l1);
}

// ------------------------------ HMMA GEMM (3-stage cp.async) ---------------
// K-tile 32. Stage = 4 matrices x 128 rows x 64B = 32KB. 3 stages = 96KB.
// 64B-row swizzle: 16B chunk slot = cb ^ ((r>>1)&3).
#define GS_AH 0
#define GS_AL 8192
#define GS_WH 16384
#define GS_WL 24576
#define GSTG  32768
#define GEMM_SMEM (3 * GSTG)

__global__ void __launch_bounds__(256) gemm_mma_kernel(
    const __nv_bfloat16* __restrict__ Ah, const __nv_bfloat16* __restrict__ Al,
    const __nv_bfloat16* __restrict__ Wh, const __nv_bfloat16* __restrict__ Wl,
    const float* __restrict__ bias, float* __restrict__ Cf,
    __nv_bfloat16* __restrict__ Chi, __nv_bfloat16* __restrict__ Clo)
{
    extern __shared__ char sm[];
    const uint32_t sb = smem_u32(sm);
    const int tid = threadIdx.x;
    const int wid = tid >> 5, lane = tid & 31;
    const int wm = wid >> 2, wn = wid & 3;
    const int bm = blockIdx.y * 128, bn = blockIdx.x * 128;

    const int lrow = (lane & 7) + ((lane >> 3) & 1) * 8;
    const int lcb  = lane >> 4;

    float acc[4][4][4];
#pragma unroll
    for (int mt = 0; mt < 4; mt++)
#pragma unroll
        for (int nt = 0; nt < 4; nt++)
#pragma unroll
            for (int e = 0; e < 4; e++) acc[mt][nt][e] = 0.f;

    auto issue = [&](int t) {
        uint32_t st = sb + (uint32_t)(t % 3) * GSTG;
#pragma unroll
        for (int i = 0; i < 2; i++) {
            int f = tid + i * 256;
            int r = f >> 2, cb = f & 3;
            size_t gA = (size_t)(bm + r) * D_ + t * 32 + cb * 8;
            size_t gW = (size_t)(bn + r) * D_ + t * 32 + cb * 8;
            uint32_t so = r * 64 + ((cb ^ ((r >> 1) & 3)) << 4);
            cp16(st + GS_AH + so, Ah + gA);
            cp16(st + GS_AL + so, Al + gA);
            cp16(st + GS_WH + so, Wh + gW);
            cp16(st + GS_WL + so, Wl + gW);
        }
    };

    issue(0); CP_COMMIT();
    issue(1); CP_COMMIT();

    for (int t = 0; t < 32; t++) {
        CP_WAIT1();
        __syncthreads();
        const uint32_t st = sb + (uint32_t)(t % 3) * GSTG;
#pragma unroll
        for (int ks = 0; ks < 2; ks++) {
            uint32_t ah[4][4], al[4][4], bh[2][4], bl[2][4];
            const int cb = ks * 2 + lcb;
#pragma unroll
            for (int mt = 0; mt < 4; mt++) {
                int r = wm * 64 + mt * 16 + lrow;
                uint32_t ad = st + r * 64 + ((cb ^ ((r >> 1) & 3)) << 4);
                LDSM4(ah[mt], ad + GS_AH);
                LDSM4(al[mt], ad + GS_AL);
            }
#pragma unroll
            for (int p = 0; p < 2; p++) {
                int r = wn * 32 + p * 16 + lrow;
                uint32_t ad = st + r * 64 + ((cb ^ ((r >> 1) & 3)) << 4);
                LDSM4(bh[p], ad + GS_WH);
                LDSM4(bl[p], ad + GS_WL);
            }
#pragma unroll
            for (int mt = 0; mt < 4; mt++) {
#pragma unroll
                for (int nt = 0; nt < 4; nt++) {
                    const int p = nt >> 1, o = nt & 1;
                    MMA16816(acc[mt][nt], ah[mt], bh[p][o], bh[p][o + 2]);
                    MMA16816(acc[mt][nt], ah[mt], bl[p][o], bl[p][o + 2]);
                    MMA16816(acc[mt][nt], al[mt], bh[p][o], bh[p][o + 2]);
                }
            }
        }
        if (t + 2 < 32) issue(t + 2);
        CP_COMMIT();
    }

    const int g = lane >> 2, tig = lane & 3;
#pragma unroll
    for (int mt = 0; mt < 4; mt++) {
#pragma unroll
        for (int nt = 0; nt < 4; nt++) {
            int row = bm + wm * 64 + mt * 16 + g;
            int col = bn + wn * 32 + nt * 8 + tig * 2;
            float2 bv = *(const float2*)&bias[col];
            float v00 = acc[mt][nt][0] + bv.x, v01 = acc[mt][nt][1] + bv.y;
            float v10 = acc[mt][nt][2] + bv.x, v11 = acc[mt][nt][3] + bv.y;
            if (Cf) {
                *(float2*)(Cf + (size_t)row * D_ + col) = make_float2(v00, v01);
                *(float2*)(Cf + (size_t)(row + 8) * D_ + col) = make_float2(v10, v11);
            } else {
                uint32_t hh, ll;
                split2(v00, v01, hh, ll);
                *(uint32_t*)(Chi + (size_t)row * D_ + col) = hh;
                *(uint32_t*)(Clo + (size_t)row * D_ + col) = ll;
                split2(v10, v11, hh, ll);
                *(uint32_t*)(Chi + (size_t)(row + 8) * D_ + col) = hh;
                *(uint32_t*)(Clo + (size_t)(row + 8) * D_ + col) = ll;
            }
        }
    }
}

// ------------------------------ HMMA flash attention (2-stage cp.async) ----
// Q 32KB persistent; KV stage = 32KB (K/V hi/lo, 64x64), 2 stages.
#define FQH 0
#define FQL 16384
#define FSB 32768          // stage region base
#define FKH 0
#define FKL 8192
#define FVH 16384
#define FVL 24576
#define FSTG 32768
#define FLASH_SMEM (FSB + 2 * FSTG)   // 98304

__global__ void __launch_bounds__(256) flash_mma_kernel(
    const __nv_bfloat16* __restrict__ Qh_, const __nv_bfloat16* __restrict__ Ql_,
    const __nv_bfloat16* __restrict__ Kh_, const __nv_bfloat16* __restrict__ Kl_,
    const __nv_bfloat16* __restrict__ Vh_, const __nv_bfloat16* __restrict__ Vl_,
    const int* __restrict__ mask,
    __nv_bfloat16* __restrict__ Ohi, __nv_bfloat16* __restrict__ Olo)
{
    extern __shared__ char sm[];
    const uint32_t sb = smem_u32(sm);
    const int tid = threadIdx.x, wid = tid >> 5, lane = tid & 31;
    const int h = blockIdx.x, qt = blockIdx.y, b = blockIdx.z;
    const int qbase = qt * 128;
    const int g = lane >> 2, t4 = lane & 3;

    auto issue_kv = [&](int t) {
        uint32_t st = sb + FSB + (uint32_t)(t & 1) * FSTG;
#pragma unroll
        for (int i = 0; i < 2; i++) {
            int f = tid + i * 256;
            int r = f >> 3, c = f & 7;
            size_t go = ((size_t)(b * S_ + t * 64 + r)) * D_ + h * DH_ + c * 8;
            uint32_t so = r * 128 + ((c ^ (r & 7)) << 4);
            cp16(st + FKH + so, Kh_ + go);
            cp16(st + FKL + so, Kl_ + go);
            cp16(st + FVH + so, Vh_ + go);
            cp16(st + FVL + so, Vl_ + go);
        }
    };

    issue_kv(0); CP_COMMIT();

    // Q tile (128 x 64 bf16 hi/lo), swizzled 128B rows (plain stores)
#pragma unroll
    for (int i = 0; i < 4; i++) {
        int f = tid + i * 256;
        int r = f >> 3, c = f & 7;
        size_t go = ((size_t)(b * S_ + qbase + r)) * D_ + h * DH_ + c * 8;
        uint32_t so = r * 128 + ((c ^ (r & 7)) << 4);
        *(uint4*)(sm + FQH + so) = *(const uint4*)(Qh_ + go);
        *(uint4*)(sm + FQL + so) = *(const uint4*)(Ql_ + go);
    }
    __syncthreads();

    uint32_t qh[4][4], ql[4][4];
    {
        const int lrow = wid * 16 + ((lane >> 3) & 1) * 8 + (lane & 7);
        const int lcb  = lane >> 4;
#pragma unroll
        for (int ks = 0; ks < 4; ks++) {
            uint32_t ad = sb + lrow * 128 + (((2 * ks + lcb) ^ (lrow & 7)) << 4);
            LDSM4(qh[ks], ad + FQH);
            LDSM4(ql[ks], ad + FQL);
        }
    }

    float o[8][4];
#pragma unroll
    for (int n = 0; n < 8; n++)
#pragma unroll
        for (int e = 0; e < 4; e++) o[n][e] = 0.f;
    float m0 = -1e30f, m1 = -1e30f, l0 = 0.f, l1 = 0.f;

    const int qr0 = qbase + wid * 16 + g;
    const size_t mrow0 = ((size_t)b * S_ + qr0) * S_;
    const size_t mrow1 = mrow0 + (size_t)8 * S_;

    for (int t = 0; t < S_ / 64; t++) {
        const int kvb = t * 64;
        if (t + 1 < S_ / 64) issue_kv(t + 1);
        CP_COMMIT();
        CP_WAIT1();
        __syncthreads();
        const uint32_t st = sb + FSB + (uint32_t)(t & 1) * FSTG;

        // ---- S = Q @ K^T (split)
        float s[8][4];
#pragma unroll
        for (int n = 0; n < 8; n++)
#pragma unroll
            for (int e = 0; e < 4; e++) s[n][e] = 0.f;

        {
            const int krow = ((lane >> 4) << 3) + (lane & 7);
            const int kchb = (lane >> 3) & 1;
#pragma unroll
            for (int ks = 0; ks < 4; ks++) {
                const int kch = 2 * ks + kchb;
#pragma unroll
                for (int ng = 0; ng < 4; ng++) {
                    int r = ng * 16 + krow;
                    uint32_t ad = st + r * 128 + ((kch ^ (r & 7)) << 4);
                    uint32_t kh4[4], kl4[4];
                    LDSM4(kh4, ad + FKH);
                    LDSM4(kl4, ad + FKL);
                    MMA16816(s[2 * ng],     qh[ks], kh4[0], kh4[1]);
                    MMA16816(s[2 * ng],     qh[ks], kl4[0], kl4[1]);
                    MMA16816(s[2 * ng],     ql[ks], kh4[0], kh4[1]);
                    MMA16816(s[2 * ng + 1], qh[ks], kh4[2], kh4[3]);
                    MMA16816(s[2 * ng + 1], qh[ks], kl4[2], kl4[3]);
                    MMA16816(s[2 * ng + 1], ql[ks], kh4[2], kh4[3]);
                }
            }
        }

        // ---- mask + scale + online softmax
        float mx0 = -1e30f, mx1 = -1e30f;
#pragma unroll
        for (int n = 0; n < 8; n++) {
            const int col = kvb + n * 8 + t4 * 2;
            int2 ma = *(const int2*)(mask + mrow0 + col);
            int2 mb = *(const int2*)(mask + mrow1 + col);
            s[n][0] = ma.x ? s[n][0] * 0.125f : -1e9f;
            s[n][1] = ma.y ? s[n][1] * 0.125f : -1e9f;
            s[n][2] = mb.x ? s[n][2] * 0.125f : -1e9f;
            s[n][3] = mb.y ? s[n][3] * 0.125f : -1e9f;
            mx0 = fmaxf(mx0, fmaxf(s[n][0], s[n][1]));
            mx1 = fmaxf(mx1, fmaxf(s[n][2], s[n][3]));
        }
        mx0 = fmaxf(mx0, __shfl_xor_sync(0xffffffffu, mx0, 1));
        mx0 = fmaxf(mx0, __shfl_xor_sync(0xffffffffu, mx0, 2));
        mx1 = fmaxf(mx1, __shfl_xor_sync(0xffffffffu, mx1, 1));
        mx1 = fmaxf(mx1, __shfl_xor_sync(0xffffffffu, mx1, 2));

        float mn0 = fmaxf(m0, mx0), mn1 = fmaxf(m1, mx1);
        float al0 = __expf(m0 - mn0), al1 = __expf(m1 - mn1);
        m0 = mn0; m1 = mn1;

        float rs0 = 0.f, rs1 = 0.f;
#pragma unroll
        for (int n = 0; n < 8; n++) {
            s[n][0] = __expf(s[n][0] - mn0);
            s[n][1] = __expf(s[n][1] - mn0);
            s[n][2] = __expf(s[n][2] - mn1);
            s[n][3] = __expf(s[n][3] - mn1);
            rs0 += s[n][0] + s[n][1];
            rs1 += s[n][2] + s[n][3];
        }
        rs0 += __shfl_xor_sync(0xffffffffu, rs0, 1);
        rs0 += __shfl_xor_sync(0xffffffffu, rs0, 2);
        rs1 += __shfl_xor_sync(0xffffffffu, rs1, 1);
        rs1 += __shfl_xor_sync(0xffffffffu, rs1, 2);
        l0 = l0 * al0 + rs0;
        l1 = l1 * al1 + rs1;
#pragma unroll
        for (int n = 0; n < 8; n++) {
            o[n][0] *= al0; o[n][1] *= al0;
            o[n][2] *= al1; o[n][3] *= al1;
        }

        // ---- O += P @ V (split)
        {
            const int vrow_b = ((lane >> 3) & 1) * 8 + (lane & 7);
            const int vchb   = lane >> 4;
#pragma unroll
            for (int ks = 0; ks < 4; ks++) {
                uint32_t ah4[4], al4[4];
                split2(s[2 * ks][0],     s[2 * ks][1],     ah4[0], al4[0]);
                split2(s[2 * ks][2],     s[2 * ks][3],     ah4[1], al4[1]);
                split2(s[2 * ks + 1][0], s[2 * ks + 1][1], ah4[2], al4[2]);
                split2(s[2 * ks + 1][2], s[2 * ks + 1][3], ah4[3], al4[3]);
                const int vrow = ks * 16 + vrow_b;
#pragma unroll
                for (int ng = 0; ng < 4; ng++) {
                    uint32_t ad = st + vrow * 128 + (((2 * ng + vchb) ^ (vrow & 7)) << 4);
                    uint32_t vh4[4], vl4[4];
                    LDSM4T(vh4, ad + FVH);
                    LDSM4T(vl4, ad + FVL);
                    MMA16816(o[2 * ng],     ah4, vh4[0], vh4[1]);
                    MMA16816(o[2 * ng],     ah4, vl4[0], vl4[1]);
                    MMA16816(o[2 * ng],     al4, vh4[0], vh4[1]);
                    MMA16816(o[2 * ng + 1], ah4, vh4[2], vh4[3]);
                    MMA16816(o[2 * ng + 1], ah4, vl4[2], vl4[3]);
                    MMA16816(o[2 * ng + 1], al4, vh4[2], vh4[3]);
                }
            }
        }
        __syncthreads();
    }

    const float inv0 = 1.f / l0, inv1 = 1.f / l1;
#pragma unroll
    for (int n = 0; n < 8; n++) {
        const int col = h * DH_ + n * 8 + t4 * 2;
        size_t o0 = ((size_t)(b * S_ + qr0)) * D_ + col;
        size_t o1 = o0 + (size_t)8 * D_;
        uint32_t hh, ll;
        split2(o[n][0] * inv0, o[n][1] * inv0, hh, ll);
        *(uint32_t*)(Ohi + o0) = hh;
        *(uint32_t*)(Olo + o0) = ll;
        split2(o[n][2] * inv1, o[n][3] * inv1, hh, ll);
        *(uint32_t*)(Ohi + o1) = hh;
        *(uint32_t*)(Olo + o1) = ll;
    }
}

// ---------------------------------------------------------------------------
extern "C" void kernel_launch(void* const* d_in, const int* in_sizes, int n_in,
                              void* d_out, int out_size)
{
    (void)in_sizes; (void)n_in; (void)out_size;
    const float* q_tok  = (const float*)d_in[0];
    const float* kv_tok = (const float*)d_in[1];
    const int*   mask   = (const int*)d_in[2];
    const float* Wq = (const float*)d_in[3];
    const float* bq = (const float*)d_in[4];
    const float* Wk = (const float*)d_in[5];
    const float* bk = (const float*)d_in[6];
    const float* Wv = (const float*)d_in[7];
    const float* bv = (const float*)d_in[8];
    const float* Wo = (const float*)d_in[9];
    const float* bo = (const float*)d_in[10];
    float* out = (float*)d_out;

    __nv_bfloat16 *ah, *al, *bh, *bl, *wh, *wl;
    __nv_bfloat16 *qh, *ql, *kh, *kl, *vh, *vl, *ch, *cl;
    cudaGetSymbolAddress((void**)&ah, g_ah);
    cudaGetSymbolAddress((void**)&al, g_al);
    cudaGetSymbolAddress((void**)&bh, g_bh);
    cudaGetSymbolAddress((void**)&bl, g_bl);
    cudaGetSymbolAddress((void**)&wh, g_wh);
    cudaGetSymbolAddress((void**)&wl, g_wl);
    cudaGetSymbolAddress((void**)&qh, g_qh);
    cudaGetSymbolAddress((void**)&ql, g_ql);
    cudaGetSymbolAddress((void**)&kh, g_kh);
    cudaGetSymbolAddress((void**)&kl, g_kl);
    cudaGetSymbolAddress((void**)&vh, g_vh);
    cudaGetSymbolAddress((void**)&vl, g_vl);
    cudaGetSymbolAddress((void**)&ch, g_ch);
    cudaGetSymbolAddress((void**)&cl, g_cl);

    cudaFuncSetAttribute(gemm_mma_kernel,
                         cudaFuncAttributeMaxDynamicSharedMemorySize, GEMM_SMEM);
    cudaFuncSetAttribute(flash_mma_kernel,
                         cudaFuncAttributeMaxDynamicSharedMemorySize, FLASH_SMEM);

    const int nTok = M_ * D_;
    const int nW = D_ * D_;

    split_kernel<<<nTok / 1024, 256>>>(q_tok,  ah, al, nTok);
    split_kernel<<<nTok / 1024, 256>>>(kv_tok, bh, bl, nTok);
    dim3 wgrid(nW / 1024, 4);
    split4_kernel<<<wgrid, 256>>>(Wq, Wk, Wv, Wo, wh, wl, nW);

    dim3 ggrid(D_ / 128, M_ / 128);  // (8, 32)
    gemm_mma_kernel<<<ggrid, 256, GEMM_SMEM>>>(ah, al, wh + 0 * (size_t)nW, wl + 0 * (size_t)nW, bq, nullptr, qh, ql);
    gemm_mma_kernel<<<ggrid, 256, GEMM_SMEM>>>(bh, bl, wh + 1 * (size_t)nW, wl + 1 * (size_t)nW, bk, nullptr, kh, kl);
    gemm_mma_kernel<<<ggrid, 256, GEMM_SMEM>>>(bh, bl, wh + 2 * (size_t)nW, wl + 2 * (size_t)nW, bv, nullptr, vh, vl);

    dim3 fgrid(H_, S_ / 128, B_);    // (16, 16, 2)
    flash_mma_kernel<<<fgrid, 256, FLASH_SMEM>>>(qh, ql, kh, kl, vh, vl, mask, ch, cl);

    gemm_mma_kernel<<<ggrid, 256, GEMM_SMEM>>>(ch, cl, wh + 3 * (size_t)nW, wl + 3 * (size_t)nW, bo, out, nullptr, nullptr);
}

// round 7
// speedup vs baseline: 2.7476x; 1.0242x over previous
#include <cuda_runtime.h>
#include <cuda_bf16.h>
#include <cstdint>

#define B_  2
#define S_  2048
#define D_  1024
#define H_  16
#define DH_ 64
#define M_  (B_*S_)   // 4096

// ------------------------------ scratch (allocation-free rule) -------------
__device__ __nv_bfloat16 g_ah[(size_t)M_ * D_];
__device__ __nv_bfloat16 g_al[(size_t)M_ * D_];
__device__ __nv_bfloat16 g_bh[(size_t)M_ * D_];
__device__ __nv_bfloat16 g_bl[(size_t)M_ * D_];
__device__ __nv_bfloat16 g_wh[(size_t)4 * D_ * D_];
__device__ __nv_bfloat16 g_wl[(size_t)4 * D_ * D_];
__device__ __nv_bfloat16 g_qh[(size_t)M_ * D_];
__device__ __nv_bfloat16 g_ql[(size_t)M_ * D_];
__device__ __nv_bfloat16 g_kh[(size_t)M_ * D_];
__device__ __nv_bfloat16 g_kl[(size_t)M_ * D_];
__device__ __nv_bfloat16 g_vh[(size_t)M_ * D_];
__device__ __nv_bfloat16 g_vl[(size_t)M_ * D_];
__device__ __nv_bfloat16 g_ch[(size_t)M_ * D_];
__device__ __nv_bfloat16 g_cl[(size_t)M_ * D_];

// ------------------------------ helpers ------------------------------------
__device__ __forceinline__ uint32_t smem_u32(const void* p) {
    uint32_t a;
    asm("{ .reg .u64 t; cvta.to.shared.u64 t, %1; cvt.u32.u64 %0, t; }"
        : "=r"(a) : "l"(p));
    return a;
}
__device__ __forceinline__ void cp16(uint32_t s, const void* g) {
    asm volatile("cp.async.cg.shared.global [%0], [%1], 16;" :: "r"(s), "l"(g));
}
#define CP_COMMIT() asm volatile("cp.async.commit_group;" ::: "memory")
#define CP_WAIT1()  asm volatile("cp.async.wait_group 1;" ::: "memory")

#define LDSM4(r, addr) \
    asm volatile("ldmatrix.sync.aligned.m8n8.x4.shared.b16 {%0,%1,%2,%3}, [%4];" \
        : "=r"((r)[0]), "=r"((r)[1]), "=r"((r)[2]), "=r"((r)[3]) : "r"(addr))

#define LDSM4T(r, addr) \
    asm volatile("ldmatrix.sync.aligned.m8n8.x4.trans.shared.b16 {%0,%1,%2,%3}, [%4];" \
        : "=r"((r)[0]), "=r"((r)[1]), "=r"((r)[2]), "=r"((r)[3]) : "r"(addr))

#define MMA16816(d, a, b0, b1) \
    asm volatile("mma.sync.aligned.m16n8k16.row.col.f32.bf16.bf16.f32 " \
        "{%0,%1,%2,%3}, {%4,%5,%6,%7}, {%8,%9}, {%0,%1,%2,%3};" \
        : "+f"((d)[0]), "+f"((d)[1]), "+f"((d)[2]), "+f"((d)[3]) \
        : "r"((a)[0]), "r"((a)[1]), "r"((a)[2]), "r"((a)[3]), "r"(b0), "r"(b1))

__device__ __forceinline__ void split2(float x, float y, uint32_t& h, uint32_t& l) {
    __nv_bfloat162 hh = __floats2bfloat162_rn(x, y);
    __nv_bfloat162 ll = __floats2bfloat162_rn(x - __bfloat162float(hh.x),
                                              y - __bfloat162float(hh.y));
    h = *(uint32_t*)&hh;
    l = *(uint32_t*)&ll;
}

// ------------------------------ split kernels -------------------------------
__global__ void __launch_bounds__(256) split_kernel(
    const float* __restrict__ x, __nv_bfloat16* __restrict__ hi,
    __nv_bfloat16* __restrict__ lo, int n)
{
    int i = (blockIdx.x * 256 + threadIdx.x) * 4;
    if (i >= n) return;
    float4 v = *(const float4*)(x + i);
    uint32_t h0, l0, h1, l1;
    split2(v.x, v.y, h0, l0);
    split2(v.z, v.w, h1, l1);
    *(uint2*)((char*)hi + (size_t)i * 2) = make_uint2(h0, h1);
    *(uint2*)((char*)lo + (size_t)i * 2) = make_uint2(l0, l1);
}

__global__ void __launch_bounds__(256) split4_kernel(
    const float* __restrict__ w0, const float* __restrict__ w1,
    const float* __restrict__ w2, const float* __restrict__ w3,
    __nv_bfloat16* __restrict__ hi, __nv_bfloat16* __restrict__ lo, int n)
{
    const float* src = (blockIdx.y == 0) ? w0 : (blockIdx.y == 1) ? w1
                     : (blockIdx.y == 2) ? w2 : w3;
    size_t base = (size_t)blockIdx.y * n;
    int i = (blockIdx.x * 256 + threadIdx.x) * 4;
    if (i >= n) return;
    float4 v = *(const float4*)(src + i);
    uint32_t h0, l0, h1, l1;
    split2(v.x, v.y, h0, l0);
    split2(v.z, v.w, h1, l1);
    *(uint2*)((char*)(hi + base) + (size_t)i * 2) = make_uint2(h0, h1);
    *(uint2*)((char*)(lo + base) + (size_t)i * 2) = make_uint2(l0, l1);
}

// ------------------------------ HMMA GEMM body (3-stage cp.async) ----------
#define GS_AH 0
#define GS_AL 8192
#define GS_WH 16384
#define GS_WL 24576
#define GSTG  32768
#define GEMM_SMEM (3 * GSTG)

__device__ __forceinline__ void gemm_body(
    char* sm,
    const __nv_bfloat16* __restrict__ Ah, const __nv_bfloat16* __restrict__ Al,
    const __nv_bfloat16* __restrict__ Wh, const __nv_bfloat16* __restrict__ Wl,
    const float* __restrict__ bias, float* __restrict__ Cf,
    __nv_bfloat16* __restrict__ Chi, __nv_bfloat16* __restrict__ Clo,
    int bm, int bn)
{
    const uint32_t sb = smem_u32(sm);
    const int tid = threadIdx.x;
    const int wid = tid >> 5, lane = tid & 31;
    const int wm = wid >> 2, wn = wid & 3;

    const int lrow = (lane & 7) + ((lane >> 3) & 1) * 8;
    const int lcb  = lane >> 4;

    float acc[4][4][4];
#pragma unroll
    for (int mt = 0; mt < 4; mt++)
#pragma unroll
        for (int nt = 0; nt < 4; nt++)
#pragma unroll
            for (int e = 0; e < 4; e++) acc[mt][nt][e] = 0.f;

    auto issue = [&](int t) {
        uint32_t st = sb + (uint32_t)(t % 3) * GSTG;
#pragma unroll
        for (int i = 0; i < 2; i++) {
            int f = tid + i * 256;
            int r = f >> 2, cb = f & 3;
            size_t gA = (size_t)(bm + r) * D_ + t * 32 + cb * 8;
            size_t gW = (size_t)(bn + r) * D_ + t * 32 + cb * 8;
            uint32_t so = r * 64 + ((cb ^ ((r >> 1) & 3)) << 4);
            cp16(st + GS_AH + so, Ah + gA);
            cp16(st + GS_AL + so, Al + gA);
            cp16(st + GS_WH + so, Wh + gW);
            cp16(st + GS_WL + so, Wl + gW);
        }
    };

    issue(0); CP_COMMIT();
    issue(1); CP_COMMIT();

    for (int t = 0; t < 32; t++) {
        CP_WAIT1();
        __syncthreads();
        const uint32_t st = sb + (uint32_t)(t % 3) * GSTG;
#pragma unroll
        for (int ks = 0; ks < 2; ks++) {
            uint32_t ah[4][4], al[4][4], bh[2][4], bl[2][4];
            const int cb = ks * 2 + lcb;
#pragma unroll
            for (int mt = 0; mt < 4; mt++) {
                int r = wm * 64 + mt * 16 + lrow;
                uint32_t ad = st + r * 64 + ((cb ^ ((r >> 1) & 3)) << 4);
                LDSM4(ah[mt], ad + GS_AH);
                LDSM4(al[mt], ad + GS_AL);
            }
#pragma unroll
            for (int p = 0; p < 2; p++) {
                int r = wn * 32 + p * 16 + lrow;
                uint32_t ad = st + r * 64 + ((cb ^ ((r >> 1) & 3)) << 4);
                LDSM4(bh[p], ad + GS_WH);
                LDSM4(bl[p], ad + GS_WL);
            }
            // pass-major: 16 independent MMAs per pass (no RAW chains)
#pragma unroll
            for (int mt = 0; mt < 4; mt++)
#pragma unroll
                for (int nt = 0; nt < 4; nt++)
                    MMA16816(acc[mt][nt], ah[mt], bh[nt >> 1][nt & 1], bh[nt >> 1][(nt & 1) + 2]);
#pragma unroll
            for (int mt = 0; mt < 4; mt++)
#pragma unroll
                for (int nt = 0; nt < 4; nt++)
                    MMA16816(acc[mt][nt], ah[mt], bl[nt >> 1][nt & 1], bl[nt >> 1][(nt & 1) + 2]);
#pragma unroll
            for (int mt = 0; mt < 4; mt++)
#pragma unroll
                for (int nt = 0; nt < 4; nt++)
                    MMA16816(acc[mt][nt], al[mt], bh[nt >> 1][nt & 1], bh[nt >> 1][(nt & 1) + 2]);
        }
        if (t + 2 < 32) issue(t + 2);
        CP_COMMIT();
    }

    const int g = lane >> 2, tig = lane & 3;
#pragma unroll
    for (int mt = 0; mt < 4; mt++) {
#pragma unroll
        for (int nt = 0; nt < 4; nt++) {
            int row = bm + wm * 64 + mt * 16 + g;
            int col = bn + wn * 32 + nt * 8 + tig * 2;
            float2 bv = *(const float2*)&bias[col];
            float v00 = acc[mt][nt][0] + bv.x, v01 = acc[mt][nt][1] + bv.y;
            float v10 = acc[mt][nt][2] + bv.x, v11 = acc[mt][nt][3] + bv.y;
            if (Cf) {
                *(float2*)(Cf + (size_t)row * D_ + col) = make_float2(v00, v01);
                *(float2*)(Cf + (size_t)(row + 8) * D_ + col) = make_float2(v10, v11);
            } else {
                uint32_t hh, ll;
                split2(v00, v01, hh, ll);
                *(uint32_t*)(Chi + (size_t)row * D_ + col) = hh;
                *(uint32_t*)(Clo + (size_t)row * D_ + col) = ll;
                split2(v10, v11, hh, ll);
                *(uint32_t*)(Chi + (size_t)(row + 8) * D_ + col) = hh;
                *(uint32_t*)(Clo + (size_t)(row + 8) * D_ + col) = ll;
            }
        }
    }
}

// Fused Q/K/V projection: blockIdx.z selects which GEMM.
__global__ void __launch_bounds__(256) gemm_qkv_kernel(
    const __nv_bfloat16* __restrict__ ah, const __nv_bfloat16* __restrict__ al,
    const __nv_bfloat16* __restrict__ bh, const __nv_bfloat16* __restrict__ bl,
    const __nv_bfloat16* __restrict__ wh, const __nv_bfloat16* __restrict__ wl,
    const float* __restrict__ bq, const float* __restrict__ bk,
    const float* __restrict__ bv,
    __nv_bfloat16* __restrict__ qh, __nv_bfloat16* __restrict__ ql,
    __nv_bfloat16* __restrict__ kh, __nv_bfloat16* __restrict__ kl,
    __nv_bfloat16* __restrict__ vh, __nv_bfloat16* __restrict__ vl)
{
    extern __shared__ char sm[];
    const int z = blockIdx.z;
    const __nv_bfloat16* Ah = (z == 0) ? ah : bh;
    const __nv_bfloat16* Al = (z == 0) ? al : bl;
    const __nv_bfloat16* Wh = wh + (size_t)z * D_ * D_;
    const __nv_bfloat16* Wl = wl + (size_t)z * D_ * D_;
    const float* bias = (z == 0) ? bq : (z == 1) ? bk : bv;
    __nv_bfloat16* Chi = (z == 0) ? qh : (z == 1) ? kh : vh;
    __nv_bfloat16* Clo = (z == 0) ? ql : (z == 1) ? kl : vl;
    gemm_body(sm, Ah, Al, Wh, Wl, bias, nullptr, Chi, Clo,
              blockIdx.y * 128, blockIdx.x * 128);
}

// Output projection (fp32 out)
__global__ void __launch_bounds__(256) gemm_out_kernel(
    const __nv_bfloat16* __restrict__ Ah, const __nv_bfloat16* __restrict__ Al,
    const __nv_bfloat16* __restrict__ Wh, const __nv_bfloat16* __restrict__ Wl,
    const float* __restrict__ bias, float* __restrict__ Cf)
{
    extern __shared__ char sm[];
    gemm_body(sm, Ah, Al, Wh, Wl, bias, Cf, nullptr, nullptr,
              blockIdx.y * 128, blockIdx.x * 128);
}

// ------------------------------ HMMA flash attention (2-stage cp.async) ----
#define FQH 0
#define FQL 16384
#define FSB 32768
#define FKH 0
#define FKL 8192
#define FVH 16384
#define FVL 24576
#define FSTG 32768
#define FLASH_SMEM (FSB + 2 * FSTG)   // 98304

__global__ void __launch_bounds__(256) flash_mma_kernel(
    const __nv_bfloat16* __restrict__ Qh_, const __nv_bfloat16* __restrict__ Ql_,
    const __nv_bfloat16* __restrict__ Kh_, const __nv_bfloat16* __restrict__ Kl_,
    const __nv_bfloat16* __restrict__ Vh_, const __nv_bfloat16* __restrict__ Vl_,
    const int* __restrict__ mask,
    __nv_bfloat16* __restrict__ Ohi, __nv_bfloat16* __restrict__ Olo)
{
    extern __shared__ char sm[];
    const uint32_t sb = smem_u32(sm);
    const int tid = threadIdx.x, wid = tid >> 5, lane = tid & 31;
    const int h = blockIdx.x, qt = blockIdx.y, b = blockIdx.z;
    const int qbase = qt * 128;
    const int g = lane >> 2, t4 = lane & 3;

    auto issue_kv = [&](int t) {
        uint32_t st = sb + FSB + (uint32_t)(t & 1) * FSTG;
#pragma unroll
        for (int i = 0; i < 2; i++) {
            int f = tid + i * 256;
            int r = f >> 3, c = f & 7;
            size_t go = ((size_t)(b * S_ + t * 64 + r)) * D_ + h * DH_ + c * 8;
            uint32_t so = r * 128 + ((c ^ (r & 7)) << 4);
            cp16(st + FKH + so, Kh_ + go);
            cp16(st + FKL + so, Kl_ + go);
            cp16(st + FVH + so, Vh_ + go);
            cp16(st + FVL + so, Vl_ + go);
        }
    };

    issue_kv(0); CP_COMMIT();

#pragma unroll
    for (int i = 0; i < 4; i++) {
        int f = tid + i * 256;
        int r = f >> 3, c = f & 7;
        size_t go = ((size_t)(b * S_ + qbase + r)) * D_ + h * DH_ + c * 8;
        uint32_t so = r * 128 + ((c ^ (r & 7)) << 4);
        *(uint4*)(sm + FQH + so) = *(const uint4*)(Qh_ + go);
        *(uint4*)(sm + FQL + so) = *(const uint4*)(Ql_ + go);
    }
    __syncthreads();

    uint32_t qh[4][4], ql[4][4];
    {
        const int lrow = wid * 16 + ((lane >> 3) & 1) * 8 + (lane & 7);
        const int lcb  = lane >> 4;
#pragma unroll
        for (int ks = 0; ks < 4; ks++) {
            uint32_t ad = sb + lrow * 128 + (((2 * ks + lcb) ^ (lrow & 7)) << 4);
            LDSM4(qh[ks], ad + FQH);
            LDSM4(ql[ks], ad + FQL);
        }
    }

    float o[8][4];
#pragma unroll
    for (int n = 0; n < 8; n++)
#pragma unroll
        for (int e = 0; e < 4; e++) o[n][e] = 0.f;
    float m0 = -1e30f, m1 = -1e30f, l0 = 0.f, l1 = 0.f;

    const int qr0 = qbase + wid * 16 + g;
    const size_t mrow0 = ((size_t)b * S_ + qr0) * S_;
    const size_t mrow1 = mrow0 + (size_t)8 * S_;

    for (int t = 0; t < S_ / 64; t++) {
        const int kvb = t * 64;
        if (t + 1 < S_ / 64) issue_kv(t + 1);
        CP_COMMIT();
        CP_WAIT1();
        __syncthreads();
        const uint32_t st = sb + FSB + (uint32_t)(t & 1) * FSTG;

        // ---- S = Q @ K^T (split), pass-interleaved across the two n-tiles
        float s[8][4];
#pragma unroll
        for (int n = 0; n < 8; n++)
#pragma unroll
            for (int e = 0; e < 4; e++) s[n][e] = 0.f;

        {
            const int krow = ((lane >> 4) << 3) + (lane & 7);
            const int kchb = (lane >> 3) & 1;
#pragma unroll
            for (int ks = 0; ks < 4; ks++) {
                const int kch = 2 * ks + kchb;
#pragma unroll
                for (int ng = 0; ng < 4; ng++) {
                    int r = ng * 16 + krow;
                    uint32_t ad = st + r * 128 + ((kch ^ (r & 7)) << 4);
                    uint32_t kh4[4], kl4[4];
                    LDSM4(kh4, ad + FKH);
                    LDSM4(kl4, ad + FKL);
                    MMA16816(s[2 * ng],     qh[ks], kh4[0], kh4[1]);
                    MMA16816(s[2 * ng + 1], qh[ks], kh4[2], kh4[3]);
                    MMA16816(s[2 * ng],     qh[ks], kl4[0], kl4[1]);
                    MMA16816(s[2 * ng + 1], qh[ks], kl4[2], kl4[3]);
                    MMA16816(s[2 * ng],     ql[ks], kh4[0], kh4[1]);
                    MMA16816(s[2 * ng + 1], ql[ks], kh4[2], kh4[3]);
                }
            }
        }

        // ---- mask + scale + online softmax
        float mx0 = -1e30f, mx1 = -1e30f;
#pragma unroll
        for (int n = 0; n < 8; n++) {
            const int col = kvb + n * 8 + t4 * 2;
            int2 ma = *(const int2*)(mask + mrow0 + col);
            int2 mb = *(const int2*)(mask + mrow1 + col);
            s[n][0] = ma.x ? s[n][0] * 0.125f : -1e9f;
            s[n][1] = ma.y ? s[n][1] * 0.125f : -1e9f;
            s[n][2] = mb.x ? s[n][2] * 0.125f : -1e9f;
            s[n][3] = mb.y ? s[n][3] * 0.125f : -1e9f;
            mx0 = fmaxf(mx0, fmaxf(s[n][0], s[n][1]));
            mx1 = fmaxf(mx1, fmaxf(s[n][2], s[n][3]));
        }
        mx0 = fmaxf(mx0, __shfl_xor_sync(0xffffffffu, mx0, 1));
        mx0 = fmaxf(mx0, __shfl_xor_sync(0xffffffffu, mx0, 2));
        mx1 = fmaxf(mx1, __shfl_xor_sync(0xffffffffu, mx1, 1));
        mx1 = fmaxf(mx1, __shfl_xor_sync(0xffffffffu, mx1, 2));

        float mn0 = fmaxf(m0, mx0), mn1 = fmaxf(m1, mx1);
        float al0 = __expf(m0 - mn0), al1 = __expf(m1 - mn1);
        m0 = mn0; m1 = mn1;

        float rs0 = 0.f, rs1 = 0.f;
#pragma unroll
        for (int n = 0; n < 8; n++) {
            s[n][0] = __expf(s[n][0] - mn0);
            s[n][1] = __expf(s[n][1] - mn0);
            s[n][2] = __expf(s[n][2] - mn1);
            s[n][3] = __expf(s[n][3] - mn1);
            rs0 += s[n][0] + s[n][1];
            rs1 += s[n][2] + s[n][3];
        }
        rs0 += __shfl_xor_sync(0xffffffffu, rs0, 1);
        rs0 += __shfl_xor_sync(0xffffffffu, rs0, 2);
        rs1 += __shfl_xor_sync(0xffffffffu, rs1, 1);
        rs1 += __shfl_xor_sync(0xffffffffu, rs1, 2);
        l0 = l0 * al0 + rs0;
        l1 = l1 * al1 + rs1;
#pragma unroll
        for (int n = 0; n < 8; n++) {
            o[n][0] *= al0; o[n][1] *= al0;
            o[n][2] *= al1; o[n][3] *= al1;
        }

        // ---- O += P @ V (split), interleaved across the two n-tiles
        {
            const int vrow_b = ((lane >> 3) & 1) * 8 + (lane & 7);
            const int vchb   = lane >> 4;
#pragma unroll
            for (int ks = 0; ks < 4; ks++) {
                uint32_t ah4[4], al4[4];
                split2(s[2 * ks][0],     s[2 * ks][1],     ah4[0], al4[0]);
                split2(s[2 * ks][2],     s[2 * ks][3],     ah4[1], al4[1]);
                split2(s[2 * ks + 1][0], s[2 * ks + 1][1], ah4[2], al4[2]);
                split2(s[2 * ks + 1][2], s[2 * ks + 1][3], ah4[3], al4[3]);
                const int vrow = ks * 16 + vrow_b;
#pragma unroll
                for (int ng = 0; ng < 4; ng++) {
                    uint32_t ad = st + vrow * 128 + (((2 * ng + vchb) ^ (vrow & 7)) << 4);
                    uint32_t vh4[4], vl4[4];
                    LDSM4T(vh4, ad + FVH);
                    LDSM4T(vl4, ad + FVL);
                    MMA16816(o[2 * ng],     ah4, vh4[0], vh4[1]);
                    MMA16816(o[2 * ng + 1], ah4, vh4[2], vh4[3]);
                    MMA16816(o[2 * ng],     ah4, vl4[0], vl4[1]);
                    MMA16816(o[2 * ng + 1], ah4, vl4[2], vl4[3]);
                    MMA16816(o[2 * ng],     al4, vh4[0], vh4[1]);
                    MMA16816(o[2 * ng + 1], al4, vh4[2], vh4[3]);
                }
            }
        }
        __syncthreads();
    }

    const float inv0 = 1.f / l0, inv1 = 1.f / l1;
#pragma unroll
    for (int n = 0; n < 8; n++) {
        const int col = h * DH_ + n * 8 + t4 * 2;
        size_t o0 = ((size_t)(b * S_ + qr0)) * D_ + col;
        size_t o1 = o0 + (size_t)8 * D_;
        uint32_t hh, ll;
        split2(o[n][0] * inv0, o[n][1] * inv0, hh, ll);
        *(uint32_t*)(Ohi + o0) = hh;
        *(uint32_t*)(Olo + o0) = ll;
        split2(o[n][2] * inv1, o[n][3] * inv1, hh, ll);
        *(uint32_t*)(Ohi + o1) = hh;
        *(uint32_t*)(Olo + o1) = ll;
    }
}

// ---------------------------------------------------------------------------
extern "C" void kernel_launch(void* const* d_in, const int* in_sizes, int n_in,
                              void* d_out, int out_size)
{
    (void)in_sizes; (void)n_in; (void)out_size;
    const float* q_tok  = (const float*)d_in[0];
    const float* kv_tok = (const float*)d_in[1];
    const int*   mask   = (const int*)d_in[2];
    const float* Wq = (const float*)d_in[3];
    const float* bq = (const float*)d_in[4];
    const float* Wk = (const float*)d_in[5];
    const float* bk = (const float*)d_in[6];
    const float* Wv = (const float*)d_in[7];
    const float* bv = (const float*)d_in[8];
    const float* Wo = (const float*)d_in[9];
    const float* bo = (const float*)d_in[10];
    float* out = (float*)d_out;

    __nv_bfloat16 *ah, *al, *bh, *bl, *wh, *wl;
    __nv_bfloat16 *qh, *ql, *kh, *kl, *vh, *vl, *ch, *cl;
    cudaGetSymbolAddress((void**)&ah, g_ah);
    cudaGetSymbolAddress((void**)&al, g_al);
    cudaGetSymbolAddress((void**)&bh, g_bh);
    cudaGetSymbolAddress((void**)&bl, g_bl);
    cudaGetSymbolAddress((void**)&wh, g_wh);
    cudaGetSymbolAddress((void**)&wl, g_wl);
    cudaGetSymbolAddress((void**)&qh, g_qh);
    cudaGetSymbolAddress((void**)&ql, g_ql);
    cudaGetSymbolAddress((void**)&kh, g_kh);
    cudaGetSymbolAddress((void**)&kl, g_kl);
    cudaGetSymbolAddress((void**)&vh, g_vh);
    cudaGetSymbolAddress((void**)&vl, g_vl);
    cudaGetSymbolAddress((void**)&ch, g_ch);
    cudaGetSymbolAddress((void**)&cl, g_cl);

    cudaFuncSetAttribute(gemm_qkv_kernel,
                         cudaFuncAttributeMaxDynamicSharedMemorySize, GEMM_SMEM);
    cudaFuncSetAttribute(gemm_out_kernel,
                         cudaFuncAttributeMaxDynamicSharedMemorySize, GEMM_SMEM);
    cudaFuncSetAttribute(flash_mma_kernel,
                         cudaFuncAttributeMaxDynamicSharedMemorySize, FLASH_SMEM);

    const int nTok = M_ * D_;
    const int nW = D_ * D_;

    split_kernel<<<nTok / 1024, 256>>>(q_tok,  ah, al, nTok);
    split_kernel<<<nTok / 1024, 256>>>(kv_tok, bh, bl, nTok);
    dim3 wgrid(nW / 1024, 4);
    split4_kernel<<<wgrid, 256>>>(Wq, Wk, Wv, Wo, wh, wl, nW);

    dim3 qkvgrid(D_ / 128, M_ / 128, 3);   // (8, 32, 3) = 768 CTAs
    gemm_qkv_kernel<<<qkvgrid, 256, GEMM_SMEM>>>(
        ah, al, bh, bl, wh, wl, bq, bk, bv, qh, ql, kh, kl, vh, vl);

    dim3 fgrid(H_, S_ / 128, B_);          // (16, 16, 2)
    flash_mma_kernel<<<fgrid, 256, FLASH_SMEM>>>(qh, ql, kh, kl, vh, vl, mask, ch, cl);

    dim3 ogrid(D_ / 128, M_ / 128);
    gemm_out_kernel<<<ogrid, 256, GEMM_SMEM>>>(
        ch, cl, wh + 3 * (size_t)nW, wl + 3 * (size_t)nW, bo, out);
}

// round 8
// speedup vs baseline: 3.2757x; 1.1922x over previous
#include <cuda_runtime.h>
#include <cuda_bf16.h>
#include <cuda_fp16.h>
#include <cstdint>

#define B_  2
#define S_  2048
#define D_  1024
#define H_  16
#define DH_ 64
#define M_  (B_*S_)   // 4096

// ------------------------------ scratch (allocation-free rule) -------------
__device__ __nv_bfloat16 g_ah[(size_t)M_ * D_];
__device__ __nv_bfloat16 g_al[(size_t)M_ * D_];
__device__ __nv_bfloat16 g_bh[(size_t)M_ * D_];
__device__ __nv_bfloat16 g_bl[(size_t)M_ * D_];
__device__ __nv_bfloat16 g_wh[(size_t)4 * D_ * D_];
__device__ __nv_bfloat16 g_wl[(size_t)4 * D_ * D_];
__device__ __half        g_qh[(size_t)M_ * D_];   // Q proj fp16 hi/lo
__device__ __half        g_ql[(size_t)M_ * D_];
__device__ __half        g_kf[(size_t)M_ * D_];   // K proj fp16 single
__device__ __half        g_vf[(size_t)M_ * D_];   // V proj fp16 single
__device__ __nv_bfloat16 g_ch[(size_t)M_ * D_];   // ctx bf16 hi/lo
__device__ __nv_bfloat16 g_cl[(size_t)M_ * D_];

// ------------------------------ helpers ------------------------------------
__device__ __forceinline__ uint32_t smem_u32(const void* p) {
    uint32_t a;
    asm("{ .reg .u64 t; cvta.to.shared.u64 t, %1; cvt.u32.u64 %0, t; }"
        : "=r"(a) : "l"(p));
    return a;
}
__device__ __forceinline__ void cp16(uint32_t s, const void* g) {
    asm volatile("cp.async.cg.shared.global [%0], [%1], 16;" :: "r"(s), "l"(g));
}
#define CP_COMMIT() asm volatile("cp.async.commit_group;" ::: "memory")
#define CP_WAIT1()  asm volatile("cp.async.wait_group 1;" ::: "memory")

#define LDSM4(r, addr) \
    asm volatile("ldmatrix.sync.aligned.m8n8.x4.shared.b16 {%0,%1,%2,%3}, [%4];" \
        : "=r"((r)[0]), "=r"((r)[1]), "=r"((r)[2]), "=r"((r)[3]) : "r"(addr))

#define LDSM4T(r, addr) \
    asm volatile("ldmatrix.sync.aligned.m8n8.x4.trans.shared.b16 {%0,%1,%2,%3}, [%4];" \
        : "=r"((r)[0]), "=r"((r)[1]), "=r"((r)[2]), "=r"((r)[3]) : "r"(addr))

#define MMA16816(d, a, b0, b1) \
    asm volatile("mma.sync.aligned.m16n8k16.row.col.f32.bf16.bf16.f32 " \
        "{%0,%1,%2,%3}, {%4,%5,%6,%7}, {%8,%9}, {%0,%1,%2,%3};" \
        : "+f"((d)[0]), "+f"((d)[1]), "+f"((d)[2]), "+f"((d)[3]) \
        : "r"((a)[0]), "r"((a)[1]), "r"((a)[2]), "r"((a)[3]), "r"(b0), "r"(b1))

#define MMAF16(d, a, b0, b1) \
    asm volatile("mma.sync.aligned.m16n8k16.row.col.f32.f16.f16.f32 " \
        "{%0,%1,%2,%3}, {%4,%5,%6,%7}, {%8,%9}, {%0,%1,%2,%3};" \
        : "+f"((d)[0]), "+f"((d)[1]), "+f"((d)[2]), "+f"((d)[3]) \
        : "r"((a)[0]), "r"((a)[1]), "r"((a)[2]), "r"((a)[3]), "r"(b0), "r"(b1))

__device__ __forceinline__ void split2(float x, float y, uint32_t& h, uint32_t& l) {
    __nv_bfloat162 hh = __floats2bfloat162_rn(x, y);
    __nv_bfloat162 ll = __floats2bfloat162_rn(x - __bfloat162float(hh.x),
                                              y - __bfloat162float(hh.y));
    h = *(uint32_t*)&hh;
    l = *(uint32_t*)&ll;
}
__device__ __forceinline__ void split2h(float x, float y, uint32_t& h, uint32_t& l) {
    __half2 hh = __floats2half2_rn(x, y);
    __half2 ll = __floats2half2_rn(x - __half2float(__low2half(hh)),
                                   y - __half2float(__high2half(hh)));
    h = *(uint32_t*)&hh;
    l = *(uint32_t*)&ll;
}
__device__ __forceinline__ uint32_t pack2h(float x, float y) {
    __half2 hh = __floats2half2_rn(x, y);
    return *(uint32_t*)&hh;
}

// ------------------------------ split kernels -------------------------------
__global__ void __launch_bounds__(256) split_kernel(
    const float* __restrict__ x, __nv_bfloat16* __restrict__ hi,
    __nv_bfloat16* __restrict__ lo, int n)
{
    int i = (blockIdx.x * 256 + threadIdx.x) * 4;
    if (i >= n) return;
    float4 v = *(const float4*)(x + i);
    uint32_t h0, l0, h1, l1;
    split2(v.x, v.y, h0, l0);
    split2(v.z, v.w, h1, l1);
    *(uint2*)((char*)hi + (size_t)i * 2) = make_uint2(h0, h1);
    *(uint2*)((char*)lo + (size_t)i * 2) = make_uint2(l0, l1);
}

__global__ void __launch_bounds__(256) split4_kernel(
    const float* __restrict__ w0, const float* __restrict__ w1,
    const float* __restrict__ w2, const float* __restrict__ w3,
    __nv_bfloat16* __restrict__ hi, __nv_bfloat16* __restrict__ lo, int n)
{
    const float* src = (blockIdx.y == 0) ? w0 : (blockIdx.y == 1) ? w1
                     : (blockIdx.y == 2) ? w2 : w3;
    size_t base = (size_t)blockIdx.y * n;
    int i = (blockIdx.x * 256 + threadIdx.x) * 4;
    if (i >= n) return;
    float4 v = *(const float4*)(src + i);
    uint32_t h0, l0, h1, l1;
    split2(v.x, v.y, h0, l0);
    split2(v.z, v.w, h1, l1);
    *(uint2*)((char*)(hi + base) + (size_t)i * 2) = make_uint2(h0, h1);
    *(uint2*)((char*)(lo + base) + (size_t)i * 2) = make_uint2(l0, l1);
}

// ------------------------------ HMMA GEMM body (3-stage cp.async) ----------
// Output modes: 0 = fp32 -> Cf, 2 = fp16 split -> Fhi/Flo, 3 = fp16 single -> Fhi
// (bf16 split output unused this round; ctx is produced by flash directly)
#define GS_AH 0
#define GS_AL 8192
#define GS_WH 16384
#define GS_WL 24576
#define GSTG  32768
#define GEMM_SMEM (3 * GSTG)

__device__ __forceinline__ void gemm_body(
    char* sm,
    const __nv_bfloat16* __restrict__ Ah, const __nv_bfloat16* __restrict__ Al,
    const __nv_bfloat16* __restrict__ Wh, const __nv_bfloat16* __restrict__ Wl,
    const float* __restrict__ bias, int omode, float* __restrict__ Cf,
    __half* __restrict__ Fhi, __half* __restrict__ Flo,
    int bm, int bn)
{
    const uint32_t sb = smem_u32(sm);
    const int tid = threadIdx.x;
    const int wid = tid >> 5, lane = tid & 31;
    const int wm = wid >> 2, wn = wid & 3;

    const int lrow = (lane & 7) + ((lane >> 3) & 1) * 8;
    const int lcb  = lane >> 4;

    float acc[4][4][4];
#pragma unroll
    for (int mt = 0; mt < 4; mt++)
#pragma unroll
        for (int nt = 0; nt < 4; nt++)
#pragma unroll
            for (int e = 0; e < 4; e++) acc[mt][nt][e] = 0.f;

    auto issue = [&](int t) {
        uint32_t st = sb + (uint32_t)(t % 3) * GSTG;
#pragma unroll
        for (int i = 0; i < 2; i++) {
            int f = tid + i * 256;
            int r = f >> 2, cb = f & 3;
            size_t gA = (size_t)(bm + r) * D_ + t * 32 + cb * 8;
            size_t gW = (size_t)(bn + r) * D_ + t * 32 + cb * 8;
            uint32_t so = r * 64 + ((cb ^ ((r >> 1) & 3)) << 4);
            cp16(st + GS_AH + so, Ah + gA);
            cp16(st + GS_AL + so, Al + gA);
            cp16(st + GS_WH + so, Wh + gW);
            cp16(st + GS_WL + so, Wl + gW);
        }
    };

    issue(0); CP_COMMIT();
    issue(1); CP_COMMIT();

    for (int t = 0; t < 32; t++) {
        CP_WAIT1();
        __syncthreads();
        const uint32_t st = sb + (uint32_t)(t % 3) * GSTG;
#pragma unroll
        for (int ks = 0; ks < 2; ks++) {
            uint32_t ah[4][4], al[4][4], bh[2][4], bl[2][4];
            const int cb = ks * 2 + lcb;
#pragma unroll
            for (int mt = 0; mt < 4; mt++) {
                int r = wm * 64 + mt * 16 + lrow;
                uint32_t ad = st + r * 64 + ((cb ^ ((r >> 1) & 3)) << 4);
                LDSM4(ah[mt], ad + GS_AH);
                LDSM4(al[mt], ad + GS_AL);
            }
#pragma unroll
            for (int p = 0; p < 2; p++) {
                int r = wn * 32 + p * 16 + lrow;
                uint32_t ad = st + r * 64 + ((cb ^ ((r >> 1) & 3)) << 4);
                LDSM4(bh[p], ad + GS_WH);
                LDSM4(bl[p], ad + GS_WL);
            }
#pragma unroll
            for (int mt = 0; mt < 4; mt++)
#pragma unroll
                for (int nt = 0; nt < 4; nt++)
                    MMA16816(acc[mt][nt], ah[mt], bh[nt >> 1][nt & 1], bh[nt >> 1][(nt & 1) + 2]);
#pragma unroll
            for (int mt = 0; mt < 4; mt++)
#pragma unroll
                for (int nt = 0; nt < 4; nt++)
                    MMA16816(acc[mt][nt], ah[mt], bl[nt >> 1][nt & 1], bl[nt >> 1][(nt & 1) + 2]);
#pragma unroll
            for (int mt = 0; mt < 4; mt++)
#pragma unroll
                for (int nt = 0; nt < 4; nt++)
                    MMA16816(acc[mt][nt], al[mt], bh[nt >> 1][nt & 1], bh[nt >> 1][(nt & 1) + 2]);
        }
        if (t + 2 < 32) issue(t + 2);
        CP_COMMIT();
    }

    const int g = lane >> 2, tig = lane & 3;
#pragma unroll
    for (int mt = 0; mt < 4; mt++) {
#pragma unroll
        for (int nt = 0; nt < 4; nt++) {
            int row = bm + wm * 64 + mt * 16 + g;
            int col = bn + wn * 32 + nt * 8 + tig * 2;
            float2 bv = *(const float2*)&bias[col];
            float v00 = acc[mt][nt][0] + bv.x, v01 = acc[mt][nt][1] + bv.y;
            float v10 = acc[mt][nt][2] + bv.x, v11 = acc[mt][nt][3] + bv.y;
            if (omode == 0) {
                *(float2*)(Cf + (size_t)row * D_ + col) = make_float2(v00, v01);
                *(float2*)(Cf + (size_t)(row + 8) * D_ + col) = make_float2(v10, v11);
            } else if (omode == 2) {
                uint32_t hh, ll;
                split2h(v00, v01, hh, ll);
                *(uint32_t*)(Fhi + (size_t)row * D_ + col) = hh;
                *(uint32_t*)(Flo + (size_t)row * D_ + col) = ll;
                split2h(v10, v11, hh, ll);
                *(uint32_t*)(Fhi + (size_t)(row + 8) * D_ + col) = hh;
                *(uint32_t*)(Flo + (size_t)(row + 8) * D_ + col) = ll;
            } else {
                *(uint32_t*)(Fhi + (size_t)row * D_ + col) = pack2h(v00, v01);
                *(uint32_t*)(Fhi + (size_t)(row + 8) * D_ + col) = pack2h(v10, v11);
            }
        }
    }
}

// Fused Q/K/V projection: z=0 -> Q (fp16 split), z=1 -> K, z=2 -> V (fp16 single)
__global__ void __launch_bounds__(256) gemm_qkv_kernel(
    const __nv_bfloat16* __restrict__ ah, const __nv_bfloat16* __restrict__ al,
    const __nv_bfloat16* __restrict__ bh, const __nv_bfloat16* __restrict__ bl,
    const __nv_bfloat16* __restrict__ wh, const __nv_bfloat16* __restrict__ wl,
    const float* __restrict__ bq, const float* __restrict__ bk,
    const float* __restrict__ bv,
    __half* __restrict__ qh, __half* __restrict__ ql,
    __half* __restrict__ kf, __half* __restrict__ vf)
{
    extern __shared__ char sm[];
    const int z = blockIdx.z;
    const __nv_bfloat16* Ah = (z == 0) ? ah : bh;
    const __nv_bfloat16* Al = (z == 0) ? al : bl;
    const __nv_bfloat16* Wh = wh + (size_t)z * D_ * D_;
    const __nv_bfloat16* Wl = wl + (size_t)z * D_ * D_;
    const float* bias = (z == 0) ? bq : (z == 1) ? bk : bv;
    __half* Fhi = (z == 0) ? qh : (z == 1) ? kf : vf;
    __half* Flo = (z == 0) ? ql : nullptr;
    gemm_body(sm, Ah, Al, Wh, Wl, bias, (z == 0) ? 2 : 3, nullptr, Fhi, Flo,
              blockIdx.y * 128, blockIdx.x * 128);
}

__global__ void __launch_bounds__(256) gemm_out_kernel(
    const __nv_bfloat16* __restrict__ Ah, const __nv_bfloat16* __restrict__ Al,
    const __nv_bfloat16* __restrict__ Wh, const __nv_bfloat16* __restrict__ Wl,
    const float* __restrict__ bias, float* __restrict__ Cf)
{
    extern __shared__ char sm[];
    gemm_body(sm, Ah, Al, Wh, Wl, bias, 0, Cf, nullptr, nullptr,
              blockIdx.y * 128, blockIdx.x * 128);
}

// ------------------------------ fp16 flash attention (2-pass split) --------
// Q split fp16 (exact to 2^-22), K/V single fp16. 2 MMAs per product.
// Smem: Q hi/lo 2x16KB + 2 stages x (K 8KB + V 8KB) = 64KB -> 3 CTAs/SM.
#define FQH 0
#define FQL 16384
#define FSB 32768
#define FK  0
#define FV  8192
#define FSTG 16384
#define FLASH_SMEM (FSB + 2 * FSTG)   // 65536

__global__ void __launch_bounds__(256) flash_mma_kernel(
    const __half* __restrict__ Qh_, const __half* __restrict__ Ql_,
    const __half* __restrict__ Kf_, const __half* __restrict__ Vf_,
    const int* __restrict__ mask,
    __nv_bfloat16* __restrict__ Ohi, __nv_bfloat16* __restrict__ Olo)
{
    extern __shared__ char sm[];
    const uint32_t sb = smem_u32(sm);
    const int tid = threadIdx.x, wid = tid >> 5, lane = tid & 31;
    const int h = blockIdx.x, qt = blockIdx.y, b = blockIdx.z;
    const int qbase = qt * 128;
    const int g = lane >> 2, t4 = lane & 3;

    auto issue_kv = [&](int t) {
        uint32_t st = sb + FSB + (uint32_t)(t & 1) * FSTG;
#pragma unroll
        for (int i = 0; i < 2; i++) {
            int f = tid + i * 256;
            int r = f >> 3, c = f & 7;
            size_t go = ((size_t)(b * S_ + t * 64 + r)) * D_ + h * DH_ + c * 8;
            uint32_t so = r * 128 + ((c ^ (r & 7)) << 4);
            cp16(st + FK + so, Kf_ + go);
            cp16(st + FV + so, Vf_ + go);
        }
    };

    issue_kv(0); CP_COMMIT();

#pragma unroll
    for (int i = 0; i < 4; i++) {
        int f = tid + i * 256;
        int r = f >> 3, c = f & 7;
        size_t go = ((size_t)(b * S_ + qbase + r)) * D_ + h * DH_ + c * 8;
        uint32_t so = r * 128 + ((c ^ (r & 7)) << 4);
        *(uint4*)(sm + FQH + so) = *(const uint4*)(Qh_ + go);
        *(uint4*)(sm + FQL + so) = *(const uint4*)(Ql_ + go);
    }
    __syncthreads();

    uint32_t qh[4][4], ql[4][4];
    {
        const int lrow = wid * 16 + ((lane >> 3) & 1) * 8 + (lane & 7);
        const int lcb  = lane >> 4;
#pragma unroll
        for (int ks = 0; ks < 4; ks++) {
            uint32_t ad = sb + lrow * 128 + (((2 * ks + lcb) ^ (lrow & 7)) << 4);
            LDSM4(qh[ks], ad + FQH);
            LDSM4(ql[ks], ad + FQL);
        }
    }

    float o[8][4];
#pragma unroll
    for (int n = 0; n < 8; n++)
#pragma unroll
        for (int e = 0; e < 4; e++) o[n][e] = 0.f;
    float m0 = -1e30f, m1 = -1e30f, l0 = 0.f, l1 = 0.f;

    const int qr0 = qbase + wid * 16 + g;
    const size_t mrow0 = ((size_t)b * S_ + qr0) * S_;
    const size_t mrow1 = mrow0 + (size_t)8 * S_;

    for (int t = 0; t < S_ / 64; t++) {
        const int kvb = t * 64;
        if (t + 1 < S_ / 64) issue_kv(t + 1);
        CP_COMMIT();
        CP_WAIT1();
        __syncthreads();
        const uint32_t st = sb + FSB + (uint32_t)(t & 1) * FSTG;

        // ---- S = Q @ K^T : 2-pass fp16 split
        float s[8][4];
#pragma unroll
        for (int n = 0; n < 8; n++)
#pragma unroll
            for (int e = 0; e < 4; e++) s[n][e] = 0.f;

        {
            const int krow = ((lane >> 4) << 3) + (lane & 7);
            const int kchb = (lane >> 3) & 1;
#pragma unroll
            for (int ks = 0; ks < 4; ks++) {
                const int kch = 2 * ks + kchb;
#pragma unroll
                for (int ng = 0; ng < 4; ng++) {
                    int r = ng * 16 + krow;
                    uint32_t ad = st + FK + r * 128 + ((kch ^ (r & 7)) << 4);
                    uint32_t k4[4];
                    LDSM4(k4, ad);
                    MMAF16(s[2 * ng],     qh[ks], k4[0], k4[1]);
                    MMAF16(s[2 * ng + 1], qh[ks], k4[2], k4[3]);
                    MMAF16(s[2 * ng],     ql[ks], k4[0], k4[1]);
                    MMAF16(s[2 * ng + 1], ql[ks], k4[2], k4[3]);
                }
            }
        }

        // ---- mask + scale + online softmax
        float mx0 = -1e30f, mx1 = -1e30f;
#pragma unroll
        for (int n = 0; n < 8; n++) {
            const int col = kvb + n * 8 + t4 * 2;
            int2 ma = *(const int2*)(mask + mrow0 + col);
            int2 mb = *(const int2*)(mask + mrow1 + col);
            s[n][0] = ma.x ? s[n][0] * 0.125f : -1e9f;
            s[n][1] = ma.y ? s[n][1] * 0.125f : -1e9f;
            s[n][2] = mb.x ? s[n][2] * 0.125f : -1e9f;
            s[n][3] = mb.y ? s[n][3] * 0.125f : -1e9f;
            mx0 = fmaxf(mx0, fmaxf(s[n][0], s[n][1]));
            mx1 = fmaxf(mx1, fmaxf(s[n][2], s[n][3]));
        }
        mx0 = fmaxf(mx0, __shfl_xor_sync(0xffffffffu, mx0, 1));
        mx0 = fmaxf(mx0, __shfl_xor_sync(0xffffffffu, mx0, 2));
        mx1 = fmaxf(mx1, __shfl_xor_sync(0xffffffffu, mx1, 1));
        mx1 = fmaxf(mx1, __shfl_xor_sync(0xffffffffu, mx1, 2));

        float mn0 = fmaxf(m0, mx0), mn1 = fmaxf(m1, mx1);
        float al0 = __expf(m0 - mn0), al1 = __expf(m1 - mn1);
        m0 = mn0; m1 = mn1;

        float rs0 = 0.f, rs1 = 0.f;
#pragma unroll
        for (int n = 0; n < 8; n++) {
            s[n][0] = __expf(s[n][0] - mn0);
            s[n][1] = __expf(s[n][1] - mn0);
            s[n][2] = __expf(s[n][2] - mn1);
            s[n][3] = __expf(s[n][3] - mn1);
            rs0 += s[n][0] + s[n][1];
            rs1 += s[n][2] + s[n][3];
        }
        rs0 += __shfl_xor_sync(0xffffffffu, rs0, 1);
        rs0 += __shfl_xor_sync(0xffffffffu, rs0, 2);
        rs1 += __shfl_xor_sync(0xffffffffu, rs1, 1);
        rs1 += __shfl_xor_sync(0xffffffffu, rs1, 2);
        l0 = l0 * al0 + rs0;
        l1 = l1 * al1 + rs1;
#pragma unroll
        for (int n = 0; n < 8; n++) {
            o[n][0] *= al0; o[n][1] *= al0;
            o[n][2] *= al1; o[n][3] *= al1;
        }

        // ---- O += P @ V : 2-pass fp16 split (P split, V single)
        {
            const int vrow_b = ((lane >> 3) & 1) * 8 + (lane & 7);
            const int vchb   = lane >> 4;
#pragma unroll
            for (int ks = 0; ks < 4; ks++) {
                uint32_t ph4[4], pl4[4];
                split2h(s[2 * ks][0],     s[2 * ks][1],     ph4[0], pl4[0]);
                split2h(s[2 * ks][2],     s[2 * ks][3],     ph4[1], pl4[1]);
                split2h(s[2 * ks + 1][0], s[2 * ks + 1][1], ph4[2], pl4[2]);
                split2h(s[2 * ks + 1][2], s[2 * ks + 1][3], ph4[3], pl4[3]);
                const int vrow = ks * 16 + vrow_b;
#pragma unroll
                for (int ng = 0; ng < 4; ng++) {
                    uint32_t ad = st + FV + vrow * 128 + (((2 * ng + vchb) ^ (vrow & 7)) << 4);
                    uint32_t v4[4];
                    LDSM4T(v4, ad);
                    MMAF16(o[2 * ng],     ph4, v4[0], v4[1]);
                    MMAF16(o[2 * ng + 1], ph4, v4[2], v4[3]);
                    MMAF16(o[2 * ng],     pl4, v4[0], v4[1]);
                    MMAF16(o[2 * ng + 1], pl4, v4[2], v4[3]);
                }
            }
        }
        __syncthreads();
    }

    const float inv0 = 1.f / l0, inv1 = 1.f / l1;
#pragma unroll
    for (int n = 0; n < 8; n++) {
        const int col = h * DH_ + n * 8 + t4 * 2;
        size_t o0 = ((size_t)(b * S_ + qr0)) * D_ + col;
        size_t o1 = o0 + (size_t)8 * D_;
        uint32_t hh, ll;
        split2(o[n][0] * inv0, o[n][1] * inv0, hh, ll);
        *(uint32_t*)(Ohi + o0) = hh;
        *(uint32_t*)(Olo + o0) = ll;
        split2(o[n][2] * inv1, o[n][3] * inv1, hh, ll);
        *(uint32_t*)(Ohi + o1) = hh;
        *(uint32_t*)(Olo + o1) = ll;
    }
}

// ---------------------------------------------------------------------------
extern "C" void kernel_launch(void* const* d_in, const int* in_sizes, int n_in,
                              void* d_out, int out_size)
{
    (void)in_sizes; (void)n_in; (void)out_size;
    const float* q_tok  = (const float*)d_in[0];
    const float* kv_tok = (const float*)d_in[1];
    const int*   mask   = (const int*)d_in[2];
    const float* Wq = (const float*)d_in[3];
    const float* bq = (const float*)d_in[4];
    const float* Wk = (const float*)d_in[5];
    const float* bk = (const float*)d_in[6];
    const float* Wv = (const float*)d_in[7];
    const float* bv = (const float*)d_in[8];
    const float* Wo = (const float*)d_in[9];
    const float* bo = (const float*)d_in[10];
    float* out = (float*)d_out;

    __nv_bfloat16 *ah, *al, *bh, *bl, *wh, *wl, *ch, *cl;
    __half *qh, *ql, *kf, *vf;
    cudaGetSymbolAddress((void**)&ah, g_ah);
    cudaGetSymbolAddress((void**)&al, g_al);
    cudaGetSymbolAddress((void**)&bh, g_bh);
    cudaGetSymbolAddress((void**)&bl, g_bl);
    cudaGetSymbolAddress((void**)&wh, g_wh);
    cudaGetSymbolAddress((void**)&wl, g_wl);
    cudaGetSymbolAddress((void**)&qh, g_qh);
    cudaGetSymbolAddress((void**)&ql, g_ql);
    cudaGetSymbolAddress((void**)&kf, g_kf);
    cudaGetSymbolAddress((void**)&vf, g_vf);
    cudaGetSymbolAddress((void**)&ch, g_ch);
    cudaGetSymbolAddress((void**)&cl, g_cl);

    cudaFuncSetAttribute(gemm_qkv_kernel,
                         cudaFuncAttributeMaxDynamicSharedMemorySize, GEMM_SMEM);
    cudaFuncSetAttribute(gemm_out_kernel,
                         cudaFuncAttributeMaxDynamicSharedMemorySize, GEMM_SMEM);
    cudaFuncSetAttribute(flash_mma_kernel,
                         cudaFuncAttributeMaxDynamicSharedMemorySize, FLASH_SMEM);

    const int nTok = M_ * D_;
    const int nW = D_ * D_;

    split_kernel<<<nTok / 1024, 256>>>(q_tok,  ah, al, nTok);
    split_kernel<<<nTok / 1024, 256>>>(kv_tok, bh, bl, nTok);
    dim3 wgrid(nW / 1024, 4);
    split4_kernel<<<wgrid, 256>>>(Wq, Wk, Wv, Wo, wh, wl, nW);

    dim3 qkvgrid(D_ / 128, M_ / 128, 3);   // (8, 32, 3)
    gemm_qkv_kernel<<<qkvgrid, 256, GEMM_SMEM>>>(
        ah, al, bh, bl, wh, wl, bq, bk, bv, qh, ql, kf, vf);

    dim3 fgrid(H_, S_ / 128, B_);          // (16, 16, 2)
    flash_mma_kernel<<<fgrid, 256, FLASH_SMEM>>>(qh, ql, kf, vf, mask, ch, cl);

    dim3 ogrid(D_ / 128, M_ / 128);
    gemm_out_kernel<<<ogrid, 256, GEMM_SMEM>>>(
        ch, cl, wh + 3 * (size_t)nW, wl + 3 * (size_t)nW, bo, out);
}

// round 9
// speedup vs baseline: 3.8294x; 1.1690x over previous
#include <cuda_runtime.h>
#include <cuda_bf16.h>
#include <cuda_fp16.h>
#include <cstdint>

#define B_  2
#define S_  2048
#define D_  1024
#define H_  16
#define DH_ 64
#define M_  (B_*S_)   // 4096

// ------------------------------ scratch (allocation-free rule) -------------
__device__ __half g_ah[(size_t)M_ * D_];   // q tokens fp16 hi/lo
__device__ __half g_al[(size_t)M_ * D_];
__device__ __half g_bh[(size_t)M_ * D_];   // kv tokens fp16 hi/lo
__device__ __half g_bl[(size_t)M_ * D_];
__device__ __half g_wf[(size_t)4 * D_ * D_];  // Wq,Wk,Wv,Wo single fp16
__device__ __half g_qh[(size_t)M_ * D_];   // Q proj fp16 hi/lo
__device__ __half g_ql[(size_t)M_ * D_];
__device__ __half g_kf[(size_t)M_ * D_];   // K proj fp16 single
__device__ __half g_vf[(size_t)M_ * D_];   // V proj fp16 single
__device__ __half g_ch[(size_t)M_ * D_];   // ctx fp16 hi/lo
__device__ __half g_cl[(size_t)M_ * D_];

// ------------------------------ helpers ------------------------------------
__device__ __forceinline__ uint32_t smem_u32(const void* p) {
    uint32_t a;
    asm("{ .reg .u64 t; cvta.to.shared.u64 t, %1; cvt.u32.u64 %0, t; }"
        : "=r"(a) : "l"(p));
    return a;
}
__device__ __forceinline__ void cp16(uint32_t s, const void* g) {
    asm volatile("cp.async.cg.shared.global [%0], [%1], 16;" :: "r"(s), "l"(g));
}
#define CP_COMMIT() asm volatile("cp.async.commit_group;" ::: "memory")
#define CP_WAIT1()  asm volatile("cp.async.wait_group 1;" ::: "memory")

#define LDSM4(r, addr) \
    asm volatile("ldmatrix.sync.aligned.m8n8.x4.shared.b16 {%0,%1,%2,%3}, [%4];" \
        : "=r"((r)[0]), "=r"((r)[1]), "=r"((r)[2]), "=r"((r)[3]) : "r"(addr))

#define LDSM4T(r, addr) \
    asm volatile("ldmatrix.sync.aligned.m8n8.x4.trans.shared.b16 {%0,%1,%2,%3}, [%4];" \
        : "=r"((r)[0]), "=r"((r)[1]), "=r"((r)[2]), "=r"((r)[3]) : "r"(addr))

#define MMAF16(d, a, b0, b1) \
    asm volatile("mma.sync.aligned.m16n8k16.row.col.f32.f16.f16.f32 " \
        "{%0,%1,%2,%3}, {%4,%5,%6,%7}, {%8,%9}, {%0,%1,%2,%3};" \
        : "+f"((d)[0]), "+f"((d)[1]), "+f"((d)[2]), "+f"((d)[3]) \
        : "r"((a)[0]), "r"((a)[1]), "r"((a)[2]), "r"((a)[3]), "r"(b0), "r"(b1))

__device__ __forceinline__ void split2h(float x, float y, uint32_t& h, uint32_t& l) {
    __half2 hh = __floats2half2_rn(x, y);
    __half2 ll = __floats2half2_rn(x - __half2float(__low2half(hh)),
                                   y - __half2float(__high2half(hh)));
    h = *(uint32_t*)&hh;
    l = *(uint32_t*)&ll;
}
__device__ __forceinline__ uint32_t pack2h(float x, float y) {
    __half2 hh = __floats2half2_rn(x, y);
    return *(uint32_t*)&hh;
}

// ------------------------------ split kernels -------------------------------
// tokens: fp32 -> fp16 hi/lo (exact to 2^-22)
__global__ void __launch_bounds__(256) split_kernel(
    const float* __restrict__ x, __half* __restrict__ hi,
    __half* __restrict__ lo, int n)
{
    int i = (blockIdx.x * 256 + threadIdx.x) * 4;
    if (i >= n) return;
    float4 v = *(const float4*)(x + i);
    uint32_t h0, l0, h1, l1;
    split2h(v.x, v.y, h0, l0);
    split2h(v.z, v.w, h1, l1);
    *(uint2*)((char*)hi + (size_t)i * 2) = make_uint2(h0, h1);
    *(uint2*)((char*)lo + (size_t)i * 2) = make_uint2(l0, l1);
}

// weights: fp32 -> single fp16
__global__ void __launch_bounds__(256) cvt4_kernel(
    const float* __restrict__ w0, const float* __restrict__ w1,
    const float* __restrict__ w2, const float* __restrict__ w3,
    __half* __restrict__ wf, int n)
{
    const float* src = (blockIdx.y == 0) ? w0 : (blockIdx.y == 1) ? w1
                     : (blockIdx.y == 2) ? w2 : w3;
    size_t base = (size_t)blockIdx.y * n;
    int i = (blockIdx.x * 256 + threadIdx.x) * 4;
    if (i >= n) return;
    float4 v = *(const float4*)(src + i);
    *(uint2*)((char*)(wf + base) + (size_t)i * 2) =
        make_uint2(pack2h(v.x, v.y), pack2h(v.z, v.w));
}

// ------------------------------ fp16 GEMM body (3-stage cp.async) ----------
// C = (Ah+Al) @ W^T + bias, 2 MMA passes (A split fp16, W single fp16).
#define GS_AH 0
#define GS_AL 8192
#define GS_W  16384
#define GSTG  24576
#define GEMM_SMEM (3 * GSTG)   // 73728

__device__ __forceinline__ void gemm_body(
    char* sm,
    const __half* __restrict__ Ah, const __half* __restrict__ Al,
    const __half* __restrict__ W,
    const float* __restrict__ bias, int omode, float* __restrict__ Cf,
    __half* __restrict__ Fhi, __half* __restrict__ Flo,
    int bm, int bn)
{
    const uint32_t sb = smem_u32(sm);
    const int tid = threadIdx.x;
    const int wid = tid >> 5, lane = tid & 31;
    const int wm = wid >> 2, wn = wid & 3;

    const int lrow = (lane & 7) + ((lane >> 3) & 1) * 8;
    const int lcb  = lane >> 4;

    float acc[4][4][4];
#pragma unroll
    for (int mt = 0; mt < 4; mt++)
#pragma unroll
        for (int nt = 0; nt < 4; nt++)
#pragma unroll
            for (int e = 0; e < 4; e++) acc[mt][nt][e] = 0.f;

    auto issue = [&](int t) {
        uint32_t st = sb + (uint32_t)(t % 3) * GSTG;
#pragma unroll
        for (int i = 0; i < 2; i++) {
            int f = tid + i * 256;
            int r = f >> 2, cb = f & 3;
            size_t gA = (size_t)(bm + r) * D_ + t * 32 + cb * 8;
            size_t gW = (size_t)(bn + r) * D_ + t * 32 + cb * 8;
            uint32_t so = r * 64 + ((cb ^ ((r >> 1) & 3)) << 4);
            cp16(st + GS_AH + so, Ah + gA);
            cp16(st + GS_AL + so, Al + gA);
            cp16(st + GS_W  + so, W  + gW);
        }
    };

    issue(0); CP_COMMIT();
    issue(1); CP_COMMIT();

    for (int t = 0; t < 32; t++) {
        CP_WAIT1();
        __syncthreads();
        const uint32_t st = sb + (uint32_t)(t % 3) * GSTG;
#pragma unroll
        for (int ks = 0; ks < 2; ks++) {
            uint32_t ah[4][4], al[4][4], w2[2][4];
            const int cb = ks * 2 + lcb;
#pragma unroll
            for (int mt = 0; mt < 4; mt++) {
                int r = wm * 64 + mt * 16 + lrow;
                uint32_t ad = st + r * 64 + ((cb ^ ((r >> 1) & 3)) << 4);
                LDSM4(ah[mt], ad + GS_AH);
                LDSM4(al[mt], ad + GS_AL);
            }
#pragma unroll
            for (int p = 0; p < 2; p++) {
                int r = wn * 32 + p * 16 + lrow;
                uint32_t ad = st + r * 64 + ((cb ^ ((r >> 1) & 3)) << 4);
                LDSM4(w2[p], ad + GS_W);
            }
#pragma unroll
            for (int mt = 0; mt < 4; mt++)
#pragma unroll
                for (int nt = 0; nt < 4; nt++)
                    MMAF16(acc[mt][nt], ah[mt], w2[nt >> 1][nt & 1], w2[nt >> 1][(nt & 1) + 2]);
#pragma unroll
            for (int mt = 0; mt < 4; mt++)
#pragma unroll
                for (int nt = 0; nt < 4; nt++)
                    MMAF16(acc[mt][nt], al[mt], w2[nt >> 1][nt & 1], w2[nt >> 1][(nt & 1) + 2]);
        }
        if (t + 2 < 32) issue(t + 2);
        CP_COMMIT();
    }

    const int g = lane >> 2, tig = lane & 3;
#pragma unroll
    for (int mt = 0; mt < 4; mt++) {
#pragma unroll
        for (int nt = 0; nt < 4; nt++) {
            int row = bm + wm * 64 + mt * 16 + g;
            int col = bn + wn * 32 + nt * 8 + tig * 2;
            float2 bv = *(const float2*)&bias[col];
            float v00 = acc[mt][nt][0] + bv.x, v01 = acc[mt][nt][1] + bv.y;
            float v10 = acc[mt][nt][2] + bv.x, v11 = acc[mt][nt][3] + bv.y;
            if (omode == 0) {
                *(float2*)(Cf + (size_t)row * D_ + col) = make_float2(v00, v01);
                *(float2*)(Cf + (size_t)(row + 8) * D_ + col) = make_float2(v10, v11);
            } else if (omode == 2) {
                uint32_t hh, ll;
                split2h(v00, v01, hh, ll);
                *(uint32_t*)(Fhi + (size_t)row * D_ + col) = hh;
                *(uint32_t*)(Flo + (size_t)row * D_ + col) = ll;
                split2h(v10, v11, hh, ll);
                *(uint32_t*)(Fhi + (size_t)(row + 8) * D_ + col) = hh;
                *(uint32_t*)(Flo + (size_t)(row + 8) * D_ + col) = ll;
            } else {
                *(uint32_t*)(Fhi + (size_t)row * D_ + col) = pack2h(v00, v01);
                *(uint32_t*)(Fhi + (size_t)(row + 8) * D_ + col) = pack2h(v10, v11);
            }
        }
    }
}

// Fused Q/K/V projection: z=0 -> Q (fp16 split out), z=1/2 -> K/V (fp16 single)
__global__ void __launch_bounds__(256) gemm_qkv_kernel(
    const __half* __restrict__ ah, const __half* __restrict__ al,
    const __half* __restrict__ bh, const __half* __restrict__ bl,
    const __half* __restrict__ wf,
    const float* __restrict__ bq, const float* __restrict__ bk,
    const float* __restrict__ bv,
    __half* __restrict__ qh, __half* __restrict__ ql,
    __half* __restrict__ kf, __half* __restrict__ vf)
{
    extern __shared__ char sm[];
    const int z = blockIdx.z;
    const __half* Ah = (z == 0) ? ah : bh;
    const __half* Al = (z == 0) ? al : bl;
    const __half* W  = wf + (size_t)z * D_ * D_;
    const float* bias = (z == 0) ? bq : (z == 1) ? bk : bv;
    __half* Fhi = (z == 0) ? qh : (z == 1) ? kf : vf;
    __half* Flo = (z == 0) ? ql : nullptr;
    gemm_body(sm, Ah, Al, W, bias, (z == 0) ? 2 : 3, nullptr, Fhi, Flo,
              blockIdx.y * 128, blockIdx.x * 128);
}

__global__ void __launch_bounds__(256) gemm_out_kernel(
    const __half* __restrict__ Ah, const __half* __restrict__ Al,
    const __half* __restrict__ W,
    const float* __restrict__ bias, float* __restrict__ Cf)
{
    extern __shared__ char sm[];
    gemm_body(sm, Ah, Al, W, bias, 0, Cf, nullptr, nullptr,
              blockIdx.y * 128, blockIdx.x * 128);
}

// ------------------------------ fp16 flash attention (2-pass split) --------
#define FQH 0
#define FQL 16384
#define FSB 32768
#define FK  0
#define FV  8192
#define FSTG 16384
#define FLASH_SMEM (FSB + 2 * FSTG)   // 65536

__global__ void __launch_bounds__(256) flash_mma_kernel(
    const __half* __restrict__ Qh_, const __half* __restrict__ Ql_,
    const __half* __restrict__ Kf_, const __half* __restrict__ Vf_,
    const int* __restrict__ mask,
    __half* __restrict__ Ohi, __half* __restrict__ Olo)
{
    extern __shared__ char sm[];
    const uint32_t sb = smem_u32(sm);
    const int tid = threadIdx.x, wid = tid >> 5, lane = tid & 31;
    const int h = blockIdx.x, qt = blockIdx.y, b = blockIdx.z;
    const int qbase = qt * 128;
    const int g = lane >> 2, t4 = lane & 3;

    auto issue_kv = [&](int t) {
        uint32_t st = sb + FSB + (uint32_t)(t & 1) * FSTG;
#pragma unroll
        for (int i = 0; i < 2; i++) {
            int f = tid + i * 256;
            int r = f >> 3, c = f & 7;
            size_t go = ((size_t)(b * S_ + t * 64 + r)) * D_ + h * DH_ + c * 8;
            uint32_t so = r * 128 + ((c ^ (r & 7)) << 4);
            cp16(st + FK + so, Kf_ + go);
            cp16(st + FV + so, Vf_ + go);
        }
    };

    issue_kv(0); CP_COMMIT();

#pragma unroll
    for (int i = 0; i < 4; i++) {
        int f = tid + i * 256;
        int r = f >> 3, c = f & 7;
        size_t go = ((size_t)(b * S_ + qbase + r)) * D_ + h * DH_ + c * 8;
        uint32_t so = r * 128 + ((c ^ (r & 7)) << 4);
        *(uint4*)(sm + FQH + so) = *(const uint4*)(Qh_ + go);
        *(uint4*)(sm + FQL + so) = *(const uint4*)(Ql_ + go);
    }
    __syncthreads();

    uint32_t qh[4][4], ql[4][4];
    {
        const int lrow = wid * 16 + ((lane >> 3) & 1) * 8 + (lane & 7);
        const int lcb  = lane >> 4;
#pragma unroll
        for (int ks = 0; ks < 4; ks++) {
            uint32_t ad = sb + lrow * 128 + (((2 * ks + lcb) ^ (lrow & 7)) << 4);
            LDSM4(qh[ks], ad + FQH);
            LDSM4(ql[ks], ad + FQL);
        }
    }

    float o[8][4];
#pragma unroll
    for (int n = 0; n < 8; n++)
#pragma unroll
        for (int e = 0; e < 4; e++) o[n][e] = 0.f;
    float m0 = -1e30f, m1 = -1e30f, l0 = 0.f, l1 = 0.f;

    const int qr0 = qbase + wid * 16 + g;
    const size_t mrow0 = ((size_t)b * S_ + qr0) * S_;
    const size_t mrow1 = mrow0 + (size_t)8 * S_;

    for (int t = 0; t < S_ / 64; t++) {
        const int kvb = t * 64;
        if (t + 1 < S_ / 64) issue_kv(t + 1);
        CP_COMMIT();
        CP_WAIT1();
        __syncthreads();
        const uint32_t st = sb + FSB + (uint32_t)(t & 1) * FSTG;

        float s[8][4];
#pragma unroll
        for (int n = 0; n < 8; n++)
#pragma unroll
            for (int e = 0; e < 4; e++) s[n][e] = 0.f;

        {
            const int krow = ((lane >> 4) << 3) + (lane & 7);
            const int kchb = (lane >> 3) & 1;
#pragma unroll
            for (int ks = 0; ks < 4; ks++) {
                const int kch = 2 * ks + kchb;
#pragma unroll
                for (int ng = 0; ng < 4; ng++) {
                    int r = ng * 16 + krow;
                    uint32_t ad = st + FK + r * 128 + ((kch ^ (r & 7)) << 4);
                    uint32_t k4[4];
                    LDSM4(k4, ad);
                    MMAF16(s[2 * ng],     qh[ks], k4[0], k4[1]);
                    MMAF16(s[2 * ng + 1], qh[ks], k4[2], k4[3]);
                    MMAF16(s[2 * ng],     ql[ks], k4[0], k4[1]);
                    MMAF16(s[2 * ng + 1], ql[ks], k4[2], k4[3]);
                }
            }
        }

        float mx0 = -1e30f, mx1 = -1e30f;
#pragma unroll
        for (int n = 0; n < 8; n++) {
            const int col = kvb + n * 8 + t4 * 2;
            int2 ma = *(const int2*)(mask + mrow0 + col);
            int2 mb = *(const int2*)(mask + mrow1 + col);
            s[n][0] = ma.x ? s[n][0] * 0.125f : -1e9f;
            s[n][1] = ma.y ? s[n][1] * 0.125f : -1e9f;
            s[n][2] = mb.x ? s[n][2] * 0.125f : -1e9f;
            s[n][3] = mb.y ? s[n][3] * 0.125f : -1e9f;
            mx0 = fmaxf(mx0, fmaxf(s[n][0], s[n][1]));
            mx1 = fmaxf(mx1, fmaxf(s[n][2], s[n][3]));
        }
        mx0 = fmaxf(mx0, __shfl_xor_sync(0xffffffffu, mx0, 1));
        mx0 = fmaxf(mx0, __shfl_xor_sync(0xffffffffu, mx0, 2));
        mx1 = fmaxf(mx1, __shfl_xor_sync(0xffffffffu, mx1, 1));
        mx1 = fmaxf(mx1, __shfl_xor_sync(0xffffffffu, mx1, 2));

        float mn0 = fmaxf(m0, mx0), mn1 = fmaxf(m1, mx1);
        float al0 = __expf(m0 - mn0), al1 = __expf(m1 - mn1);
        m0 = mn0; m1 = mn1;

        float rs0 = 0.f, rs1 = 0.f;
#pragma unroll
        for (int n = 0; n < 8; n++) {
            s[n][0] = __expf(s[n][0] - mn0);
            s[n][1] = __expf(s[n][1] - mn0);
            s[n][2] = __expf(s[n][2] - mn1);
            s[n][3] = __expf(s[n][3] - mn1);
            rs0 += s[n][0] + s[n][1];
            rs1 += s[n][2] + s[n][3];
        }
        rs0 += __shfl_xor_sync(0xffffffffu, rs0, 1);
        rs0 += __shfl_xor_sync(0xffffffffu, rs0, 2);
        rs1 += __shfl_xor_sync(0xffffffffu, rs1, 1);
        rs1 += __shfl_xor_sync(0xffffffffu, rs1, 2);
        l0 = l0 * al0 + rs0;
        l1 = l1 * al1 + rs1;
#pragma unroll
        for (int n = 0; n < 8; n++) {
            o[n][0] *= al0; o[n][1] *= al0;
            o[n][2] *= al1; o[n][3] *= al1;
        }

        {
            const int vrow_b = ((lane >> 3) & 1) * 8 + (lane & 7);
            const int vchb   = lane >> 4;
#pragma unroll
            for (int ks = 0; ks < 4; ks++) {
                uint32_t ph4[4], pl4[4];
                split2h(s[2 * ks][0],     s[2 * ks][1],     ph4[0], pl4[0]);
                split2h(s[2 * ks][2],     s[2 * ks][3],     ph4[1], pl4[1]);
                split2h(s[2 * ks + 1][0], s[2 * ks + 1][1], ph4[2], pl4[2]);
                split2h(s[2 * ks + 1][2], s[2 * ks + 1][3], ph4[3], pl4[3]);
                const int vrow = ks * 16 + vrow_b;
#pragma unroll
                for (int ng = 0; ng < 4; ng++) {
                    uint32_t ad = st + FV + vrow * 128 + (((2 * ng + vchb) ^ (vrow & 7)) << 4);
                    uint32_t v4[4];
                    LDSM4T(v4, ad);
                    MMAF16(o[2 * ng],     ph4, v4[0], v4[1]);
                    MMAF16(o[2 * ng + 1], ph4, v4[2], v4[3]);
                    MMAF16(o[2 * ng],     pl4, v4[0], v4[1]);
                    MMAF16(o[2 * ng + 1], pl4, v4[2], v4[3]);
                }
            }
        }
        __syncthreads();
    }

    const float inv0 = 1.f / l0, inv1 = 1.f / l1;
#pragma unroll
    for (int n = 0; n < 8; n++) {
        const int col = h * DH_ + n * 8 + t4 * 2;
        size_t o0 = ((size_t)(b * S_ + qr0)) * D_ + col;
        size_t o1 = o0 + (size_t)8 * D_;
        uint32_t hh, ll;
        split2h(o[n][0] * inv0, o[n][1] * inv0, hh, ll);
        *(uint32_t*)(Ohi + o0) = hh;
        *(uint32_t*)(Olo + o0) = ll;
        split2h(o[n][2] * inv1, o[n][3] * inv1, hh, ll);
        *(uint32_t*)(Ohi + o1) = hh;
        *(uint32_t*)(Olo + o1) = ll;
    }
}

// ---------------------------------------------------------------------------
extern "C" void kernel_launch(void* const* d_in, const int* in_sizes, int n_in,
                              void* d_out, int out_size)
{
    (void)in_sizes; (void)n_in; (void)out_size;
    const float* q_tok  = (const float*)d_in[0];
    const float* kv_tok = (const float*)d_in[1];
    const int*   mask   = (const int*)d_in[2];
    const float* Wq = (const float*)d_in[3];
    const float* bq = (const float*)d_in[4];
    const float* Wk = (const float*)d_in[5];
    const float* bk = (const float*)d_in[6];
    const float* Wv = (const float*)d_in[7];
    const float* bv = (const float*)d_in[8];
    const float* Wo = (const float*)d_in[9];
    const float* bo = (const float*)d_in[10];
    float* out = (float*)d_out;

    __half *ah, *al, *bh, *bl, *wf, *qh, *ql, *kf, *vf, *ch, *cl;
    cudaGetSymbolAddress((void**)&ah, g_ah);
    cudaGetSymbolAddress((void**)&al, g_al);
    cudaGetSymbolAddress((void**)&bh, g_bh);
    cudaGetSymbolAddress((void**)&bl, g_bl);
    cudaGetSymbolAddress((void**)&wf, g_wf);
    cudaGetSymbolAddress((void**)&qh, g_qh);
    cudaGetSymbolAddress((void**)&ql, g_ql);
    cudaGetSymbolAddress((void**)&kf, g_kf);
    cudaGetSymbolAddress((void**)&vf, g_vf);
    cudaGetSymbolAddress((void**)&ch, g_ch);
    cudaGetSymbolAddress((void**)&cl, g_cl);

    cudaFuncSetAttribute(gemm_qkv_kernel,
                         cudaFuncAttributeMaxDynamicSharedMemorySize, GEMM_SMEM);
    cudaFuncSetAttribute(gemm_out_kernel,
                         cudaFuncAttributeMaxDynamicSharedMemorySize, GEMM_SMEM);
    cudaFuncSetAttribute(flash_mma_kernel,
                         cudaFuncAttributeMaxDynamicSharedMemorySize, FLASH_SMEM);

    const int nTok = M_ * D_;
    const int nW = D_ * D_;

    split_kernel<<<nTok / 1024, 256>>>(q_tok,  ah, al, nTok);
    split_kernel<<<nTok / 1024, 256>>>(kv_tok, bh, bl, nTok);
    dim3 wgrid(nW / 1024, 4);
    cvt4_kernel<<<wgrid, 256>>>(Wq, Wk, Wv, Wo, wf, nW);

    dim3 qkvgrid(D_ / 128, M_ / 128, 3);   // (8, 32, 3)
    gemm_qkv_kernel<<<qkvgrid, 256, GEMM_SMEM>>>(
        ah, al, bh, bl, wf, bq, bk, bv, qh, ql, kf, vf);

    dim3 fgrid(H_, S_ / 128, B_);          // (16, 16, 2)
    flash_mma_kernel<<<fgrid, 256, FLASH_SMEM>>>(qh, ql, kf, vf, mask, ch, cl);

    dim3 ogrid(D_ / 128, M_ / 128);
    gemm_out_kernel<<<ogrid, 256, GEMM_SMEM>>>(
        ch, cl, wf + 3 * (size_t)nW, bo, out);
}

// round 10
// speedup vs baseline: 4.4725x; 1.1680x over previous
#include <cuda_runtime.h>
#include <cuda_bf16.h>
#include <cuda_fp16.h>
#include <cstdint>

#define B_  2
#define S_  2048
#define D_  1024
#define H_  16
#define DH_ 64
#define M_  (B_*S_)   // 4096

// ------------------------------ scratch (allocation-free rule) -------------
__device__ __half g_ah[(size_t)M_ * D_];   // q tokens fp16 hi/lo
__device__ __half g_al[(size_t)M_ * D_];
__device__ __half g_bh[(size_t)M_ * D_];   // kv tokens fp16 hi/lo
__device__ __half g_bl[(size_t)M_ * D_];
__device__ __half g_wf[(size_t)4 * D_ * D_];  // Wq,Wk,Wv,Wo single fp16
__device__ __half g_qf[(size_t)M_ * D_];   // Q proj fp16 single
__device__ __half g_kf[(size_t)M_ * D_];   // K proj fp16 single
__device__ __half g_vf[(size_t)M_ * D_];   // V proj fp16 single
__device__ __half g_ch[(size_t)M_ * D_];   // ctx fp16 hi/lo
__device__ __half g_cl[(size_t)M_ * D_];

// ------------------------------ helpers ------------------------------------
__device__ __forceinline__ uint32_t smem_u32(const void* p) {
    uint32_t a;
    asm("{ .reg .u64 t; cvta.to.shared.u64 t, %1; cvt.u32.u64 %0, t; }"
        : "=r"(a) : "l"(p));
    return a;
}
__device__ __forceinline__ void cp16(uint32_t s, const void* g) {
    asm volatile("cp.async.cg.shared.global [%0], [%1], 16;" :: "r"(s), "l"(g));
}
#define CP_COMMIT() asm volatile("cp.async.commit_group;" ::: "memory")
#define CP_WAIT1()  asm volatile("cp.async.wait_group 1;" ::: "memory")

#define LDSM4(r, addr) \
    asm volatile("ldmatrix.sync.aligned.m8n8.x4.shared.b16 {%0,%1,%2,%3}, [%4];" \
        : "=r"((r)[0]), "=r"((r)[1]), "=r"((r)[2]), "=r"((r)[3]) : "r"(addr))

#define LDSM4T(r, addr) \
    asm volatile("ldmatrix.sync.aligned.m8n8.x4.trans.shared.b16 {%0,%1,%2,%3}, [%4];" \
        : "=r"((r)[0]), "=r"((r)[1]), "=r"((r)[2]), "=r"((r)[3]) : "r"(addr))

#define MMAF16(d, a, b0, b1) \
    asm volatile("mma.sync.aligned.m16n8k16.row.col.f32.f16.f16.f32 " \
        "{%0,%1,%2,%3}, {%4,%5,%6,%7}, {%8,%9}, {%0,%1,%2,%3};" \
        : "+f"((d)[0]), "+f"((d)[1]), "+f"((d)[2]), "+f"((d)[3]) \
        : "r"((a)[0]), "r"((a)[1]), "r"((a)[2]), "r"((a)[3]), "r"(b0), "r"(b1))

__device__ __forceinline__ void split2h(float x, float y, uint32_t& h, uint32_t& l) {
    __half2 hh = __floats2half2_rn(x, y);
    __half2 ll = __floats2half2_rn(x - __half2float(__low2half(hh)),
                                   y - __half2float(__high2half(hh)));
    h = *(uint32_t*)&hh;
    l = *(uint32_t*)&ll;
}
__device__ __forceinline__ uint32_t pack2h(float x, float y) {
    __half2 hh = __floats2half2_rn(x, y);
    return *(uint32_t*)&hh;
}

// ------------------------------ split kernels -------------------------------
__global__ void __launch_bounds__(256) split_kernel(
    const float* __restrict__ x, __half* __restrict__ hi,
    __half* __restrict__ lo, int n)
{
    int i = (blockIdx.x * 256 + threadIdx.x) * 4;
    if (i >= n) return;
    float4 v = *(const float4*)(x + i);
    uint32_t h0, l0, h1, l1;
    split2h(v.x, v.y, h0, l0);
    split2h(v.z, v.w, h1, l1);
    *(uint2*)((char*)hi + (size_t)i * 2) = make_uint2(h0, h1);
    *(uint2*)((char*)lo + (size_t)i * 2) = make_uint2(l0, l1);
}

__global__ void __launch_bounds__(256) cvt4_kernel(
    const float* __restrict__ w0, const float* __restrict__ w1,
    const float* __restrict__ w2, const float* __restrict__ w3,
    __half* __restrict__ wf, int n)
{
    const float* src = (blockIdx.y == 0) ? w0 : (blockIdx.y == 1) ? w1
                     : (blockIdx.y == 2) ? w2 : w3;
    size_t base = (size_t)blockIdx.y * n;
    int i = (blockIdx.x * 256 + threadIdx.x) * 4;
    if (i >= n) return;
    float4 v = *(const float4*)(src + i);
    *(uint2*)((char*)(wf + base) + (size_t)i * 2) =
        make_uint2(pack2h(v.x, v.y), pack2h(v.z, v.w));
}

// ------------------------------ fp16 GEMM body (3-stage cp.async) ----------
#define GS_AH 0
#define GS_AL 8192
#define GS_W  16384
#define GSTG  24576
#define GEMM_SMEM (3 * GSTG)   // 73728

__device__ __forceinline__ void gemm_body(
    char* sm,
    const __half* __restrict__ Ah, const __half* __restrict__ Al,
    const __half* __restrict__ W,
    const float* __restrict__ bias, int omode, float* __restrict__ Cf,
    __half* __restrict__ Fhi, __half* __restrict__ Flo,
    int bm, int bn)
{
    const uint32_t sb = smem_u32(sm);
    const int tid = threadIdx.x;
    const int wid = tid >> 5, lane = tid & 31;
    const int wm = wid >> 2, wn = wid & 3;

    const int lrow = (lane & 7) + ((lane >> 3) & 1) * 8;
    const int lcb  = lane >> 4;

    float acc[4][4][4];
#pragma unroll
    for (int mt = 0; mt < 4; mt++)
#pragma unroll
        for (int nt = 0; nt < 4; nt++)
#pragma unroll
            for (int e = 0; e < 4; e++) acc[mt][nt][e] = 0.f;

    auto issue = [&](int t) {
        uint32_t st = sb + (uint32_t)(t % 3) * GSTG;
#pragma unroll
        for (int i = 0; i < 2; i++) {
            int f = tid + i * 256;
            int r = f >> 2, cb = f & 3;
            size_t gA = (size_t)(bm + r) * D_ + t * 32 + cb * 8;
            size_t gW = (size_t)(bn + r) * D_ + t * 32 + cb * 8;
            uint32_t so = r * 64 + ((cb ^ ((r >> 1) & 3)) << 4);
            cp16(st + GS_AH + so, Ah + gA);
            cp16(st + GS_AL + so, Al + gA);
            cp16(st + GS_W  + so, W  + gW);
        }
    };

    issue(0); CP_COMMIT();
    issue(1); CP_COMMIT();

    for (int t = 0; t < 32; t++) {
        CP_WAIT1();
        __syncthreads();
        const uint32_t st = sb + (uint32_t)(t % 3) * GSTG;
#pragma unroll
        for (int ks = 0; ks < 2; ks++) {
            uint32_t ah[4][4], al[4][4], w2[2][4];
            const int cb = ks * 2 + lcb;
#pragma unroll
            for (int mt = 0; mt < 4; mt++) {
                int r = wm * 64 + mt * 16 + lrow;
                uint32_t ad = st + r * 64 + ((cb ^ ((r >> 1) & 3)) << 4);
                LDSM4(ah[mt], ad + GS_AH);
                LDSM4(al[mt], ad + GS_AL);
            }
#pragma unroll
            for (int p = 0; p < 2; p++) {
                int r = wn * 32 + p * 16 + lrow;
                uint32_t ad = st + r * 64 + ((cb ^ ((r >> 1) & 3)) << 4);
                LDSM4(w2[p], ad + GS_W);
            }
#pragma unroll
            for (int mt = 0; mt < 4; mt++)
#pragma unroll
                for (int nt = 0; nt < 4; nt++)
                    MMAF16(acc[mt][nt], ah[mt], w2[nt >> 1][nt & 1], w2[nt >> 1][(nt & 1) + 2]);
#pragma unroll
            for (int mt = 0; mt < 4; mt++)
#pragma unroll
                for (int nt = 0; nt < 4; nt++)
                    MMAF16(acc[mt][nt], al[mt], w2[nt >> 1][nt & 1], w2[nt >> 1][(nt & 1) + 2]);
        }
        if (t + 2 < 32) issue(t + 2);
        CP_COMMIT();
    }

    const int g = lane >> 2, tig = lane & 3;
#pragma unroll
    for (int mt = 0; mt < 4; mt++) {
#pragma unroll
        for (int nt = 0; nt < 4; nt++) {
            int row = bm + wm * 64 + mt * 16 + g;
            int col = bn + wn * 32 + nt * 8 + tig * 2;
            float2 bv = *(const float2*)&bias[col];
            float v00 = acc[mt][nt][0] + bv.x, v01 = acc[mt][nt][1] + bv.y;
            float v10 = acc[mt][nt][2] + bv.x, v11 = acc[mt][nt][3] + bv.y;
            if (omode == 0) {
                *(float2*)(Cf + (size_t)row * D_ + col) = make_float2(v00, v01);
                *(float2*)(Cf + (size_t)(row + 8) * D_ + col) = make_float2(v10, v11);
            } else if (omode == 2) {
                uint32_t hh, ll;
                split2h(v00, v01, hh, ll);
                *(uint32_t*)(Fhi + (size_t)row * D_ + col) = hh;
                *(uint32_t*)(Flo + (size_t)row * D_ + col) = ll;
                split2h(v10, v11, hh, ll);
                *(uint32_t*)(Fhi + (size_t)(row + 8) * D_ + col) = hh;
                *(uint32_t*)(Flo + (size_t)(row + 8) * D_ + col) = ll;
            } else {
                *(uint32_t*)(Fhi + (size_t)row * D_ + col) = pack2h(v00, v01);
                *(uint32_t*)(Fhi + (size_t)(row + 8) * D_ + col) = pack2h(v10, v11);
            }
        }
    }
}

// Fused Q/K/V projection: all outputs single fp16 now.
__global__ void __launch_bounds__(256) gemm_qkv_kernel(
    const __half* __restrict__ ah, const __half* __restrict__ al,
    const __half* __restrict__ bh, const __half* __restrict__ bl,
    const __half* __restrict__ wf,
    const float* __restrict__ bq, const float* __restrict__ bk,
    const float* __restrict__ bv,
    __half* __restrict__ qf, __half* __restrict__ kf, __half* __restrict__ vf)
{
    extern __shared__ char sm[];
    const int z = blockIdx.z;
    const __half* Ah = (z == 0) ? ah : bh;
    const __half* Al = (z == 0) ? al : bl;
    const __half* W  = wf + (size_t)z * D_ * D_;
    const float* bias = (z == 0) ? bq : (z == 1) ? bk : bv;
    __half* Fhi = (z == 0) ? qf : (z == 1) ? kf : vf;
    gemm_body(sm, Ah, Al, W, bias, 3, nullptr, Fhi, nullptr,
              blockIdx.y * 128, blockIdx.x * 128);
}

__global__ void __launch_bounds__(256) gemm_out_kernel(
    const __half* __restrict__ Ah, const __half* __restrict__ Al,
    const __half* __restrict__ W,
    const float* __restrict__ bias, float* __restrict__ Cf)
{
    extern __shared__ char sm[];
    gemm_body(sm, Ah, Al, W, bias, 0, Cf, nullptr, nullptr,
              blockIdx.y * 128, blockIdx.x * 128);
}

// ------------------------------ fp16 flash attention (1-pass) --------------
// Q single fp16, K/V single fp16, P single fp16: 1 MMA per product.
// Smem: Q 16KB + 2 stages x (K 8KB + V 8KB) = 48KB.
#define FQ  0
#define FSB 16384
#define FK  0
#define FV  8192
#define FSTG 16384
#define FLASH_SMEM (FSB + 2 * FSTG)   // 49152

__global__ void __launch_bounds__(256) flash_mma_kernel(
    const __half* __restrict__ Qf_,
    const __half* __restrict__ Kf_, const __half* __restrict__ Vf_,
    const int* __restrict__ mask,
    __half* __restrict__ Ohi, __half* __restrict__ Olo)
{
    extern __shared__ char sm[];
    const uint32_t sb = smem_u32(sm);
    const int tid = threadIdx.x, wid = tid >> 5, lane = tid & 31;
    const int h = blockIdx.x, qt = blockIdx.y, b = blockIdx.z;
    const int qbase = qt * 128;
    const int g = lane >> 2, t4 = lane & 3;

    auto issue_kv = [&](int t) {
        uint32_t st = sb + FSB + (uint32_t)(t & 1) * FSTG;
#pragma unroll
        for (int i = 0; i < 2; i++) {
            int f = tid + i * 256;
            int r = f >> 3, c = f & 7;
            size_t go = ((size_t)(b * S_ + t * 64 + r)) * D_ + h * DH_ + c * 8;
            uint32_t so = r * 128 + ((c ^ (r & 7)) << 4);
            cp16(st + FK + so, Kf_ + go);
            cp16(st + FV + so, Vf_ + go);
        }
    };

    issue_kv(0); CP_COMMIT();

    // Q tile (128 x 64 fp16), swizzled 128B rows
#pragma unroll
    for (int i = 0; i < 4; i++) {
        int f = tid + i * 256;
        int r = f >> 3, c = f & 7;
        size_t go = ((size_t)(b * S_ + qbase + r)) * D_ + h * DH_ + c * 8;
        uint32_t so = r * 128 + ((c ^ (r & 7)) << 4);
        *(uint4*)(sm + FQ + so) = *(const uint4*)(Qf_ + go);
    }
    __syncthreads();

    uint32_t qf[4][4];
    {
        const int lrow = wid * 16 + ((lane >> 3) & 1) * 8 + (lane & 7);
        const int lcb  = lane >> 4;
#pragma unroll
        for (int ks = 0; ks < 4; ks++) {
            uint32_t ad = sb + FQ + lrow * 128 + (((2 * ks + lcb) ^ (lrow & 7)) << 4);
            LDSM4(qf[ks], ad);
        }
    }

    float o[8][4];
#pragma unroll
    for (int n = 0; n < 8; n++)
#pragma unroll
        for (int e = 0; e < 4; e++) o[n][e] = 0.f;
    float m0 = -1e30f, m1 = -1e30f, l0 = 0.f, l1 = 0.f;

    const int qr0 = qbase + wid * 16 + g;
    const size_t mrow0 = ((size_t)b * S_ + qr0) * S_;
    const size_t mrow1 = mrow0 + (size_t)8 * S_;

    for (int t = 0; t < S_ / 64; t++) {
        const int kvb = t * 64;
        if (t + 1 < S_ / 64) issue_kv(t + 1);
        CP_COMMIT();
        CP_WAIT1();
        __syncthreads();
        const uint32_t st = sb + FSB + (uint32_t)(t & 1) * FSTG;

        // ---- S = Q @ K^T : 1 pass
        float s[8][4];
#pragma unroll
        for (int n = 0; n < 8; n++)
#pragma unroll
            for (int e = 0; e < 4; e++) s[n][e] = 0.f;

        {
            const int krow = ((lane >> 4) << 3) + (lane & 7);
            const int kchb = (lane >> 3) & 1;
#pragma unroll
            for (int ks = 0; ks < 4; ks++) {
                const int kch = 2 * ks + kchb;
#pragma unroll
                for (int ng = 0; ng < 4; ng++) {
                    int r = ng * 16 + krow;
                    uint32_t ad = st + FK + r * 128 + ((kch ^ (r & 7)) << 4);
                    uint32_t k4[4];
                    LDSM4(k4, ad);
                    MMAF16(s[2 * ng],     qf[ks], k4[0], k4[1]);
                    MMAF16(s[2 * ng + 1], qf[ks], k4[2], k4[3]);
                }
            }
        }

        // ---- mask + scale + online softmax
        float mx0 = -1e30f, mx1 = -1e30f;
#pragma unroll
        for (int n = 0; n < 8; n++) {
            const int col = kvb + n * 8 + t4 * 2;
            int2 ma = *(const int2*)(mask + mrow0 + col);
            int2 mb = *(const int2*)(mask + mrow1 + col);
            s[n][0] = ma.x ? s[n][0] * 0.125f : -1e9f;
            s[n][1] = ma.y ? s[n][1] * 0.125f : -1e9f;
            s[n][2] = mb.x ? s[n][2] * 0.125f : -1e9f;
            s[n][3] = mb.y ? s[n][3] * 0.125f : -1e9f;
            mx0 = fmaxf(mx0, fmaxf(s[n][0], s[n][1]));
            mx1 = fmaxf(mx1, fmaxf(s[n][2], s[n][3]));
        }
        mx0 = fmaxf(mx0, __shfl_xor_sync(0xffffffffu, mx0, 1));
        mx0 = fmaxf(mx0, __shfl_xor_sync(0xffffffffu, mx0, 2));
        mx1 = fmaxf(mx1, __shfl_xor_sync(0xffffffffu, mx1, 1));
        mx1 = fmaxf(mx1, __shfl_xor_sync(0xffffffffu, mx1, 2));

        float mn0 = fmaxf(m0, mx0), mn1 = fmaxf(m1, mx1);
        float al0 = __expf(m0 - mn0), al1 = __expf(m1 - mn1);
        m0 = mn0; m1 = mn1;

        float rs0 = 0.f, rs1 = 0.f;
#pragma unroll
        for (int n = 0; n < 8; n++) {
            s[n][0] = __expf(s[n][0] - mn0);
            s[n][1] = __expf(s[n][1] - mn0);
            s[n][2] = __expf(s[n][2] - mn1);
            s[n][3] = __expf(s[n][3] - mn1);
            rs0 += s[n][0] + s[n][1];
            rs1 += s[n][2] + s[n][3];
        }
        rs0 += __shfl_xor_sync(0xffffffffu, rs0, 1);
        rs0 += __shfl_xor_sync(0xffffffffu, rs0, 2);
        rs1 += __shfl_xor_sync(0xffffffffu, rs1, 1);
        rs1 += __shfl_xor_sync(0xffffffffu, rs1, 2);
        l0 = l0 * al0 + rs0;
        l1 = l1 * al1 + rs1;
#pragma unroll
        for (int n = 0; n < 8; n++) {
            o[n][0] *= al0; o[n][1] *= al0;
            o[n][2] *= al1; o[n][3] *= al1;
        }

        // ---- O += P @ V : 1 pass (P single fp16)
        {
            const int vrow_b = ((lane >> 3) & 1) * 8 + (lane & 7);
            const int vchb   = lane >> 4;
#pragma unroll
            for (int ks = 0; ks < 4; ks++) {
                uint32_t p4[4];
                p4[0] = pack2h(s[2 * ks][0],     s[2 * ks][1]);
                p4[1] = pack2h(s[2 * ks][2],     s[2 * ks][3]);
                p4[2] = pack2h(s[2 * ks + 1][0], s[2 * ks + 1][1]);
                p4[3] = pack2h(s[2 * ks + 1][2], s[2 * ks + 1][3]);
                const int vrow = ks * 16 + vrow_b;
#pragma unroll
                for (int ng = 0; ng < 4; ng++) {
                    uint32_t ad = st + FV + vrow * 128 + (((2 * ng + vchb) ^ (vrow & 7)) << 4);
                    uint32_t v4[4];
                    LDSM4T(v4, ad);
                    MMAF16(o[2 * ng],     p4, v4[0], v4[1]);
                    MMAF16(o[2 * ng + 1], p4, v4[2], v4[3]);
                }
            }
        }
        __syncthreads();
    }

    // ---- finalize: split fp16 ctx (keeps out-GEMM 2-pass accurate)
    const float inv0 = 1.f / l0, inv1 = 1.f / l1;
#pragma unroll
    for (int n = 0; n < 8; n++) {
        const int col = h * DH_ + n * 8 + t4 * 2;
        size_t o0 = ((size_t)(b * S_ + qr0)) * D_ + col;
        size_t o1 = o0 + (size_t)8 * D_;
        uint32_t hh, ll;
        split2h(o[n][0] * inv0, o[n][1] * inv0, hh, ll);
        *(uint32_t*)(Ohi + o0) = hh;
        *(uint32_t*)(Olo + o0) = ll;
        split2h(o[n][2] * inv1, o[n][3] * inv1, hh, ll);
        *(uint32_t*)(Ohi + o1) = hh;
        *(uint32_t*)(Olo + o1) = ll;
    }
}

// ---------------------------------------------------------------------------
extern "C" void kernel_launch(void* const* d_in, const int* in_sizes, int n_in,
                              void* d_out, int out_size)
{
    (void)in_sizes; (void)n_in; (void)out_size;
    const float* q_tok  = (const float*)d_in[0];
    const float* kv_tok = (const float*)d_in[1];
    const int*   mask   = (const int*)d_in[2];
    const float* Wq = (const float*)d_in[3];
    const float* bq = (const float*)d_in[4];
    const float* Wk = (const float*)d_in[5];
    const float* bk = (const float*)d_in[6];
    const float* Wv = (const float*)d_in[7];
    const float* bv = (const float*)d_in[8];
    const float* Wo = (const float*)d_in[9];
    const float* bo = (const float*)d_in[10];
    float* out = (float*)d_out;

    __half *ah, *al, *bh, *bl, *wf, *qf, *kf, *vf, *ch, *cl;
    cudaGetSymbolAddress((void**)&ah, g_ah);
    cudaGetSymbolAddress((void**)&al, g_al);
    cudaGetSymbolAddress((void**)&bh, g_bh);
    cudaGetSymbolAddress((void**)&bl, g_bl);
    cudaGetSymbolAddress((void**)&wf, g_wf);
    cudaGetSymbolAddress((void**)&qf, g_qf);
    cudaGetSymbolAddress((void**)&kf, g_kf);
    cudaGetSymbolAddress((void**)&vf, g_vf);
    cudaGetSymbolAddress((void**)&ch, g_ch);
    cudaGetSymbolAddress((void**)&cl, g_cl);

    cudaFuncSetAttribute(gemm_qkv_kernel,
                         cudaFuncAttributeMaxDynamicSharedMemorySize, GEMM_SMEM);
    cudaFuncSetAttribute(gemm_out_kernel,
                         cudaFuncAttributeMaxDynamicSharedMemorySize, GEMM_SMEM);
    cudaFuncSetAttribute(flash_mma_kernel,
                         cudaFuncAttributeMaxDynamicSharedMemorySize, FLASH_SMEM);

    const int nTok = M_ * D_;
    const int nW = D_ * D_;

    split_kernel<<<nTok / 1024, 256>>>(q_tok,  ah, al, nTok);
    split_kernel<<<nTok / 1024, 256>>>(kv_tok, bh, bl, nTok);
    dim3 wgrid(nW / 1024, 4);
    cvt4_kernel<<<wgrid, 256>>>(Wq, Wk, Wv, Wo, wf, nW);

    dim3 qkvgrid(D_ / 128, M_ / 128, 3);   // (8, 32, 3)
    gemm_qkv_kernel<<<qkvgrid, 256, GEMM_SMEM>>>(
        ah, al, bh, bl, wf, bq, bk, bv, qf, kf, vf);

    dim3 fgrid(H_, S_ / 128, B_);          // (16, 16, 2)
    flash_mma_kernel<<<fgrid, 256, FLASH_SMEM>>>(qf, kf, vf, mask, ch, cl);

    dim3 ogrid(D_ / 128, M_ / 128);
    gemm_out_kernel<<<ogrid, 256, GEMM_SMEM>>>(
        ch, cl, wf + 3 * (size_t)nW, bo, out);
}

// round 11
// speedup vs baseline: 5.7387x; 1.2831x over previous
#include <cuda_runtime.h>
#include <cuda_fp16.h>
#include <cstdint>

#define B_  2
#define S_  2048
#define D_  1024
#define H_  16
#define DH_ 64
#define M_  (B_*S_)   // 4096

// ------------------------------ scratch (allocation-free rule) -------------
__device__ __half g_af[(size_t)M_ * D_];   // q tokens fp16
__device__ __half g_bf[(size_t)M_ * D_];   // kv tokens fp16
__device__ __half g_wf[(size_t)4 * D_ * D_];  // Wq,Wk,Wv,Wo fp16
__device__ __half g_qf[(size_t)M_ * D_];   // Q proj fp16
__device__ __half g_kf[(size_t)M_ * D_];   // K proj fp16
__device__ __half g_vf[(size_t)M_ * D_];   // V proj fp16
__device__ __half g_cf[(size_t)M_ * D_];   // ctx fp16

// ------------------------------ helpers ------------------------------------
__device__ __forceinline__ uint32_t smem_u32(const void* p) {
    uint32_t a;
    asm("{ .reg .u64 t; cvta.to.shared.u64 t, %1; cvt.u32.u64 %0, t; }"
        : "=r"(a) : "l"(p));
    return a;
}
__device__ __forceinline__ void cp16(uint32_t s, const void* g) {
    asm volatile("cp.async.cg.shared.global [%0], [%1], 16;" :: "r"(s), "l"(g));
}
#define CP_COMMIT() asm volatile("cp.async.commit_group;" ::: "memory")
#define CP_WAIT1()  asm volatile("cp.async.wait_group 1;" ::: "memory")

#define LDSM4(r, addr) \
    asm volatile("ldmatrix.sync.aligned.m8n8.x4.shared.b16 {%0,%1,%2,%3}, [%4];" \
        : "=r"((r)[0]), "=r"((r)[1]), "=r"((r)[2]), "=r"((r)[3]) : "r"(addr))

#define LDSM4T(r, addr) \
    asm volatile("ldmatrix.sync.aligned.m8n8.x4.trans.shared.b16 {%0,%1,%2,%3}, [%4];" \
        : "=r"((r)[0]), "=r"((r)[1]), "=r"((r)[2]), "=r"((r)[3]) : "r"(addr))

#define MMAF16(d, a, b0, b1) \
    asm volatile("mma.sync.aligned.m16n8k16.row.col.f32.f16.f16.f32 " \
        "{%0,%1,%2,%3}, {%4,%5,%6,%7}, {%8,%9}, {%0,%1,%2,%3};" \
        : "+f"((d)[0]), "+f"((d)[1]), "+f"((d)[2]), "+f"((d)[3]) \
        : "r"((a)[0]), "r"((a)[1]), "r"((a)[2]), "r"((a)[3]), "r"(b0), "r"(b1))

__device__ __forceinline__ uint32_t pack2h(float x, float y) {
    __half2 hh = __floats2half2_rn(x, y);
    return *(uint32_t*)&hh;
}

// ------------------------------ convert kernels -----------------------------
__global__ void __launch_bounds__(256) cvt_kernel(
    const float* __restrict__ x, __half* __restrict__ f, int n)
{
    int i = (blockIdx.x * 256 + threadIdx.x) * 4;
    if (i >= n) return;
    float4 v = *(const float4*)(x + i);
    *(uint2*)((char*)f + (size_t)i * 2) =
        make_uint2(pack2h(v.x, v.y), pack2h(v.z, v.w));
}

__global__ void __launch_bounds__(256) cvt4_kernel(
    const float* __restrict__ w0, const float* __restrict__ w1,
    const float* __restrict__ w2, const float* __restrict__ w3,
    __half* __restrict__ wf, int n)
{
    const float* src = (blockIdx.y == 0) ? w0 : (blockIdx.y == 1) ? w1
                     : (blockIdx.y == 2) ? w2 : w3;
    size_t base = (size_t)blockIdx.y * n;
    int i = (blockIdx.x * 256 + threadIdx.x) * 4;
    if (i >= n) return;
    float4 v = *(const float4*)(src + i);
    *(uint2*)((char*)(wf + base) + (size_t)i * 2) =
        make_uint2(pack2h(v.x, v.y), pack2h(v.z, v.w));
}

// ------------------------------ fp16 GEMM body (3-stage cp.async, 1-pass) --
#define GS_A  0
#define GS_W  8192
#define GSTG  16384
#define GEMM_SMEM (3 * GSTG)   // 49152

__device__ __forceinline__ void gemm_body(
    char* sm,
    const __half* __restrict__ A, const __half* __restrict__ W,
    const float* __restrict__ bias, int omode, float* __restrict__ Cf,
    __half* __restrict__ Fh, int bm, int bn)
{
    const uint32_t sb = smem_u32(sm);
    const int tid = threadIdx.x;
    const int wid = tid >> 5, lane = tid & 31;
    const int wm = wid >> 2, wn = wid & 3;

    const int lrow = (lane & 7) + ((lane >> 3) & 1) * 8;
    const int lcb  = lane >> 4;

    float acc[4][4][4];
#pragma unroll
    for (int mt = 0; mt < 4; mt++)
#pragma unroll
        for (int nt = 0; nt < 4; nt++)
#pragma unroll
            for (int e = 0; e < 4; e++) acc[mt][nt][e] = 0.f;

    auto issue = [&](int t) {
        uint32_t st = sb + (uint32_t)(t % 3) * GSTG;
#pragma unroll
        for (int i = 0; i < 2; i++) {
            int f = tid + i * 256;
            int r = f >> 2, cb = f & 3;
            size_t gA = (size_t)(bm + r) * D_ + t * 32 + cb * 8;
            size_t gW = (size_t)(bn + r) * D_ + t * 32 + cb * 8;
            uint32_t so = r * 64 + ((cb ^ ((r >> 1) & 3)) << 4);
            cp16(st + GS_A + so, A + gA);
            cp16(st + GS_W + so, W + gW);
        }
    };

    issue(0); CP_COMMIT();
    issue(1); CP_COMMIT();

    for (int t = 0; t < 32; t++) {
        CP_WAIT1();
        __syncthreads();
        const uint32_t st = sb + (uint32_t)(t % 3) * GSTG;
#pragma unroll
        for (int ks = 0; ks < 2; ks++) {
            uint32_t a4[4][4], w2[2][4];
            const int cb = ks * 2 + lcb;
#pragma unroll
            for (int mt = 0; mt < 4; mt++) {
                int r = wm * 64 + mt * 16 + lrow;
                uint32_t ad = st + r * 64 + ((cb ^ ((r >> 1) & 3)) << 4);
                LDSM4(a4[mt], ad + GS_A);
            }
#pragma unroll
            for (int p = 0; p < 2; p++) {
                int r = wn * 32 + p * 16 + lrow;
                uint32_t ad = st + r * 64 + ((cb ^ ((r >> 1) & 3)) << 4);
                LDSM4(w2[p], ad + GS_W);
            }
#pragma unroll
            for (int mt = 0; mt < 4; mt++)
#pragma unroll
                for (int nt = 0; nt < 4; nt++)
                    MMAF16(acc[mt][nt], a4[mt], w2[nt >> 1][nt & 1], w2[nt >> 1][(nt & 1) + 2]);
        }
        if (t + 2 < 32) issue(t + 2);
        CP_COMMIT();
    }

    const int g = lane >> 2, tig = lane & 3;
#pragma unroll
    for (int mt = 0; mt < 4; mt++) {
#pragma unroll
        for (int nt = 0; nt < 4; nt++) {
            int row = bm + wm * 64 + mt * 16 + g;
            int col = bn + wn * 32 + nt * 8 + tig * 2;
            float2 bv = *(const float2*)&bias[col];
            float v00 = acc[mt][nt][0] + bv.x, v01 = acc[mt][nt][1] + bv.y;
            float v10 = acc[mt][nt][2] + bv.x, v11 = acc[mt][nt][3] + bv.y;
            if (omode == 0) {
                *(float2*)(Cf + (size_t)row * D_ + col) = make_float2(v00, v01);
                *(float2*)(Cf + (size_t)(row + 8) * D_ + col) = make_float2(v10, v11);
            } else {
                *(uint32_t*)(Fh + (size_t)row * D_ + col) = pack2h(v00, v01);
                *(uint32_t*)(Fh + (size_t)(row + 8) * D_ + col) = pack2h(v10, v11);
            }
        }
    }
}

// Fused Q/K/V projection
__global__ void __launch_bounds__(256) gemm_qkv_kernel(
    const __half* __restrict__ af, const __half* __restrict__ bf,
    const __half* __restrict__ wf,
    const float* __restrict__ bq, const float* __restrict__ bk,
    const float* __restrict__ bv,
    __half* __restrict__ qf, __half* __restrict__ kf, __half* __restrict__ vf)
{
    extern __shared__ char sm[];
    const int z = blockIdx.z;
    const __half* A = (z == 0) ? af : bf;
    const __half* W = wf + (size_t)z * D_ * D_;
    const float* bias = (z == 0) ? bq : (z == 1) ? bk : bv;
    __half* Fh = (z == 0) ? qf : (z == 1) ? kf : vf;
    gemm_body(sm, A, W, bias, 3, nullptr, Fh,
              blockIdx.y * 128, blockIdx.x * 128);
}

__global__ void __launch_bounds__(256) gemm_out_kernel(
    const __half* __restrict__ A, const __half* __restrict__ W,
    const float* __restrict__ bias, float* __restrict__ Cf)
{
    extern __shared__ char sm[];
    gemm_body(sm, A, W, bias, 0, Cf, nullptr,
              blockIdx.y * 128, blockIdx.x * 128);
}

// ------------------------------ fp16 flash attention (1-pass) --------------
#define FQ  0
#define FSB 16384
#define FK  0
#define FV  8192
#define FSTG 16384
#define FLASH_SMEM (FSB + 2 * FSTG)   // 49152

__global__ void __launch_bounds__(256) flash_mma_kernel(
    const __half* __restrict__ Qf_,
    const __half* __restrict__ Kf_, const __half* __restrict__ Vf_,
    const int* __restrict__ mask, __half* __restrict__ Of)
{
    extern __shared__ char sm[];
    const uint32_t sb = smem_u32(sm);
    const int tid = threadIdx.x, wid = tid >> 5, lane = tid & 31;
    const int h = blockIdx.x, qt = blockIdx.y, b = blockIdx.z;
    const int qbase = qt * 128;
    const int g = lane >> 2, t4 = lane & 3;

    auto issue_kv = [&](int t) {
        uint32_t st = sb + FSB + (uint32_t)(t & 1) * FSTG;
#pragma unroll
        for (int i = 0; i < 2; i++) {
            int f = tid + i * 256;
            int r = f >> 3, c = f & 7;
            size_t go = ((size_t)(b * S_ + t * 64 + r)) * D_ + h * DH_ + c * 8;
            uint32_t so = r * 128 + ((c ^ (r & 7)) << 4);
            cp16(st + FK + so, Kf_ + go);
            cp16(st + FV + so, Vf_ + go);
        }
    };

    issue_kv(0); CP_COMMIT();

#pragma unroll
    for (int i = 0; i < 4; i++) {
        int f = tid + i * 256;
        int r = f >> 3, c = f & 7;
        size_t go = ((size_t)(b * S_ + qbase + r)) * D_ + h * DH_ + c * 8;
        uint32_t so = r * 128 + ((c ^ (r & 7)) << 4);
        *(uint4*)(sm + FQ + so) = *(const uint4*)(Qf_ + go);
    }
    __syncthreads();

    uint32_t qf[4][4];
    {
        const int lrow = wid * 16 + ((lane >> 3) & 1) * 8 + (lane & 7);
        const int lcb  = lane >> 4;
#pragma unroll
        for (int ks = 0; ks < 4; ks++) {
            uint32_t ad = sb + FQ + lrow * 128 + (((2 * ks + lcb) ^ (lrow & 7)) << 4);
            LDSM4(qf[ks], ad);
        }
    }

    float o[8][4];
#pragma unroll
    for (int n = 0; n < 8; n++)
#pragma unroll
        for (int e = 0; e < 4; e++) o[n][e] = 0.f;
    float m0 = -1e30f, m1 = -1e30f, l0 = 0.f, l1 = 0.f;

    const int qr0 = qbase + wid * 16 + g;
    const size_t mrow0 = ((size_t)b * S_ + qr0) * S_;
    const size_t mrow1 = mrow0 + (size_t)8 * S_;

    for (int t = 0; t < S_ / 64; t++) {
        const int kvb = t * 64;
        if (t + 1 < S_ / 64) issue_kv(t + 1);
        CP_COMMIT();
        CP_WAIT1();
        __syncthreads();
        const uint32_t st = sb + FSB + (uint32_t)(t & 1) * FSTG;

        float s[8][4];
#pragma unroll
        for (int n = 0; n < 8; n++)
#pragma unroll
            for (int e = 0; e < 4; e++) s[n][e] = 0.f;

        {
            const int krow = ((lane >> 4) << 3) + (lane & 7);
            const int kchb = (lane >> 3) & 1;
#pragma unroll
            for (int ks = 0; ks < 4; ks++) {
                const int kch = 2 * ks + kchb;
#pragma unroll
                for (int ng = 0; ng < 4; ng++) {
                    int r = ng * 16 + krow;
                    uint32_t ad = st + FK + r * 128 + ((kch ^ (r & 7)) << 4);
                    uint32_t k4[4];
                    LDSM4(k4, ad);
                    MMAF16(s[2 * ng],     qf[ks], k4[0], k4[1]);
                    MMAF16(s[2 * ng + 1], qf[ks], k4[2], k4[3]);
                }
            }
        }

        float mx0 = -1e30f, mx1 = -1e30f;
#pragma unroll
        for (int n = 0; n < 8; n++) {
            const int col = kvb + n * 8 + t4 * 2;
            int2 ma = *(const int2*)(mask + mrow0 + col);
            int2 mb = *(const int2*)(mask + mrow1 + col);
            s[n][0] = ma.x ? s[n][0] * 0.125f : -1e9f;
            s[n][1] = ma.y ? s[n][1] * 0.125f : -1e9f;
            s[n][2] = mb.x ? s[n][2] * 0.125f : -1e9f;
            s[n][3] = mb.y ? s[n][3] * 0.125f : -1e9f;
            mx0 = fmaxf(mx0, fmaxf(s[n][0], s[n][1]));
            mx1 = fmaxf(mx1, fmaxf(s[n][2], s[n][3]));
        }
        mx0 = fmaxf(mx0, __shfl_xor_sync(0xffffffffu, mx0, 1));
        mx0 = fmaxf(mx0, __shfl_xor_sync(0xffffffffu, mx0, 2));
        mx1 = fmaxf(mx1, __shfl_xor_sync(0xffffffffu, mx1, 1));
        mx1 = fmaxf(mx1, __shfl_xor_sync(0xffffffffu, mx1, 2));

        float mn0 = fmaxf(m0, mx0), mn1 = fmaxf(m1, mx1);
        float al0 = __expf(m0 - mn0), al1 = __expf(m1 - mn1);
        m0 = mn0; m1 = mn1;

        float rs0 = 0.f, rs1 = 0.f;
#pragma unroll
        for (int n = 0; n < 8; n++) {
            s[n][0] = __expf(s[n][0] - mn0);
            s[n][1] = __expf(s[n][1] - mn0);
            s[n][2] = __expf(s[n][2] - mn1);
            s[n][3] = __expf(s[n][3] - mn1);
            rs0 += s[n][0] + s[n][1];
            rs1 += s[n][2] + s[n][3];
        }
        rs0 += __shfl_xor_sync(0xffffffffu, rs0, 1);
        rs0 += __shfl_xor_sync(0xffffffffu, rs0, 2);
        rs1 += __shfl_xor_sync(0xffffffffu, rs1, 1);
        rs1 += __shfl_xor_sync(0xffffffffu, rs1, 2);
        l0 = l0 * al0 + rs0;
        l1 = l1 * al1 + rs1;
#pragma unroll
        for (int n = 0; n < 8; n++) {
            o[n][0] *= al0; o[n][1] *= al0;
            o[n][2] *= al1; o[n][3] *= al1;
        }

        {
            const int vrow_b = ((lane >> 3) & 1) * 8 + (lane & 7);
            const int vchb   = lane >> 4;
#pragma unroll
            for (int ks = 0; ks < 4; ks++) {
                uint32_t p4[4];
                p4[0] = pack2h(s[2 * ks][0],     s[2 * ks][1]);
                p4[1] = pack2h(s[2 * ks][2],     s[2 * ks][3]);
                p4[2] = pack2h(s[2 * ks + 1][0], s[2 * ks + 1][1]);
                p4[3] = pack2h(s[2 * ks + 1][2], s[2 * ks + 1][3]);
                const int vrow = ks * 16 + vrow_b;
#pragma unroll
                for (int ng = 0; ng < 4; ng++) {
                    uint32_t ad = st + FV + vrow * 128 + (((2 * ng + vchb) ^ (vrow & 7)) << 4);
                    uint32_t v4[4];
                    LDSM4T(v4, ad);
                    MMAF16(o[2 * ng],     p4, v4[0], v4[1]);
                    MMAF16(o[2 * ng + 1], p4, v4[2], v4[3]);
                }
            }
        }
        __syncthreads();
    }

    const float inv0 = 1.f / l0, inv1 = 1.f / l1;
#pragma unroll
    for (int n = 0; n < 8; n++) {
        const int col = h * DH_ + n * 8 + t4 * 2;
        size_t o0 = ((size_t)(b * S_ + qr0)) * D_ + col;
        size_t o1 = o0 + (size_t)8 * D_;
        *(uint32_t*)(Of + o0) = pack2h(o[n][0] * inv0, o[n][1] * inv0);
        *(uint32_t*)(Of + o1) = pack2h(o[n][2] * inv1, o[n][3] * inv1);
    }
}

// ---------------------------------------------------------------------------
extern "C" void kernel_launch(void* const* d_in, const int* in_sizes, int n_in,
                              void* d_out, int out_size)
{
    (void)in_sizes; (void)n_in; (void)out_size;
    const float* q_tok  = (const float*)d_in[0];
    const float* kv_tok = (const float*)d_in[1];
    const int*   mask   = (const int*)d_in[2];
    const float* Wq = (const float*)d_in[3];
    const float* bq = (const float*)d_in[4];
    const float* Wk = (const float*)d_in[5];
    const float* bk = (const float*)d_in[6];
    const float* Wv = (const float*)d_in[7];
    const float* bv = (const float*)d_in[8];
    const float* Wo = (const float*)d_in[9];
    const float* bo = (const float*)d_in[10];
    float* out = (float*)d_out;

    __half *af, *bf, *wf, *qf, *kf, *vf, *cf;
    cudaGetSymbolAddress((void**)&af, g_af);
    cudaGetSymbolAddress((void**)&bf, g_bf);
    cudaGetSymbolAddress((void**)&wf, g_wf);
    cudaGetSymbolAddress((void**)&qf, g_qf);
    cudaGetSymbolAddress((void**)&kf, g_kf);
    cudaGetSymbolAddress((void**)&vf, g_vf);
    cudaGetSymbolAddress((void**)&cf, g_cf);

    cudaFuncSetAttribute(gemm_qkv_kernel,
                         cudaFuncAttributeMaxDynamicSharedMemorySize, GEMM_SMEM);
    cudaFuncSetAttribute(gemm_out_kernel,
                         cudaFuncAttributeMaxDynamicSharedMemorySize, GEMM_SMEM);
    cudaFuncSetAttribute(flash_mma_kernel,
                         cudaFuncAttributeMaxDynamicSharedMemorySize, FLASH_SMEM);

    const int nTok = M_ * D_;
    const int nW = D_ * D_;

    cvt_kernel<<<nTok / 1024, 256>>>(q_tok,  af, nTok);
    cvt_kernel<<<nTok / 1024, 256>>>(kv_tok, bf, nTok);
    dim3 wgrid(nW / 1024, 4);
    cvt4_kernel<<<wgrid, 256>>>(Wq, Wk, Wv, Wo, wf, nW);

    dim3 qkvgrid(D_ / 128, M_ / 128, 3);   // (8, 32, 3)
    gemm_qkv_kernel<<<qkvgrid, 256, GEMM_SMEM>>>(
        af, bf, wf, bq, bk, bv, qf, kf, vf);

    dim3 fgrid(H_, S_ / 128, B_);          // (16, 16, 2)
    flash_mma_kernel<<<fgrid, 256, FLASH_SMEM>>>(qf, kf, vf, mask, cf);

    dim3 ogrid(D_ / 128, M_ / 128);
    gemm_out_kernel<<<ogrid, 256, GEMM_SMEM>>>(
        cf, wf + 3 * (size_t)nW, bo, out);
}

// round 13
// speedup vs baseline: 6.3271x; 1.1025x over previous
#include <cuda_runtime.h>
#include <cuda_fp16.h>
#include <cstdint>

#define B_  2
#define S_  2048
#define D_  1024
#define H_  16
#define DH_ 64
#define M_  (B_*S_)   // 4096

// ------------------------------ scratch (allocation-free rule) -------------
__device__ __half g_af[(size_t)M_ * D_];   // q tokens fp16
__device__ __half g_bf[(size_t)M_ * D_];   // kv tokens fp16
__device__ __half g_wf[(size_t)4 * D_ * D_];  // Wq,Wk,Wv,Wo fp16
__device__ __half g_qf[(size_t)M_ * D_];   // Q proj fp16
__device__ __half g_kf[(size_t)M_ * D_];   // K proj fp16
__device__ __half g_vf[(size_t)M_ * D_];   // V proj fp16
__device__ __half g_cf[(size_t)M_ * D_];   // ctx fp16
__device__ uint2  g_mb[(size_t)M_ * 32];   // mask bits: 64 per (row, 64-col chunk)

// ------------------------------ helpers ------------------------------------
__device__ __forceinline__ uint32_t smem_u32(const void* p) {
    uint32_t a;
    asm("{ .reg .u64 t; cvta.to.shared.u64 t, %1; cvt.u32.u64 %0, t; }"
        : "=r"(a) : "l"(p));
    return a;
}
__device__ __forceinline__ void cp16(uint32_t s, const void* g) {
    asm volatile("cp.async.cg.shared.global [%0], [%1], 16;" :: "r"(s), "l"(g));
}
#define CP_COMMIT() asm volatile("cp.async.commit_group;" ::: "memory")
#define CP_WAIT1()  asm volatile("cp.async.wait_group 1;" ::: "memory")

#define LDSM4(r, addr) \
    asm volatile("ldmatrix.sync.aligned.m8n8.x4.shared.b16 {%0,%1,%2,%3}, [%4];" \
        : "=r"((r)[0]), "=r"((r)[1]), "=r"((r)[2]), "=r"((r)[3]) : "r"(addr))

#define LDSM4T(r, addr) \
    asm volatile("ldmatrix.sync.aligned.m8n8.x4.trans.shared.b16 {%0,%1,%2,%3}, [%4];" \
        : "=r"((r)[0]), "=r"((r)[1]), "=r"((r)[2]), "=r"((r)[3]) : "r"(addr))

#define MMAF16(d, a, b0, b1) \
    asm volatile("mma.sync.aligned.m16n8k16.row.col.f32.f16.f16.f32 " \
        "{%0,%1,%2,%3}, {%4,%5,%6,%7}, {%8,%9}, {%0,%1,%2,%3};" \
        : "+f"((d)[0]), "+f"((d)[1]), "+f"((d)[2]), "+f"((d)[3]) \
        : "r"((a)[0]), "r"((a)[1]), "r"((a)[2]), "r"((a)[3]), "r"(b0), "r"(b1))

__device__ __forceinline__ uint32_t pack2h(float x, float y) {
    __half2 hh = __floats2half2_rn(x, y);
    return *(uint32_t*)&hh;
}

// ------------------------------ convert / pack kernels ----------------------
__global__ void __launch_bounds__(256) cvt_kernel(
    const float* __restrict__ x, __half* __restrict__ f, int n)
{
    int i = (blockIdx.x * 256 + threadIdx.x) * 4;
    if (i >= n) return;
    float4 v = *(const float4*)(x + i);
    *(uint2*)((char*)f + (size_t)i * 2) =
        make_uint2(pack2h(v.x, v.y), pack2h(v.z, v.w));
}

__global__ void __launch_bounds__(256) cvt4_kernel(
    const float* __restrict__ w0, const float* __restrict__ w1,
    const float* __restrict__ w2, const float* __restrict__ w3,
    __half* __restrict__ wf, int n)
{
    const float* src = (blockIdx.y == 0) ? w0 : (blockIdx.y == 1) ? w1
                     : (blockIdx.y == 2) ? w2 : w3;
    size_t base = (size_t)blockIdx.y * n;
    int i = (blockIdx.x * 256 + threadIdx.x) * 4;
    if (i >= n) return;
    float4 v = *(const float4*)(src + i);
    *(uint2*)((char*)(wf + base) + (size_t)i * 2) =
        make_uint2(pack2h(v.x, v.y), pack2h(v.z, v.w));
}

// Pack mask (B*S rows x S int32) into 64-bit chunks.
__global__ void __launch_bounds__(256) pack_mask_kernel(
    const int* __restrict__ mask, uint2* __restrict__ bits)
{
    int warp = (blockIdx.x * 256 + threadIdx.x) >> 5;
    int lane = threadIdx.x & 31;
    if (warp >= M_) return;
    const int* mrow = mask + (size_t)warp * S_;
#pragma unroll 4
    for (int c = 0; c < 32; c++) {
        int m0 = mrow[c * 64 + lane];
        int m1 = mrow[c * 64 + 32 + lane];
        uint32_t b0 = __ballot_sync(0xffffffffu, m0 != 0);
        uint32_t b1 = __ballot_sync(0xffffffffu, m1 != 0);
        if (lane == 0) bits[(size_t)warp * 32 + c] = make_uint2(b0, b1);
    }
}

// ------------------------------ fp16 GEMM body (3-stage cp.async, 1-pass) --
#define GS_A  0
#define GS_W  8192
#define GSTG  16384
#define GEMM_SMEM (3 * GSTG)   // 49152

__device__ __forceinline__ void gemm_body(
    char* sm,
    const __half* __restrict__ A, const __half* __restrict__ W,
    const float* __restrict__ bias, int omode, float* __restrict__ Cf,
    __half* __restrict__ Fh, int bm, int bn)
{
    const uint32_t sb = smem_u32(sm);
    const int tid = threadIdx.x;
    const int wid = tid >> 5, lane = tid & 31;
    const int wm = wid >> 2, wn = wid & 3;

    const int lrow = (lane & 7) + ((lane >> 3) & 1) * 8;
    const int lcb  = lane >> 4;

    float acc[4][4][4];
#pragma unroll
    for (int mt = 0; mt < 4; mt++)
#pragma unroll
        for (int nt = 0; nt < 4; nt++)
#pragma unroll
            for (int e = 0; e < 4; e++) acc[mt][nt][e] = 0.f;

    auto issue = [&](int t) {
        uint32_t st = sb + (uint32_t)(t % 3) * GSTG;
#pragma unroll
        for (int i = 0; i < 2; i++) {
            int f = tid + i * 256;
            int r = f >> 2, cb = f & 3;
            size_t gA = (size_t)(bm + r) * D_ + t * 32 + cb * 8;
            size_t gW = (size_t)(bn + r) * D_ + t * 32 + cb * 8;
            uint32_t so = r * 64 + ((cb ^ ((r >> 1) & 3)) << 4);
            cp16(st + GS_A + so, A + gA);
            cp16(st + GS_W + so, W + gW);
        }
    };

    issue(0); CP_COMMIT();
    issue(1); CP_COMMIT();

    for (int t = 0; t < 32; t++) {
        CP_WAIT1();
        __syncthreads();
        const uint32_t st = sb + (uint32_t)(t % 3) * GSTG;
#pragma unroll
        for (int ks = 0; ks < 2; ks++) {
            uint32_t a4[4][4], w2[2][4];
            const int cb = ks * 2 + lcb;
#pragma unroll
            for (int mt = 0; mt < 4; mt++) {
                int r = wm * 64 + mt * 16 + lrow;
                uint32_t ad = st + r * 64 + ((cb ^ ((r >> 1) & 3)) << 4);
                LDSM4(a4[mt], ad + GS_A);
            }
#pragma unroll
            for (int p = 0; p < 2; p++) {
                int r = wn * 32 + p * 16 + lrow;
                uint32_t ad = st + r * 64 + ((cb ^ ((r >> 1) & 3)) << 4);
                LDSM4(w2[p], ad + GS_W);
            }
#pragma unroll
            for (int mt = 0; mt < 4; mt++)
#pragma unroll
                for (int nt = 0; nt < 4; nt++)
                    MMAF16(acc[mt][nt], a4[mt], w2[nt >> 1][nt & 1], w2[nt >> 1][(nt & 1) + 2]);
        }
        if (t + 2 < 32) issue(t + 2);
        CP_COMMIT();
    }

    const int g = lane >> 2, tig = lane & 3;
#pragma unroll
    for (int mt = 0; mt < 4; mt++) {
#pragma unroll
        for (int nt = 0; nt < 4; nt++) {
            int row = bm + wm * 64 + mt * 16 + g;
            int col = bn + wn * 32 + nt * 8 + tig * 2;
            float2 bv = *(const float2*)&bias[col];
            float v00 = acc[mt][nt][0] + bv.x, v01 = acc[mt][nt][1] + bv.y;
            float v10 = acc[mt][nt][2] + bv.x, v11 = acc[mt][nt][3] + bv.y;
            if (omode == 0) {
                *(float2*)(Cf + (size_t)row * D_ + col) = make_float2(v00, v01);
                *(float2*)(Cf + (size_t)(row + 8) * D_ + col) = make_float2(v10, v11);
            } else {
                *(uint32_t*)(Fh + (size_t)row * D_ + col) = pack2h(v00, v01);
                *(uint32_t*)(Fh + (size_t)(row + 8) * D_ + col) = pack2h(v10, v11);
            }
        }
    }
}

__global__ void __launch_bounds__(256) gemm_qkv_kernel(
    const __half* __restrict__ af, const __half* __restrict__ bf,
    const __half* __restrict__ wf,
    const float* __restrict__ bq, const float* __restrict__ bk,
    const float* __restrict__ bv,
    __half* __restrict__ qf, __half* __restrict__ kf, __half* __restrict__ vf)
{
    extern __shared__ char sm[];
    const int z = blockIdx.z;
    const __half* A = (z == 0) ? af : bf;
    const __half* W = wf + (size_t)z * D_ * D_;
    const float* bias = (z == 0) ? bq : (z == 1) ? bk : bv;
    __half* Fh = (z == 0) ? qf : (z == 1) ? kf : vf;
    gemm_body(sm, A, W, bias, 3, nullptr, Fh,
              blockIdx.y * 128, blockIdx.x * 128);
}

__global__ void __launch_bounds__(256) gemm_out_kernel(
    const __half* __restrict__ A, const __half* __restrict__ W,
    const float* __restrict__ bias, float* __restrict__ Cf)
{
    extern __shared__ char sm[];
    gemm_body(sm, A, W, bias, 0, Cf, nullptr,
              blockIdx.y * 128, blockIdx.x * 128);
}

// ------------------------------ fp16 flash attention (1-pass, 3-stage) -----
// Pipeline ordering mirrors gemm_body exactly: wait+barrier at top, compute,
// issue(t+2) at bottom. Buffer (t+2)%3 was last read in iteration t-1 and all
// warps passed this iteration's barrier, so the write is race-free.
#define FQ  0
#define FSB 16384
#define FK  0
#define FV  8192
#define FSTG 16384
#define FLASH_SMEM (FSB + 3 * FSTG)   // 65536

__global__ void __launch_bounds__(256) flash_mma_kernel(
    const __half* __restrict__ Qf_,
    const __half* __restrict__ Kf_, const __half* __restrict__ Vf_,
    const uint2* __restrict__ mbits, __half* __restrict__ Of)
{
    extern __shared__ char sm[];
    const uint32_t sb = smem_u32(sm);
    const int tid = threadIdx.x, wid = tid >> 5, lane = tid & 31;
    const int h = blockIdx.x, qt = blockIdx.y, b = blockIdx.z;
    const int qbase = qt * 128;
    const int g = lane >> 2, t4 = lane & 3;

    auto issue_kv = [&](int t) {
        uint32_t st = sb + FSB + (uint32_t)(t % 3) * FSTG;
#pragma unroll
        for (int i = 0; i < 2; i++) {
            int f = tid + i * 256;
            int r = f >> 3, c = f & 7;
            size_t go = ((size_t)(b * S_ + t * 64 + r)) * D_ + h * DH_ + c * 8;
            uint32_t so = r * 128 + ((c ^ (r & 7)) << 4);
            cp16(st + FK + so, Kf_ + go);
            cp16(st + FV + so, Vf_ + go);
        }
    };

    issue_kv(0); CP_COMMIT();
    issue_kv(1); CP_COMMIT();

    // Q tile (128 x 64 fp16), swizzled 128B rows
#pragma unroll
    for (int i = 0; i < 4; i++) {
        int f = tid + i * 256;
        int r = f >> 3, c = f & 7;
        size_t go = ((size_t)(b * S_ + qbase + r)) * D_ + h * DH_ + c * 8;
        uint32_t so = r * 128 + ((c ^ (r & 7)) << 4);
        *(uint4*)(sm + FQ + so) = *(const uint4*)(Qf_ + go);
    }
    __syncthreads();

    uint32_t qf[4][4];
    {
        const int lrow = wid * 16 + ((lane >> 3) & 1) * 8 + (lane & 7);
        const int lcb  = lane >> 4;
#pragma unroll
        for (int ks = 0; ks < 4; ks++) {
            uint32_t ad = sb + FQ + lrow * 128 + (((2 * ks + lcb) ^ (lrow & 7)) << 4);
            LDSM4(qf[ks], ad);
        }
    }

    float o[8][4];
#pragma unroll
    for (int n = 0; n < 8; n++)
#pragma unroll
        for (int e = 0; e < 4; e++) o[n][e] = 0.f;
    float m0 = -1e30f, m1 = -1e30f, l0 = 0.f, l1 = 0.f;

    const int qr0 = qbase + wid * 16 + g;
    const uint2* Mb0 = mbits + ((size_t)b * S_ + qr0) * 32;   // row qr0
    const uint2* Mb1 = Mb0 + (size_t)8 * 32;                   // row qr0+8

    for (int t = 0; t < S_ / 64; t++) {
        CP_WAIT1();
        __syncthreads();
        const uint32_t st = sb + FSB + (uint32_t)(t % 3) * FSTG;

        // ---- S = Q @ K^T : 1 pass
        float s[8][4];
#pragma unroll
        for (int n = 0; n < 8; n++)
#pragma unroll
            for (int e = 0; e < 4; e++) s[n][e] = 0.f;

        {
            const int krow = ((lane >> 4) << 3) + (lane & 7);
            const int kchb = (lane >> 3) & 1;
#pragma unroll
            for (int ks = 0; ks < 4; ks++) {
                const int kch = 2 * ks + kchb;
#pragma unroll
                for (int ng = 0; ng < 4; ng++) {
                    int r = ng * 16 + krow;
                    uint32_t ad = st + FK + r * 128 + ((kch ^ (r & 7)) << 4);
                    uint32_t k4[4];
                    LDSM4(k4, ad);
                    MMAF16(s[2 * ng],     qf[ks], k4[0], k4[1]);
                    MMAF16(s[2 * ng + 1], qf[ks], k4[2], k4[3]);
                }
            }
        }

        // ---- mask (bitmask) + scale + online softmax
        const uint2 w0 = Mb0[t];
        const uint2 w1 = Mb1[t];
        float mx0 = -1e30f, mx1 = -1e30f;
#pragma unroll
        for (int n = 0; n < 8; n++) {
            const uint32_t wa = (n < 4) ? w0.x : w0.y;
            const uint32_t wb = (n < 4) ? w1.x : w1.y;
            const int sh = (n & 3) * 8 + t4 * 2;
            s[n][0] = ((wa >> sh) & 1u)       ? s[n][0] * 0.125f : -1e9f;
            s[n][1] = ((wa >> (sh + 1)) & 1u) ? s[n][1] * 0.125f : -1e9f;
            s[n][2] = ((wb >> sh) & 1u)       ? s[n][2] * 0.125f : -1e9f;
            s[n][3] = ((wb >> (sh + 1)) & 1u) ? s[n][3] * 0.125f : -1e9f;
            mx0 = fmaxf(mx0, fmaxf(s[n][0], s[n][1]));
            mx1 = fmaxf(mx1, fmaxf(s[n][2], s[n][3]));
        }
        mx0 = fmaxf(mx0, __shfl_xor_sync(0xffffffffu, mx0, 1));
        mx0 = fmaxf(mx0, __shfl_xor_sync(0xffffffffu, mx0, 2));
        mx1 = fmaxf(mx1, __shfl_xor_sync(0xffffffffu, mx1, 1));
        mx1 = fmaxf(mx1, __shfl_xor_sync(0xffffffffu, mx1, 2));

        float mn0 = fmaxf(m0, mx0), mn1 = fmaxf(m1, mx1);
        float al0 = __expf(m0 - mn0), al1 = __expf(m1 - mn1);
        m0 = mn0; m1 = mn1;

        float rs0 = 0.f, rs1 = 0.f;
#pragma unroll
        for (int n = 0; n < 8; n++) {
            s[n][0] = __expf(s[n][0] - mn0);
            s[n][1] = __expf(s[n][1] - mn0);
            s[n][2] = __expf(s[n][2] - mn1);
            s[n][3] = __expf(s[n][3] - mn1);
            rs0 += s[n][0] + s[n][1];
            rs1 += s[n][2] + s[n][3];
        }
        rs0 += __shfl_xor_sync(0xffffffffu, rs0, 1);
        rs0 += __shfl_xor_sync(0xffffffffu, rs0, 2);
        rs1 += __shfl_xor_sync(0xffffffffu, rs1, 1);
        rs1 += __shfl_xor_sync(0xffffffffu, rs1, 2);
        l0 = l0 * al0 + rs0;
        l1 = l1 * al1 + rs1;
#pragma unroll
        for (int n = 0; n < 8; n++) {
            o[n][0] *= al0; o[n][1] *= al0;
            o[n][2] *= al1; o[n][3] *= al1;
        }

        // ---- O += P @ V : 1 pass
        {
            const int vrow_b = ((lane >> 3) & 1) * 8 + (lane & 7);
            const int vchb   = lane >> 4;
#pragma unroll
            for (int ks = 0; ks < 4; ks++) {
                uint32_t p4[4];
                p4[0] = pack2h(s[2 * ks][0],     s[2 * ks][1]);
                p4[1] = pack2h(s[2 * ks][2],     s[2 * ks][3]);
                p4[2] = pack2h(s[2 * ks + 1][0], s[2 * ks + 1][1]);
                p4[3] = pack2h(s[2 * ks + 1][2], s[2 * ks + 1][3]);
                const int vrow = ks * 16 + vrow_b;
#pragma unroll
                for (int ng = 0; ng < 4; ng++) {
                    uint32_t ad = st + FV + vrow * 128 + (((2 * ng + vchb) ^ (vrow & 7)) << 4);
                    uint32_t v4[4];
                    LDSM4T(v4, ad);
                    MMAF16(o[2 * ng],     p4, v4[0], v4[1]);
                    MMAF16(o[2 * ng + 1], p4, v4[2], v4[3]);
                }
            }
        }

        // issue next stage AFTER compute (race-free, mirrors gemm_body)
        if (t + 2 < S_ / 64) issue_kv(t + 2);
        CP_COMMIT();
    }

    const float inv0 = 1.f / l0, inv1 = 1.f / l1;
#pragma unroll
    for (int n = 0; n < 8; n++) {
        const int col = h * DH_ + n * 8 + t4 * 2;
        size_t o0 = ((size_t)(b * S_ + qr0)) * D_ + col;
        size_t o1 = o0 + (size_t)8 * D_;
        *(uint32_t*)(Of + o0) = pack2h(o[n][0] * inv0, o[n][1] * inv0);
        *(uint32_t*)(Of + o1) = pack2h(o[n][2] * inv1, o[n][3] * inv1);
    }
}

// ---------------------------------------------------------------------------
extern "C" void kernel_launch(void* const* d_in, const int* in_sizes, int n_in,
                              void* d_out, int out_size)
{
    (void)in_sizes; (void)n_in; (void)out_size;
    const float* q_tok  = (const float*)d_in[0];
    const float* kv_tok = (const float*)d_in[1];
    const int*   mask   = (const int*)d_in[2];
    const float* Wq = (const float*)d_in[3];
    const float* bq = (const float*)d_in[4];
    const float* Wk = (const float*)d_in[5];
    const float* bk = (const float*)d_in[6];
    const float* Wv = (const float*)d_in[7];
    const float* bv = (const float*)d_in[8];
    const float* Wo = (const float*)d_in[9];
    const float* bo = (const float*)d_in[10];
    float* out = (float*)d_out;

    __half *af, *bf, *wf, *qf, *kf, *vf, *cf;
    uint2* mb;
    cudaGetSymbolAddress((void**)&af, g_af);
    cudaGetSymbolAddress((void**)&bf, g_bf);
    cudaGetSymbolAddress((void**)&wf, g_wf);
    cudaGetSymbolAddress((void**)&qf, g_qf);
    cudaGetSymbolAddress((void**)&kf, g_kf);
    cudaGetSymbolAddress((void**)&vf, g_vf);
    cudaGetSymbolAddress((void**)&cf, g_cf);
    cudaGetSymbolAddress((void**)&mb, g_mb);

    cudaFuncSetAttribute(gemm_qkv_kernel,
                         cudaFuncAttributeMaxDynamicSharedMemorySize, GEMM_SMEM);
    cudaFuncSetAttribute(gemm_out_kernel,
                         cudaFuncAttributeMaxDynamicSharedMemorySize, GEMM_SMEM);
    cudaFuncSetAttribute(flash_mma_kernel,
                         cudaFuncAttributeMaxDynamicSharedMemorySize, FLASH_SMEM);

    const int nTok = M_ * D_;
    const int nW = D_ * D_;

    cvt_kernel<<<nTok / 1024, 256>>>(q_tok,  af, nTok);
    cvt_kernel<<<nTok / 1024, 256>>>(kv_tok, bf, nTok);
    dim3 wgrid(nW / 1024, 4);
    cvt4_kernel<<<wgrid, 256>>>(Wq, Wk, Wv, Wo, wf, nW);
    pack_mask_kernel<<<M_ / 8, 256>>>(mask, mb);

    dim3 qkvgrid(D_ / 128, M_ / 128, 3);   // (8, 32, 3)
    gemm_qkv_kernel<<<qkvgrid, 256, GEMM_SMEM>>>(
        af, bf, wf, bq, bk, bv, qf, kf, vf);

    dim3 fgrid(H_, S_ / 128, B_);          // (16, 16, 2)
    flash_mma_kernel<<<fgrid, 256, FLASH_SMEM>>>(qf, kf, vf, mb, cf);

    dim3 ogrid(D_ / 128, M_ / 128);
    gemm_out_kernel<<<ogrid, 256, GEMM_SMEM>>>(
        cf, wf + 3 * (size_t)nW, bo, out);
}

// round 14
// speedup vs baseline: 6.4053x; 1.0124x over previous
#include <cuda_runtime.h>
#include <cuda_fp16.h>
#include <cstdint>

#define B_  2
#define S_  2048
#define D_  1024
#define H_  16
#define DH_ 64
#define M_  (B_*S_)   // 4096

// ------------------------------ scratch (allocation-free rule) -------------
__device__ __half g_af[(size_t)M_ * D_];   // q tokens fp16
__device__ __half g_bf[(size_t)M_ * D_];   // kv tokens fp16
__device__ __half g_wf[(size_t)4 * D_ * D_];  // Wq,Wk,Wv,Wo fp16
__device__ __half g_qf[(size_t)M_ * D_];   // Q proj fp16
__device__ __half g_kf[(size_t)M_ * D_];   // K proj fp16
__device__ __half g_vf[(size_t)M_ * D_];   // V proj fp16
__device__ __half g_cf[(size_t)M_ * D_];   // ctx fp16
__device__ uint2  g_mb[(size_t)M_ * 32];   // mask bits: 64 per (row, 64-col chunk)

// ------------------------------ helpers ------------------------------------
__device__ __forceinline__ uint32_t smem_u32(const void* p) {
    uint32_t a;
    asm("{ .reg .u64 t; cvta.to.shared.u64 t, %1; cvt.u32.u64 %0, t; }"
        : "=r"(a) : "l"(p));
    return a;
}
__device__ __forceinline__ void cp16(uint32_t s, const void* g) {
    asm volatile("cp.async.cg.shared.global [%0], [%1], 16;" :: "r"(s), "l"(g));
}
#define CP_COMMIT() asm volatile("cp.async.commit_group;" ::: "memory")
#define CP_WAIT1()  asm volatile("cp.async.wait_group 1;" ::: "memory")

#define LDSM4(r, addr) \
    asm volatile("ldmatrix.sync.aligned.m8n8.x4.shared.b16 {%0,%1,%2,%3}, [%4];" \
        : "=r"((r)[0]), "=r"((r)[1]), "=r"((r)[2]), "=r"((r)[3]) : "r"(addr))

#define LDSM4T(r, addr) \
    asm volatile("ldmatrix.sync.aligned.m8n8.x4.trans.shared.b16 {%0,%1,%2,%3}, [%4];" \
        : "=r"((r)[0]), "=r"((r)[1]), "=r"((r)[2]), "=r"((r)[3]) : "r"(addr))

#define MMAF16(d, a, b0, b1) \
    asm volatile("mma.sync.aligned.m16n8k16.row.col.f32.f16.f16.f32 " \
        "{%0,%1,%2,%3}, {%4,%5,%6,%7}, {%8,%9}, {%0,%1,%2,%3};" \
        : "+f"((d)[0]), "+f"((d)[1]), "+f"((d)[2]), "+f"((d)[3]) \
        : "r"((a)[0]), "r"((a)[1]), "r"((a)[2]), "r"((a)[3]), "r"(b0), "r"(b1))

__device__ __forceinline__ uint32_t pack2h(float x, float y) {
    __half2 hh = __floats2half2_rn(x, y);
    return *(uint32_t*)&hh;
}

// ------------------------------ fused convert kernel ------------------------
// seg 0: q tokens, seg 1: kv tokens, seg 2..5: Wq/Wk/Wv/Wo
__global__ void __launch_bounds__(256) cvt_all_kernel(
    const float* __restrict__ q, const float* __restrict__ kv,
    const float* __restrict__ w0, const float* __restrict__ w1,
    const float* __restrict__ w2, const float* __restrict__ w3,
    __half* __restrict__ af, __half* __restrict__ bf,
    __half* __restrict__ wf, int nTok, int nW)
{
    const int seg = blockIdx.y;
    const float* src;
    __half* dst;
    int n;
    if (seg == 0)      { src = q;  dst = af; n = nTok; }
    else if (seg == 1) { src = kv; dst = bf; n = nTok; }
    else {
        src = (seg == 2) ? w0 : (seg == 3) ? w1 : (seg == 4) ? w2 : w3;
        dst = wf + (size_t)(seg - 2) * nW;
        n = nW;
    }
    int i = (blockIdx.x * 256 + threadIdx.x) * 4;
    if (i >= n) return;
    float4 v = *(const float4*)(src + i);
    *(uint2*)((char*)dst + (size_t)i * 2) =
        make_uint2(pack2h(v.x, v.y), pack2h(v.z, v.w));
}

// Pack mask (B*S rows x S int32) into 64-bit chunks.
__global__ void __launch_bounds__(256) pack_mask_kernel(
    const int* __restrict__ mask, uint2* __restrict__ bits)
{
    int warp = (blockIdx.x * 256 + threadIdx.x) >> 5;
    int lane = threadIdx.x & 31;
    if (warp >= M_) return;
    const int* mrow = mask + (size_t)warp * S_;
#pragma unroll 4
    for (int c = 0; c < 32; c++) {
        int m0 = mrow[c * 64 + lane];
        int m1 = mrow[c * 64 + 32 + lane];
        uint32_t b0 = __ballot_sync(0xffffffffu, m0 != 0);
        uint32_t b1 = __ballot_sync(0xffffffffu, m1 != 0);
        if (lane == 0) bits[(size_t)warp * 32 + c] = make_uint2(b0, b1);
    }
}

// ------------------------------ fp16 GEMM body (3-stage cp.async, 1-pass) --
// Per iteration: barrier -> issue(t+2) (safe: all warps past barrier have
// finished t-1 reads of buffer (t+2)%3) -> prefetch ALL 12 fragment LDSMs ->
// 32 back-to-back MMAs (order per accumulator unchanged: ks0 then ks1).
#define GS_A  0
#define GS_W  8192
#define GSTG  16384
#define GEMM_SMEM (3 * GSTG)   // 49152

__device__ __forceinline__ void gemm_body(
    char* sm,
    const __half* __restrict__ A, const __half* __restrict__ W,
    const float* __restrict__ bias, int omode, float* __restrict__ Cf,
    __half* __restrict__ Fh, int bm, int bn)
{
    const uint32_t sb = smem_u32(sm);
    const int tid = threadIdx.x;
    const int wid = tid >> 5, lane = tid & 31;
    const int wm = wid >> 2, wn = wid & 3;

    const int lrow = (lane & 7) + ((lane >> 3) & 1) * 8;
    const int lcb  = lane >> 4;

    float acc[4][4][4];
#pragma unroll
    for (int mt = 0; mt < 4; mt++)
#pragma unroll
        for (int nt = 0; nt < 4; nt++)
#pragma unroll
            for (int e = 0; e < 4; e++) acc[mt][nt][e] = 0.f;

    auto issue = [&](int t) {
        uint32_t st = sb + (uint32_t)(t % 3) * GSTG;
#pragma unroll
        for (int i = 0; i < 2; i++) {
            int f = tid + i * 256;
            int r = f >> 2, cb = f & 3;
            size_t gA = (size_t)(bm + r) * D_ + t * 32 + cb * 8;
            size_t gW = (size_t)(bn + r) * D_ + t * 32 + cb * 8;
            uint32_t so = r * 64 + ((cb ^ ((r >> 1) & 3)) << 4);
            cp16(st + GS_A + so, A + gA);
            cp16(st + GS_W + so, W + gW);
        }
    };

    issue(0); CP_COMMIT();
    issue(1); CP_COMMIT();

    for (int t = 0; t < 32; t++) {
        CP_WAIT1();
        __syncthreads();
        if (t + 2 < 32) issue(t + 2);
        CP_COMMIT();
        const uint32_t st = sb + (uint32_t)(t % 3) * GSTG;

        uint32_t a4[2][4][4], w2[2][2][4];
#pragma unroll
        for (int ks = 0; ks < 2; ks++) {
            const int cb = ks * 2 + lcb;
#pragma unroll
            for (int mt = 0; mt < 4; mt++) {
                int r = wm * 64 + mt * 16 + lrow;
                uint32_t ad = st + r * 64 + ((cb ^ ((r >> 1) & 3)) << 4);
                LDSM4(a4[ks][mt], ad + GS_A);
            }
#pragma unroll
            for (int p = 0; p < 2; p++) {
                int r = wn * 32 + p * 16 + lrow;
                uint32_t ad = st + r * 64 + ((cb ^ ((r >> 1) & 3)) << 4);
                LDSM4(w2[ks][p], ad + GS_W);
            }
        }
#pragma unroll
        for (int ks = 0; ks < 2; ks++)
#pragma unroll
            for (int mt = 0; mt < 4; mt++)
#pragma unroll
                for (int nt = 0; nt < 4; nt++)
                    MMAF16(acc[mt][nt], a4[ks][mt],
                           w2[ks][nt >> 1][nt & 1], w2[ks][nt >> 1][(nt & 1) + 2]);
    }

    const int g = lane >> 2, tig = lane & 3;
#pragma unroll
    for (int mt = 0; mt < 4; mt++) {
#pragma unroll
        for (int nt = 0; nt < 4; nt++) {
            int row = bm + wm * 64 + mt * 16 + g;
            int col = bn + wn * 32 + nt * 8 + tig * 2;
            float2 bv = *(const float2*)&bias[col];
            float v00 = acc[mt][nt][0] + bv.x, v01 = acc[mt][nt][1] + bv.y;
            float v10 = acc[mt][nt][2] + bv.x, v11 = acc[mt][nt][3] + bv.y;
            if (omode == 0) {
                *(float2*)(Cf + (size_t)row * D_ + col) = make_float2(v00, v01);
                *(float2*)(Cf + (size_t)(row + 8) * D_ + col) = make_float2(v10, v11);
            } else {
                *(uint32_t*)(Fh + (size_t)row * D_ + col) = pack2h(v00, v01);
                *(uint32_t*)(Fh + (size_t)(row + 8) * D_ + col) = pack2h(v10, v11);
            }
        }
    }
}

__global__ void __launch_bounds__(256, 2) gemm_qkv_kernel(
    const __half* __restrict__ af, const __half* __restrict__ bf,
    const __half* __restrict__ wf,
    const float* __restrict__ bq, const float* __restrict__ bk,
    const float* __restrict__ bv,
    __half* __restrict__ qf, __half* __restrict__ kf, __half* __restrict__ vf)
{
    extern __shared__ char sm[];
    const int z = blockIdx.z;
    const __half* A = (z == 0) ? af : bf;
    const __half* W = wf + (size_t)z * D_ * D_;
    const float* bias = (z == 0) ? bq : (z == 1) ? bk : bv;
    __half* Fh = (z == 0) ? qf : (z == 1) ? kf : vf;
    gemm_body(sm, A, W, bias, 3, nullptr, Fh,
              blockIdx.y * 128, blockIdx.x * 128);
}

__global__ void __launch_bounds__(256, 2) gemm_out_kernel(
    const __half* __restrict__ A, const __half* __restrict__ W,
    const float* __restrict__ bias, float* __restrict__ Cf)
{
    extern __shared__ char sm[];
    gemm_body(sm, A, W, bias, 0, Cf, nullptr,
              blockIdx.y * 128, blockIdx.x * 128);
}

// ------------------------------ fp16 flash attention (1-pass, 3-stage) -----
#define FQ  0
#define FSB 16384
#define FK  0
#define FV  8192
#define FSTG 16384
#define FLASH_SMEM (FSB + 3 * FSTG)   // 65536

__global__ void __launch_bounds__(256, 2) flash_mma_kernel(
    const __half* __restrict__ Qf_,
    const __half* __restrict__ Kf_, const __half* __restrict__ Vf_,
    const uint2* __restrict__ mbits, __half* __restrict__ Of)
{
    extern __shared__ char sm[];
    const uint32_t sb = smem_u32(sm);
    const int tid = threadIdx.x, wid = tid >> 5, lane = tid & 31;
    const int h = blockIdx.x, qt = blockIdx.y, b = blockIdx.z;
    const int qbase = qt * 128;
    const int g = lane >> 2, t4 = lane & 3;

    auto issue_kv = [&](int t) {
        uint32_t st = sb + FSB + (uint32_t)(t % 3) * FSTG;
#pragma unroll
        for (int i = 0; i < 2; i++) {
            int f = tid + i * 256;
            int r = f >> 3, c = f & 7;
            size_t go = ((size_t)(b * S_ + t * 64 + r)) * D_ + h * DH_ + c * 8;
            uint32_t so = r * 128 + ((c ^ (r & 7)) << 4);
            cp16(st + FK + so, Kf_ + go);
            cp16(st + FV + so, Vf_ + go);
        }
    };

    issue_kv(0); CP_COMMIT();
    issue_kv(1); CP_COMMIT();

    // Q tile (128 x 64 fp16), swizzled 128B rows
#pragma unroll
    for (int i = 0; i < 4; i++) {
        int f = tid + i * 256;
        int r = f >> 3, c = f & 7;
        size_t go = ((size_t)(b * S_ + qbase + r)) * D_ + h * DH_ + c * 8;
        uint32_t so = r * 128 + ((c ^ (r & 7)) << 4);
        *(uint4*)(sm + FQ + so) = *(const uint4*)(Qf_ + go);
    }
    __syncthreads();

    uint32_t qf[4][4];
    {
        const int lrow = wid * 16 + ((lane >> 3) & 1) * 8 + (lane & 7);
        const int lcb  = lane >> 4;
#pragma unroll
        for (int ks = 0; ks < 4; ks++) {
            uint32_t ad = sb + FQ + lrow * 128 + (((2 * ks + lcb) ^ (lrow & 7)) << 4);
            LDSM4(qf[ks], ad);
        }
    }

    float o[8][4];
#pragma unroll
    for (int n = 0; n < 8; n++)
#pragma unroll
        for (int e = 0; e < 4; e++) o[n][e] = 0.f;
    float m0 = -1e30f, m1 = -1e30f, l0 = 0.f, l1 = 0.f;

    const int qr0 = qbase + wid * 16 + g;
    const uint2* Mb0 = mbits + ((size_t)b * S_ + qr0) * 32;   // row qr0
    const uint2* Mb1 = Mb0 + (size_t)8 * 32;                   // row qr0+8

    const int krow = ((lane >> 4) << 3) + (lane & 7);
    const int kchb = (lane >> 3) & 1;
    const int vrow_b = ((lane >> 3) & 1) * 8 + (lane & 7);
    const int vchb   = lane >> 4;

    for (int t = 0; t < S_ / 64; t++) {
        CP_WAIT1();
        __syncthreads();
        if (t + 2 < S_ / 64) issue_kv(t + 2);
        CP_COMMIT();
        const uint32_t st = sb + FSB + (uint32_t)(t % 3) * FSTG;

        // ---- S = Q @ K^T : 2-deep ldsm/MMA pipeline, order preserved
        float s[8][4];
#pragma unroll
        for (int n = 0; n < 8; n++)
#pragma unroll
            for (int e = 0; e < 4; e++) s[n][e] = 0.f;

        {
            auto kaddr = [&](int idx) {
                int ks = idx >> 2, ng = idx & 3;
                int kch = 2 * ks + kchb;
                int r = ng * 16 + krow;
                return st + FK + r * 128 + ((kch ^ (r & 7)) << 4);
            };
            uint32_t k4[2][4];
            LDSM4(k4[0], kaddr(0));
#pragma unroll
            for (int idx = 0; idx < 16; idx++) {
                if (idx + 1 < 16) LDSM4(k4[(idx + 1) & 1], kaddr(idx + 1));
                const int ks = idx >> 2, ng = idx & 3, cur = idx & 1;
                MMAF16(s[2 * ng],     qf[ks], k4[cur][0], k4[cur][1]);
                MMAF16(s[2 * ng + 1], qf[ks], k4[cur][2], k4[cur][3]);
            }
        }

        // ---- mask (bitmask) + scale + online softmax
        const uint2 w0 = Mb0[t];
        const uint2 w1 = Mb1[t];
        float mx0 = -1e30f, mx1 = -1e30f;
#pragma unroll
        for (int n = 0; n < 8; n++) {
            const uint32_t wa = (n < 4) ? w0.x : w0.y;
            const uint32_t wb = (n < 4) ? w1.x : w1.y;
            const int sh = (n & 3) * 8 + t4 * 2;
            s[n][0] = ((wa >> sh) & 1u)       ? s[n][0] * 0.125f : -1e9f;
            s[n][1] = ((wa >> (sh + 1)) & 1u) ? s[n][1] * 0.125f : -1e9f;
            s[n][2] = ((wb >> sh) & 1u)       ? s[n][2] * 0.125f : -1e9f;
            s[n][3] = ((wb >> (sh + 1)) & 1u) ? s[n][3] * 0.125f : -1e9f;
            mx0 = fmaxf(mx0, fmaxf(s[n][0], s[n][1]));
            mx1 = fmaxf(mx1, fmaxf(s[n][2], s[n][3]));
        }
        mx0 = fmaxf(mx0, __shfl_xor_sync(0xffffffffu, mx0, 1));
        mx0 = fmaxf(mx0, __shfl_xor_sync(0xffffffffu, mx0, 2));
        mx1 = fmaxf(mx1, __shfl_xor_sync(0xffffffffu, mx1, 1));
        mx1 = fmaxf(mx1, __shfl_xor_sync(0xffffffffu, mx1, 2));

        float mn0 = fmaxf(m0, mx0), mn1 = fmaxf(m1, mx1);
        float al0 = __expf(m0 - mn0), al1 = __expf(m1 - mn1);
        m0 = mn0; m1 = mn1;

        float rs0 = 0.f, rs1 = 0.f;
#pragma unroll
        for (int n = 0; n < 8; n++) {
            s[n][0] = __expf(s[n][0] - mn0);
            s[n][1] = __expf(s[n][1] - mn0);
            s[n][2] = __expf(s[n][2] - mn1);
            s[n][3] = __expf(s[n][3] - mn1);
            rs0 += s[n][0] + s[n][1];
            rs1 += s[n][2] + s[n][3];
        }
        rs0 += __shfl_xor_sync(0xffffffffu, rs0, 1);
        rs0 += __shfl_xor_sync(0xffffffffu, rs0, 2);
        rs1 += __shfl_xor_sync(0xffffffffu, rs1, 1);
        rs1 += __shfl_xor_sync(0xffffffffu, rs1, 2);
        l0 = l0 * al0 + rs0;
        l1 = l1 * al1 + rs1;
#pragma unroll
        for (int n = 0; n < 8; n++) {
            o[n][0] *= al0; o[n][1] *= al0;
            o[n][2] *= al1; o[n][3] *= al1;
        }

        // ---- O += P @ V : 2-deep ldsm/MMA pipeline, order preserved
        {
            auto vaddr = [&](int idx) {
                int ks = idx >> 2, ng = idx & 3;
                int vrow = ks * 16 + vrow_b;
                return st + FV + vrow * 128 + (((2 * ng + vchb) ^ (vrow & 7)) << 4);
            };
            uint32_t v4[2][4];
            LDSM4T(v4[0], vaddr(0));
            uint32_t p4[4];
#pragma unroll
            for (int idx = 0; idx < 16; idx++) {
                const int ks = idx >> 2, ng = idx & 3, cur = idx & 1;
                if (ng == 0) {
                    p4[0] = pack2h(s[2 * ks][0],     s[2 * ks][1]);
                    p4[1] = pack2h(s[2 * ks][2],     s[2 * ks][3]);
                    p4[2] = pack2h(s[2 * ks + 1][0], s[2 * ks + 1][1]);
                    p4[3] = pack2h(s[2 * ks + 1][2], s[2 * ks + 1][3]);
                }
                if (idx + 1 < 16) LDSM4T(v4[(idx + 1) & 1], vaddr(idx + 1));
                MMAF16(o[2 * ng],     p4, v4[cur][0], v4[cur][1]);
                MMAF16(o[2 * ng + 1], p4, v4[cur][2], v4[cur][3]);
            }
        }
    }

    const float inv0 = 1.f / l0, inv1 = 1.f / l1;
#pragma unroll
    for (int n = 0; n < 8; n++) {
        const int col = h * DH_ + n * 8 + t4 * 2;
        size_t o0 = ((size_t)(b * S_ + qr0)) * D_ + col;
        size_t o1 = o0 + (size_t)8 * D_;
        *(uint32_t*)(Of + o0) = pack2h(o[n][0] * inv0, o[n][1] * inv0);
        *(uint32_t*)(Of + o1) = pack2h(o[n][2] * inv1, o[n][3] * inv1);
    }
}

// ---------------------------------------------------------------------------
extern "C" void kernel_launch(void* const* d_in, const int* in_sizes, int n_in,
                              void* d_out, int out_size)
{
    (void)in_sizes; (void)n_in; (void)out_size;
    const float* q_tok  = (const float*)d_in[0];
    const float* kv_tok = (const float*)d_in[1];
    const int*   mask   = (const int*)d_in[2];
    const float* Wq = (const float*)d_in[3];
    const float* bq = (const float*)d_in[4];
    const float* Wk = (const float*)d_in[5];
    const float* bk = (const float*)d_in[6];
    const float* Wv = (const float*)d_in[7];
    const float* bv = (const float*)d_in[8];
    const float* Wo = (const float*)d_in[9];
    const float* bo = (const float*)d_in[10];
    float* out = (float*)d_out;

    __half *af, *bf, *wf, *qf, *kf, *vf, *cf;
    uint2* mb;
    cudaGetSymbolAddress((void**)&af, g_af);
    cudaGetSymbolAddress((void**)&bf, g_bf);
    cudaGetSymbolAddress((void**)&wf, g_wf);
    cudaGetSymbolAddress((void**)&qf, g_qf);
    cudaGetSymbolAddress((void**)&kf, g_kf);
    cudaGetSymbolAddress((void**)&vf, g_vf);
    cudaGetSymbolAddress((void**)&cf, g_cf);
    cudaGetSymbolAddress((void**)&mb, g_mb);

    cudaFuncSetAttribute(gemm_qkv_kernel,
                         cudaFuncAttributeMaxDynamicSharedMemorySize, GEMM_SMEM);
    cudaFuncSetAttribute(gemm_out_kernel,
                         cudaFuncAttributeMaxDynamicSharedMemorySize, GEMM_SMEM);
    cudaFuncSetAttribute(flash_mma_kernel,
                         cudaFuncAttributeMaxDynamicSharedMemorySize, FLASH_SMEM);

    const int nTok = M_ * D_;
    const int nW = D_ * D_;

    dim3 cgrid(nTok / 1024, 6);
    cvt_all_kernel<<<cgrid, 256>>>(q_tok, kv_tok, Wq, Wk, Wv, Wo,
                                   af, bf, wf, nTok, nW);
    pack_mask_kernel<<<M_ / 8, 256>>>(mask, mb);

    dim3 qkvgrid(D_ / 128, M_ / 128, 3);   // (8, 32, 3)
    gemm_qkv_kernel<<<qkvgrid, 256, GEMM_SMEM>>>(
        af, bf, wf, bq, bk, bv, qf, kf, vf);

    dim3 fgrid(H_, S_ / 128, B_);          // (16, 16, 2)
    flash_mma_kernel<<<fgrid, 256, FLASH_SMEM>>>(qf, kf, vf, mb, cf);

    dim3 ogrid(D_ / 128, M_ / 128);
    gemm_out_kernel<<<ogrid, 256, GEMM_SMEM>>>(
        cf, wf + 3 * (size_t)nW, bo, out);
}

// round 15
// speedup vs baseline: 6.4550x; 1.0077x over previous
#include <cuda_runtime.h>
#include <cuda_fp16.h>
#include <cstdint>

#define B_  2
#define S_  2048
#define D_  1024
#define H_  16
#define DH_ 64
#define M_  (B_*S_)   // 4096

// 0.125 * log2(e): folds the 1/sqrt(dh) score scale AND the exp->exp2
// conversion into the Q projection output (single fp16 rounding, applied
// in fp32 before the pack, so no extra rounding vs baseline).
#define QSCALE 0.18033688011112042f

// ------------------------------ scratch (allocation-free rule) -------------
__device__ __half g_af[(size_t)M_ * D_];
__device__ __half g_bf[(size_t)M_ * D_];
__device__ __half g_wf[(size_t)4 * D_ * D_];
__device__ __half g_qf[(size_t)M_ * D_];
__device__ __half g_kf[(size_t)M_ * D_];
__device__ __half g_vf[(size_t)M_ * D_];
__device__ __half g_cf[(size_t)M_ * D_];
__device__ uint2  g_mb[(size_t)M_ * 32];

// ------------------------------ helpers ------------------------------------
__device__ __forceinline__ uint32_t smem_u32(const void* p) {
    uint32_t a;
    asm("{ .reg .u64 t; cvta.to.shared.u64 t, %1; cvt.u32.u64 %0, t; }"
        : "=r"(a) : "l"(p));
    return a;
}
__device__ __forceinline__ void cp16(uint32_t s, const void* g) {
    asm volatile("cp.async.cg.shared.global [%0], [%1], 16;" :: "r"(s), "l"(g));
}
#define CP_COMMIT() asm volatile("cp.async.commit_group;" ::: "memory")
#define CP_WAIT1()  asm volatile("cp.async.wait_group 1;" ::: "memory")

#define LDSM4(r, addr) \
    asm volatile("ldmatrix.sync.aligned.m8n8.x4.shared.b16 {%0,%1,%2,%3}, [%4];" \
        : "=r"((r)[0]), "=r"((r)[1]), "=r"((r)[2]), "=r"((r)[3]) : "r"(addr))

#define LDSM4T(r, addr) \
    asm volatile("ldmatrix.sync.aligned.m8n8.x4.trans.shared.b16 {%0,%1,%2,%3}, [%4];" \
        : "=r"((r)[0]), "=r"((r)[1]), "=r"((r)[2]), "=r"((r)[3]) : "r"(addr))

#define MMAF16(d, a, b0, b1) \
    asm volatile("mma.sync.aligned.m16n8k16.row.col.f32.f16.f16.f32 " \
        "{%0,%1,%2,%3}, {%4,%5,%6,%7}, {%8,%9}, {%0,%1,%2,%3};" \
        : "+f"((d)[0]), "+f"((d)[1]), "+f"((d)[2]), "+f"((d)[3]) \
        : "r"((a)[0]), "r"((a)[1]), "r"((a)[2]), "r"((a)[3]), "r"(b0), "r"(b1))

__device__ __forceinline__ uint32_t pack2h(float x, float y) {
    __half2 hh = __floats2half2_rn(x, y);
    return *(uint32_t*)&hh;
}

// ------------------------------ fused convert kernel ------------------------
__global__ void __launch_bounds__(256) cvt_all_kernel(
    const float* __restrict__ q, const float* __restrict__ kv,
    const float* __restrict__ w0, const float* __restrict__ w1,
    const float* __restrict__ w2, const float* __restrict__ w3,
    __half* __restrict__ af, __half* __restrict__ bf,
    __half* __restrict__ wf, int nTok, int nW)
{
    const int seg = blockIdx.y;
    const float* src;
    __half* dst;
    int n;
    if (seg == 0)      { src = q;  dst = af; n = nTok; }
    else if (seg == 1) { src = kv; dst = bf; n = nTok; }
    else {
        src = (seg == 2) ? w0 : (seg == 3) ? w1 : (seg == 4) ? w2 : w3;
        dst = wf + (size_t)(seg - 2) * nW;
        n = nW;
    }
    int i = (blockIdx.x * 256 + threadIdx.x) * 4;
    if (i >= n) return;
    float4 v = *(const float4*)(src + i);
    *(uint2*)((char*)dst + (size_t)i * 2) =
        make_uint2(pack2h(v.x, v.y), pack2h(v.z, v.w));
}

__global__ void __launch_bounds__(256) pack_mask_kernel(
    const int* __restrict__ mask, uint2* __restrict__ bits)
{
    int warp = (blockIdx.x * 256 + threadIdx.x) >> 5;
    int lane = threadIdx.x & 31;
    if (warp >= M_) return;
    const int* mrow = mask + (size_t)warp * S_;
#pragma unroll 4
    for (int c = 0; c < 32; c++) {
        int m0 = mrow[c * 64 + lane];
        int m1 = mrow[c * 64 + 32 + lane];
        uint32_t b0 = __ballot_sync(0xffffffffu, m0 != 0);
        uint32_t b1 = __ballot_sync(0xffffffffu, m1 != 0);
        if (lane == 0) bits[(size_t)warp * 32 + c] = make_uint2(b0, b1);
    }
}

// ------------------------------ fp16 GEMM body (3-stage cp.async, 1-pass) --
#define GS_A  0
#define GS_W  8192
#define GSTG  16384
#define GEMM_SMEM (3 * GSTG)   // 49152

__device__ __forceinline__ void gemm_body(
    char* sm,
    const __half* __restrict__ A, const __half* __restrict__ W,
    const float* __restrict__ bias, int omode, float oscale,
    float* __restrict__ Cf, __half* __restrict__ Fh, int bm, int bn)
{
    const uint32_t sb = smem_u32(sm);
    const int tid = threadIdx.x;
    const int wid = tid >> 5, lane = tid & 31;
    const int wm = wid >> 2, wn = wid & 3;

    const int lrow = (lane & 7) + ((lane >> 3) & 1) * 8;
    const int lcb  = lane >> 4;

    float acc[4][4][4];
#pragma unroll
    for (int mt = 0; mt < 4; mt++)
#pragma unroll
        for (int nt = 0; nt < 4; nt++)
#pragma unroll
            for (int e = 0; e < 4; e++) acc[mt][nt][e] = 0.f;

    auto issue = [&](int t) {
        uint32_t st = sb + (uint32_t)(t % 3) * GSTG;
#pragma unroll
        for (int i = 0; i < 2; i++) {
            int f = tid + i * 256;
            int r = f >> 2, cb = f & 3;
            size_t gA = (size_t)(bm + r) * D_ + t * 32 + cb * 8;
            size_t gW = (size_t)(bn + r) * D_ + t * 32 + cb * 8;
            uint32_t so = r * 64 + ((cb ^ ((r >> 1) & 3)) << 4);
            cp16(st + GS_A + so, A + gA);
            cp16(st + GS_W + so, W + gW);
        }
    };

    issue(0); CP_COMMIT();
    issue(1); CP_COMMIT();

    for (int t = 0; t < 32; t++) {
        CP_WAIT1();
        __syncthreads();
        if (t + 2 < 32) issue(t + 2);
        CP_COMMIT();
        const uint32_t st = sb + (uint32_t)(t % 3) * GSTG;

        uint32_t a4[2][4][4], w2[2][2][4];
#pragma unroll
        for (int ks = 0; ks < 2; ks++) {
            const int cb = ks * 2 + lcb;
#pragma unroll
            for (int mt = 0; mt < 4; mt++) {
                int r = wm * 64 + mt * 16 + lrow;
                uint32_t ad = st + r * 64 + ((cb ^ ((r >> 1) & 3)) << 4);
                LDSM4(a4[ks][mt], ad + GS_A);
            }
#pragma unroll
            for (int p = 0; p < 2; p++) {
                int r = wn * 32 + p * 16 + lrow;
                uint32_t ad = st + r * 64 + ((cb ^ ((r >> 1) & 3)) << 4);
                LDSM4(w2[ks][p], ad + GS_W);
            }
        }
#pragma unroll
        for (int ks = 0; ks < 2; ks++)
#pragma unroll
            for (int mt = 0; mt < 4; mt++)
#pragma unroll
                for (int nt = 0; nt < 4; nt++)
                    MMAF16(acc[mt][nt], a4[ks][mt],
                           w2[ks][nt >> 1][nt & 1], w2[ks][nt >> 1][(nt & 1) + 2]);
    }

    const int g = lane >> 2, tig = lane & 3;
#pragma unroll
    for (int mt = 0; mt < 4; mt++) {
#pragma unroll
        for (int nt = 0; nt < 4; nt++) {
            int row = bm + wm * 64 + mt * 16 + g;
            int col = bn + wn * 32 + nt * 8 + tig * 2;
            float2 bv = *(const float2*)&bias[col];
            float v00 = (acc[mt][nt][0] + bv.x) * oscale;
            float v01 = (acc[mt][nt][1] + bv.y) * oscale;
            float v10 = (acc[mt][nt][2] + bv.x) * oscale;
            float v11 = (acc[mt][nt][3] + bv.y) * oscale;
            if (omode == 0) {
                *(float2*)(Cf + (size_t)row * D_ + col) = make_float2(v00, v01);
                *(float2*)(Cf + (size_t)(row + 8) * D_ + col) = make_float2(v10, v11);
            } else {
                *(uint32_t*)(Fh + (size_t)row * D_ + col) = pack2h(v00, v01);
                *(uint32_t*)(Fh + (size_t)(row + 8) * D_ + col) = pack2h(v10, v11);
            }
        }
    }
}

__global__ void __launch_bounds__(256, 2) gemm_qkv_kernel(
    const __half* __restrict__ af, const __half* __restrict__ bf,
    const __half* __restrict__ wf,
    const float* __restrict__ bq, const float* __restrict__ bk,
    const float* __restrict__ bv,
    __half* __restrict__ qf, __half* __restrict__ kf, __half* __restrict__ vf)
{
    extern __shared__ char sm[];
    const int z = blockIdx.z;
    const __half* A = (z == 0) ? af : bf;
    const __half* W = wf + (size_t)z * D_ * D_;
    const float* bias = (z == 0) ? bq : (z == 1) ? bk : bv;
    __half* Fh = (z == 0) ? qf : (z == 1) ? kf : vf;
    const float oscale = (z == 0) ? QSCALE : 1.f;   // Q pre-scaled for base-2 softmax
    gemm_body(sm, A, W, bias, 3, oscale, nullptr, Fh,
              blockIdx.y * 128, blockIdx.x * 128);
}

__global__ void __launch_bounds__(256, 2) gemm_out_kernel(
    const __half* __restrict__ A, const __half* __restrict__ W,
    const float* __restrict__ bias, float* __restrict__ Cf)
{
    extern __shared__ char sm[];
    gemm_body(sm, A, W, bias, 0, 1.f, Cf, nullptr,
              blockIdx.y * 128, blockIdx.x * 128);
}

// ------------------------------ fp16 flash attention (1-pass, 3-stage) -----
// Base-2 softmax: Q is pre-scaled by 0.125*log2e, so softmax = 2^(s-max).
// Max is taken over RAW scores (shift-invariance makes including masked
// elements harmless); mask zeroes elements AFTER exp.
#define FQ  0
#define FSB 16384
#define FK  0
#define FV  8192
#define FSTG 16384
#define FLASH_SMEM (FSB + 3 * FSTG)   // 65536

__global__ void __launch_bounds__(256, 2) flash_mma_kernel(
    const __half* __restrict__ Qf_,
    const __half* __restrict__ Kf_, const __half* __restrict__ Vf_,
    const uint2* __restrict__ mbits, __half* __restrict__ Of)
{
    extern __shared__ char sm[];
    const uint32_t sb = smem_u32(sm);
    const int tid = threadIdx.x, wid = tid >> 5, lane = tid & 31;
    const int h = blockIdx.x, qt = blockIdx.y, b = blockIdx.z;
    const int qbase = qt * 128;
    const int g = lane >> 2, t4 = lane & 3;

    auto issue_kv = [&](int t) {
        uint32_t st = sb + FSB + (uint32_t)(t % 3) * FSTG;
#pragma unroll
        for (int i = 0; i < 2; i++) {
            int f = tid + i * 256;
            int r = f >> 3, c = f & 7;
            size_t go = ((size_t)(b * S_ + t * 64 + r)) * D_ + h * DH_ + c * 8;
            uint32_t so = r * 128 + ((c ^ (r & 7)) << 4);
            cp16(st + FK + so, Kf_ + go);
            cp16(st + FV + so, Vf_ + go);
        }
    };

    issue_kv(0); CP_COMMIT();
    issue_kv(1); CP_COMMIT();

#pragma unroll
    for (int i = 0; i < 4; i++) {
        int f = tid + i * 256;
        int r = f >> 3, c = f & 7;
        size_t go = ((size_t)(b * S_ + qbase + r)) * D_ + h * DH_ + c * 8;
        uint32_t so = r * 128 + ((c ^ (r & 7)) << 4);
        *(uint4*)(sm + FQ + so) = *(const uint4*)(Qf_ + go);
    }
    __syncthreads();

    uint32_t qf[4][4];
    {
        const int lrow = wid * 16 + ((lane >> 3) & 1) * 8 + (lane & 7);
        const int lcb  = lane >> 4;
#pragma unroll
        for (int ks = 0; ks < 4; ks++) {
            uint32_t ad = sb + FQ + lrow * 128 + (((2 * ks + lcb) ^ (lrow & 7)) << 4);
            LDSM4(qf[ks], ad);
        }
    }

    float o[8][4];
#pragma unroll
    for (int n = 0; n < 8; n++)
#pragma unroll
        for (int e = 0; e < 4; e++) o[n][e] = 0.f;
    float m0 = -1e30f, m1 = -1e30f, l0 = 0.f, l1 = 0.f;

    const int qr0 = qbase + wid * 16 + g;
    const uint2* Mb0 = mbits + ((size_t)b * S_ + qr0) * 32;
    const uint2* Mb1 = Mb0 + (size_t)8 * 32;

    const int krow = ((lane >> 4) << 3) + (lane & 7);
    const int kchb = (lane >> 3) & 1;
    const int vrow_b = ((lane >> 3) & 1) * 8 + (lane & 7);
    const int vchb   = lane >> 4;

    for (int t = 0; t < S_ / 64; t++) {
        CP_WAIT1();
        __syncthreads();
        if (t + 2 < S_ / 64) issue_kv(t + 2);
        CP_COMMIT();
        const uint32_t st = sb + FSB + (uint32_t)(t % 3) * FSTG;

        // ---- S = Q @ K^T (scores already in base-2 domain)
        float s[8][4];
#pragma unroll
        for (int n = 0; n < 8; n++)
#pragma unroll
            for (int e = 0; e < 4; e++) s[n][e] = 0.f;

        {
            auto kaddr = [&](int idx) {
                int ks = idx >> 2, ng = idx & 3;
                int kch = 2 * ks + kchb;
                int r = ng * 16 + krow;
                return st + FK + r * 128 + ((kch ^ (r & 7)) << 4);
            };
            uint32_t k4[2][4];
            LDSM4(k4[0], kaddr(0));
#pragma unroll
            for (int idx = 0; idx < 16; idx++) {
                if (idx + 1 < 16) LDSM4(k4[(idx + 1) & 1], kaddr(idx + 1));
                const int ks = idx >> 2, ng = idx & 3, cur = idx & 1;
                MMAF16(s[2 * ng],     qf[ks], k4[cur][0], k4[cur][1]);
                MMAF16(s[2 * ng + 1], qf[ks], k4[cur][2], k4[cur][3]);
            }
        }

        // ---- online softmax: raw max, exp2, mask after exp
        float mx0 = -1e30f, mx1 = -1e30f;
#pragma unroll
        for (int n = 0; n < 8; n++) {
            mx0 = fmaxf(mx0, fmaxf(s[n][0], s[n][1]));
            mx1 = fmaxf(mx1, fmaxf(s[n][2], s[n][3]));
        }
        mx0 = fmaxf(mx0, __shfl_xor_sync(0xffffffffu, mx0, 1));
        mx0 = fmaxf(mx0, __shfl_xor_sync(0xffffffffu, mx0, 2));
        mx1 = fmaxf(mx1, __shfl_xor_sync(0xffffffffu, mx1, 1));
        mx1 = fmaxf(mx1, __shfl_xor_sync(0xffffffffu, mx1, 2));

        float mn0 = fmaxf(m0, mx0), mn1 = fmaxf(m1, mx1);
        float al0 = exp2f(m0 - mn0), al1 = exp2f(m1 - mn1);
        m0 = mn0; m1 = mn1;

        const uint2 w0 = Mb0[t];
        const uint2 w1 = Mb1[t];
        float rs0 = 0.f, rs1 = 0.f;
#pragma unroll
        for (int n = 0; n < 8; n++) {
            const uint32_t wa = (n < 4) ? w0.x : w0.y;
            const uint32_t wb = (n < 4) ? w1.x : w1.y;
            const int sh = (n & 3) * 8 + t4 * 2;
            float e0 = exp2f(s[n][0] - mn0);
            float e1 = exp2f(s[n][1] - mn0);
            float e2 = exp2f(s[n][2] - mn1);
            float e3 = exp2f(s[n][3] - mn1);
            s[n][0] = ((wa >> sh) & 1u)       ? e0 : 0.f;
            s[n][1] = ((wa >> (sh + 1)) & 1u) ? e1 : 0.f;
            s[n][2] = ((wb >> sh) & 1u)       ? e2 : 0.f;
            s[n][3] = ((wb >> (sh + 1)) & 1u) ? e3 : 0.f;
            rs0 += s[n][0] + s[n][1];
            rs1 += s[n][2] + s[n][3];
        }
        rs0 += __shfl_xor_sync(0xffffffffu, rs0, 1);
        rs0 += __shfl_xor_sync(0xffffffffu, rs0, 2);
        rs1 += __shfl_xor_sync(0xffffffffu, rs1, 1);
        rs1 += __shfl_xor_sync(0xffffffffu, rs1, 2);
        l0 = l0 * al0 + rs0;
        l1 = l1 * al1 + rs1;
#pragma unroll
        for (int n = 0; n < 8; n++) {
            o[n][0] *= al0; o[n][1] *= al0;
            o[n][2] *= al1; o[n][3] *= al1;
        }

        // ---- O += P @ V
        {
            auto vaddr = [&](int idx) {
                int ks = idx >> 2, ng = idx & 3;
                int vrow = ks * 16 + vrow_b;
                return st + FV + vrow * 128 + (((2 * ng + vchb) ^ (vrow & 7)) << 4);
            };
            uint32_t v4[2][4];
            LDSM4T(v4[0], vaddr(0));
            uint32_t p4[4];
#pragma unroll
            for (int idx = 0; idx < 16; idx++) {
                const int ks = idx >> 2, ng = idx & 3, cur = idx & 1;
                if (ng == 0) {
                    p4[0] = pack2h(s[2 * ks][0],     s[2 * ks][1]);
                    p4[1] = pack2h(s[2 * ks][2],     s[2 * ks][3]);
                    p4[2] = pack2h(s[2 * ks + 1][0], s[2 * ks + 1][1]);
                    p4[3] = pack2h(s[2 * ks + 1][2], s[2 * ks + 1][3]);
                }
                if (idx + 1 < 16) LDSM4T(v4[(idx + 1) & 1], vaddr(idx + 1));
                MMAF16(o[2 * ng],     p4, v4[cur][0], v4[cur][1]);
                MMAF16(o[2 * ng + 1], p4, v4[cur][2], v4[cur][3]);
            }
        }
    }

    const float inv0 = 1.f / l0, inv1 = 1.f / l1;
#pragma unroll
    for (int n = 0; n < 8; n++) {
        const int col = h * DH_ + n * 8 + t4 * 2;
        size_t o0 = ((size_t)(b * S_ + qr0)) * D_ + col;
        size_t o1 = o0 + (size_t)8 * D_;
        *(uint32_t*)(Of + o0) = pack2h(o[n][0] * inv0, o[n][1] * inv0);
        *(uint32_t*)(Of + o1) = pack2h(o[n][2] * inv1, o[n][3] * inv1);
    }
}

// ---------------------------------------------------------------------------
extern "C" void kernel_launch(void* const* d_in, const int* in_sizes, int n_in,
                              void* d_out, int out_size)
{
    (void)in_sizes; (void)n_in; (void)out_size;
    const float* q_tok  = (const float*)d_in[0];
    const float* kv_tok = (const float*)d_in[1];
    const int*   mask   = (const int*)d_in[2];
    const float* Wq = (const float*)d_in[3];
    const float* bq = (const float*)d_in[4];
    const float* Wk = (const float*)d_in[5];
    const float* bk = (const float*)d_in[6];
    const float* Wv = (const float*)d_in[7];
    const float* bv = (const float*)d_in[8];
    const float* Wo = (const float*)d_in[9];
    const float* bo = (const float*)d_in[10];
    float* out = (float*)d_out;

    __half *af, *bf, *wf, *qf, *kf, *vf, *cf;
    uint2* mb;
    cudaGetSymbolAddress((void**)&af, g_af);
    cudaGetSymbolAddress((void**)&bf, g_bf);
    cudaGetSymbolAddress((void**)&wf, g_wf);
    cudaGetSymbolAddress((void**)&qf, g_qf);
    cudaGetSymbolAddress((void**)&kf, g_kf);
    cudaGetSymbolAddress((void**)&vf, g_vf);
    cudaGetSymbolAddress((void**)&cf, g_cf);
    cudaGetSymbolAddress((void**)&mb, g_mb);

    cudaFuncSetAttribute(gemm_qkv_kernel,
                         cudaFuncAttributeMaxDynamicSharedMemorySize, GEMM_SMEM);
    cudaFuncSetAttribute(gemm_out_kernel,
                         cudaFuncAttributeMaxDynamicSharedMemorySize, GEMM_SMEM);
    cudaFuncSetAttribute(flash_mma_kernel,
                         cudaFuncAttributeMaxDynamicSharedMemorySize, FLASH_SMEM);

    const int nTok = M_ * D_;
    const int nW = D_ * D_;

    dim3 cgrid(nTok / 1024, 6);
    cvt_all_kernel<<<cgrid, 256>>>(q_tok, kv_tok, Wq, Wk, Wv, Wo,
                                   af, bf, wf, nTok, nW);
    pack_mask_kernel<<<M_ / 8, 256>>>(mask, mb);

    dim3 qkvgrid(D_ / 128, M_ / 128, 3);   // (8, 32, 3)
    gemm_qkv_kernel<<<qkvgrid, 256, GEMM_SMEM>>>(
        af, bf, wf, bq, bk, bv, qf, kf, vf);

    dim3 fgrid(H_, S_ / 128, B_);          // (16, 16, 2)
    flash_mma_kernel<<<fgrid, 256, FLASH_SMEM>>>(qf, kf, vf, mb, cf);

    dim3 ogrid(D_ / 128, M_ / 128);
    gemm_out_kernel<<<ogrid, 256, GEMM_SMEM>>>(
        cf, wf + 3 * (size_t)nW, bo, out);
}

// round 16
// speedup vs baseline: 6.8206x; 1.0566x over previous
#include <cuda_runtime.h>
#include <cuda_fp16.h>
#include <cstdint>

#define B_  2
#define S_  2048
#define D_  1024
#define H_  16
#define DH_ 64
#define M_  (B_*S_)   // 4096

// 0.125 * log2(e): folds score scale + exp->exp2 into Q projection output.
#define QSCALE 0.18033688011112042f

// ------------------------------ scratch (allocation-free rule) -------------
__device__ __half g_af[(size_t)M_ * D_];
__device__ __half g_bf[(size_t)M_ * D_];
__device__ __half g_wf[(size_t)4 * D_ * D_];
__device__ __half g_qf[(size_t)M_ * D_];
__device__ __half g_kf[(size_t)M_ * D_];
__device__ __half g_vf[(size_t)M_ * D_];
__device__ __half g_cf[(size_t)M_ * D_];
__device__ uint2  g_mb[(size_t)M_ * 32];

// ------------------------------ helpers ------------------------------------
__device__ __forceinline__ uint32_t smem_u32(const void* p) {
    uint32_t a;
    asm("{ .reg .u64 t; cvta.to.shared.u64 t, %1; cvt.u32.u64 %0, t; }"
        : "=r"(a) : "l"(p));
    return a;
}
__device__ __forceinline__ void cp16(uint32_t s, const void* g) {
    asm volatile("cp.async.cg.shared.global [%0], [%1], 16;" :: "r"(s), "l"(g));
}
#define CP_COMMIT() asm volatile("cp.async.commit_group;" ::: "memory")
#define CP_WAIT1()  asm volatile("cp.async.wait_group 1;" ::: "memory")

#define LDSM4(r, addr) \
    asm volatile("ldmatrix.sync.aligned.m8n8.x4.shared.b16 {%0,%1,%2,%3}, [%4];" \
        : "=r"((r)[0]), "=r"((r)[1]), "=r"((r)[2]), "=r"((r)[3]) : "r"(addr))

#define LDSM4T(r, addr) \
    asm volatile("ldmatrix.sync.aligned.m8n8.x4.trans.shared.b16 {%0,%1,%2,%3}, [%4];" \
        : "=r"((r)[0]), "=r"((r)[1]), "=r"((r)[2]), "=r"((r)[3]) : "r"(addr))

#define MMAF16(d, a, b0, b1) \
    asm volatile("mma.sync.aligned.m16n8k16.row.col.f32.f16.f16.f32 " \
        "{%0,%1,%2,%3}, {%4,%5,%6,%7}, {%8,%9}, {%0,%1,%2,%3};" \
        : "+f"((d)[0]), "+f"((d)[1]), "+f"((d)[2]), "+f"((d)[3]) \
        : "r"((a)[0]), "r"((a)[1]), "r"((a)[2]), "r"((a)[3]), "r"(b0), "r"(b1))

__device__ __forceinline__ uint32_t pack2h(float x, float y) {
    __half2 hh = __floats2half2_rn(x, y);
    return *(uint32_t*)&hh;
}
// Single-MUFU base-2 exponential (guaranteed, independent of fast-math flags)
__device__ __forceinline__ float ex2(float x) {
    float y;
    asm("ex2.approx.ftz.f32 %0, %1;" : "=f"(y) : "f"(x));
    return y;
}

// ------------------------------ fused convert kernel ------------------------
__global__ void __launch_bounds__(256) cvt_all_kernel(
    const float* __restrict__ q, const float* __restrict__ kv,
    const float* __restrict__ w0, const float* __restrict__ w1,
    const float* __restrict__ w2, const float* __restrict__ w3,
    __half* __restrict__ af, __half* __restrict__ bf,
    __half* __restrict__ wf, int nTok, int nW)
{
    const int seg = blockIdx.y;
    const float* src;
    __half* dst;
    int n;
    if (seg == 0)      { src = q;  dst = af; n = nTok; }
    else if (seg == 1) { src = kv; dst = bf; n = nTok; }
    else {
        src = (seg == 2) ? w0 : (seg == 3) ? w1 : (seg == 4) ? w2 : w3;
        dst = wf + (size_t)(seg - 2) * nW;
        n = nW;
    }
    int i = (blockIdx.x * 256 + threadIdx.x) * 4;
    if (i >= n) return;
    float4 v = *(const float4*)(src + i);
    *(uint2*)((char*)dst + (size_t)i * 2) =
        make_uint2(pack2h(v.x, v.y), pack2h(v.z, v.w));
}

__global__ void __launch_bounds__(256) pack_mask_kernel(
    const int* __restrict__ mask, uint2* __restrict__ bits)
{
    int warp = (blockIdx.x * 256 + threadIdx.x) >> 5;
    int lane = threadIdx.x & 31;
    if (warp >= M_) return;
    const int* mrow = mask + (size_t)warp * S_;
#pragma unroll 4
    for (int c = 0; c < 32; c++) {
        int m0 = mrow[c * 64 + lane];
        int m1 = mrow[c * 64 + 32 + lane];
        uint32_t b0 = __ballot_sync(0xffffffffu, m0 != 0);
        uint32_t b1 = __ballot_sync(0xffffffffu, m1 != 0);
        if (lane == 0) bits[(size_t)warp * 32 + c] = make_uint2(b0, b1);
    }
}

// ------------------------------ fp16 GEMM body (3-stage cp.async, 1-pass) --
#define GS_A  0
#define GS_W  8192
#define GSTG  16384
#define GEMM_SMEM (3 * GSTG)   // 49152

__device__ __forceinline__ void gemm_body(
    char* sm,
    const __half* __restrict__ A, const __half* __restrict__ W,
    const float* __restrict__ bias, int omode, float oscale,
    float* __restrict__ Cf, __half* __restrict__ Fh, int bm, int bn)
{
    const uint32_t sb = smem_u32(sm);
    const int tid = threadIdx.x;
    const int wid = tid >> 5, lane = tid & 31;
    const int wm = wid >> 2, wn = wid & 3;

    const int lrow = (lane & 7) + ((lane >> 3) & 1) * 8;
    const int lcb  = lane >> 4;

    float acc[4][4][4];
#pragma unroll
    for (int mt = 0; mt < 4; mt++)
#pragma unroll
        for (int nt = 0; nt < 4; nt++)
#pragma unroll
            for (int e = 0; e < 4; e++) acc[mt][nt][e] = 0.f;

    auto issue = [&](int t) {
        uint32_t st = sb + (uint32_t)(t % 3) * GSTG;
#pragma unroll
        for (int i = 0; i < 2; i++) {
            int f = tid + i * 256;
            int r = f >> 2, cb = f & 3;
            size_t gA = (size_t)(bm + r) * D_ + t * 32 + cb * 8;
            size_t gW = (size_t)(bn + r) * D_ + t * 32 + cb * 8;
            uint32_t so = r * 64 + ((cb ^ ((r >> 1) & 3)) << 4);
            cp16(st + GS_A + so, A + gA);
            cp16(st + GS_W + so, W + gW);
        }
    };

    issue(0); CP_COMMIT();
    issue(1); CP_COMMIT();

    for (int t = 0; t < 32; t++) {
        CP_WAIT1();
        __syncthreads();
        if (t + 2 < 32) issue(t + 2);
        CP_COMMIT();
        const uint32_t st = sb + (uint32_t)(t % 3) * GSTG;

        uint32_t a4[2][4][4], w2[2][2][4];
#pragma unroll
        for (int ks = 0; ks < 2; ks++) {
            const int cb = ks * 2 + lcb;
#pragma unroll
            for (int mt = 0; mt < 4; mt++) {
                int r = wm * 64 + mt * 16 + lrow;
                uint32_t ad = st + r * 64 + ((cb ^ ((r >> 1) & 3)) << 4);
                LDSM4(a4[ks][mt], ad + GS_A);
            }
#pragma unroll
            for (int p = 0; p < 2; p++) {
                int r = wn * 32 + p * 16 + lrow;
                uint32_t ad = st + r * 64 + ((cb ^ ((r >> 1) & 3)) << 4);
                LDSM4(w2[ks][p], ad + GS_W);
            }
        }
#pragma unroll
        for (int ks = 0; ks < 2; ks++)
#pragma unroll
            for (int mt = 0; mt < 4; mt++)
#pragma unroll
                for (int nt = 0; nt < 4; nt++)
                    MMAF16(acc[mt][nt], a4[ks][mt],
                           w2[ks][nt >> 1][nt & 1], w2[ks][nt >> 1][(nt & 1) + 2]);
    }

    const int g = lane >> 2, tig = lane & 3;
#pragma unroll
    for (int mt = 0; mt < 4; mt++) {
#pragma unroll
        for (int nt = 0; nt < 4; nt++) {
            int row = bm + wm * 64 + mt * 16 + g;
            int col = bn + wn * 32 + nt * 8 + tig * 2;
            float2 bv = *(const float2*)&bias[col];
            float v00 = (acc[mt][nt][0] + bv.x) * oscale;
            float v01 = (acc[mt][nt][1] + bv.y) * oscale;
            float v10 = (acc[mt][nt][2] + bv.x) * oscale;
            float v11 = (acc[mt][nt][3] + bv.y) * oscale;
            if (omode == 0) {
                *(float2*)(Cf + (size_t)row * D_ + col) = make_float2(v00, v01);
                *(float2*)(Cf + (size_t)(row + 8) * D_ + col) = make_float2(v10, v11);
            } else {
                *(uint32_t*)(Fh + (size_t)row * D_ + col) = pack2h(v00, v01);
                *(uint32_t*)(Fh + (size_t)(row + 8) * D_ + col) = pack2h(v10, v11);
            }
        }
    }
}

__global__ void __launch_bounds__(256, 2) gemm_qkv_kernel(
    const __half* __restrict__ af, const __half* __restrict__ bf,
    const __half* __restrict__ wf,
    const float* __restrict__ bq, const float* __restrict__ bk,
    const float* __restrict__ bv,
    __half* __restrict__ qf, __half* __restrict__ kf, __half* __restrict__ vf)
{
    extern __shared__ char sm[];
    const int z = blockIdx.z;
    const __half* A = (z == 0) ? af : bf;
    const __half* W = wf + (size_t)z * D_ * D_;
    const float* bias = (z == 0) ? bq : (z == 1) ? bk : bv;
    __half* Fh = (z == 0) ? qf : (z == 1) ? kf : vf;
    const float oscale = (z == 0) ? QSCALE : 1.f;
    gemm_body(sm, A, W, bias, 3, oscale, nullptr, Fh,
              blockIdx.y * 128, blockIdx.x * 128);
}

__global__ void __launch_bounds__(256, 2) gemm_out_kernel(
    const __half* __restrict__ A, const __half* __restrict__ W,
    const float* __restrict__ bias, float* __restrict__ Cf)
{
    extern __shared__ char sm[];
    gemm_body(sm, A, W, bias, 0, 1.f, Cf, nullptr,
              blockIdx.y * 128, blockIdx.x * 128);
}

// ------------------------------ fp16 flash attention (1-pass, 3-stage) -----
#define FQ  0
#define FSB 16384
#define FK  0
#define FV  8192
#define FSTG 16384
#define FLASH_SMEM (FSB + 3 * FSTG)   // 65536

__global__ void __launch_bounds__(256, 2) flash_mma_kernel(
    const __half* __restrict__ Qf_,
    const __half* __restrict__ Kf_, const __half* __restrict__ Vf_,
    const uint2* __restrict__ mbits, __half* __restrict__ Of)
{
    extern __shared__ char sm[];
    const uint32_t sb = smem_u32(sm);
    const int tid = threadIdx.x, wid = tid >> 5, lane = tid & 31;
    const int h = blockIdx.x, qt = blockIdx.y, b = blockIdx.z;
    const int qbase = qt * 128;
    const int g = lane >> 2, t4 = lane & 3;

    auto issue_kv = [&](int t) {
        uint32_t st = sb + FSB + (uint32_t)(t % 3) * FSTG;
#pragma unroll
        for (int i = 0; i < 2; i++) {
            int f = tid + i * 256;
            int r = f >> 3, c = f & 7;
            size_t go = ((size_t)(b * S_ + t * 64 + r)) * D_ + h * DH_ + c * 8;
            uint32_t so = r * 128 + ((c ^ (r & 7)) << 4);
            cp16(st + FK + so, Kf_ + go);
            cp16(st + FV + so, Vf_ + go);
        }
    };

    issue_kv(0); CP_COMMIT();
    issue_kv(1); CP_COMMIT();

#pragma unroll
    for (int i = 0; i < 4; i++) {
        int f = tid + i * 256;
        int r = f >> 3, c = f & 7;
        size_t go = ((size_t)(b * S_ + qbase + r)) * D_ + h * DH_ + c * 8;
        uint32_t so = r * 128 + ((c ^ (r & 7)) << 4);
        *(uint4*)(sm + FQ + so) = *(const uint4*)(Qf_ + go);
    }
    __syncthreads();

    uint32_t qf[4][4];
    {
        const int lrow = wid * 16 + ((lane >> 3) & 1) * 8 + (lane & 7);
        const int lcb  = lane >> 4;
#pragma unroll
        for (int ks = 0; ks < 4; ks++) {
            uint32_t ad = sb + FQ + lrow * 128 + (((2 * ks + lcb) ^ (lrow & 7)) << 4);
            LDSM4(qf[ks], ad);
        }
    }

    float o[8][4];
#pragma unroll
    for (int n = 0; n < 8; n++)
#pragma unroll
        for (int e = 0; e < 4; e++) o[n][e] = 0.f;
    float m0 = -1e30f, m1 = -1e30f, l0 = 0.f, l1 = 0.f;

    const int qr0 = qbase + wid * 16 + g;
    const uint2* Mb0 = mbits + ((size_t)b * S_ + qr0) * 32;
    const uint2* Mb1 = Mb0 + (size_t)8 * 32;

    // Hoisted LDSM address algebra (16 == 0 mod 8, so the swizzle XOR term
    // is independent of the ng*16 row step).
    const int krow = ((lane >> 4) << 3) + (lane & 7);
    const int kchb = (lane >> 3) & 1;
    const uint32_t kbase = FK + (uint32_t)krow * 128;
    uint32_t kxor[4];
#pragma unroll
    for (int ks = 0; ks < 4; ks++)
        kxor[ks] = (uint32_t)(((2 * ks + kchb) ^ (krow & 7)) << 4);

    const int vrow_b = ((lane >> 3) & 1) * 8 + (lane & 7);
    const int vchb   = lane >> 4;
    uint32_t vbase[4], vxor[4];
#pragma unroll
    for (int i = 0; i < 4; i++) {
        int vrow = i * 16 + vrow_b;                 // i = ks
        vbase[i] = FV + (uint32_t)vrow * 128;
        vxor[i]  = (uint32_t)(vrow & 7);            // xor row component
    }

    for (int t = 0; t < S_ / 64; t++) {
        CP_WAIT1();
        __syncthreads();
        if (t + 2 < S_ / 64) issue_kv(t + 2);
        CP_COMMIT();
        const uint32_t st = sb + FSB + (uint32_t)(t % 3) * FSTG;

        // ---- S = Q @ K^T
        float s[8][4];
#pragma unroll
        for (int n = 0; n < 8; n++)
#pragma unroll
            for (int e = 0; e < 4; e++) s[n][e] = 0.f;

        {
            uint32_t k4[2][4];
            LDSM4(k4[0], st + kbase + kxor[0]);
#pragma unroll
            for (int idx = 0; idx < 16; idx++) {
                if (idx + 1 < 16) {
                    const int nks = (idx + 1) >> 2, nng = (idx + 1) & 3;
                    LDSM4(k4[(idx + 1) & 1], st + kbase + nng * 2048 + kxor[nks]);
                }
                const int ks = idx >> 2, ng = idx & 3, cur = idx & 1;
                MMAF16(s[2 * ng],     qf[ks], k4[cur][0], k4[cur][1]);
                MMAF16(s[2 * ng + 1], qf[ks], k4[cur][2], k4[cur][3]);
            }
        }

        // ---- online softmax: raw max, ex2 (MUFU), mask-after-exp fast path
        float mx0 = -1e30f, mx1 = -1e30f;
#pragma unroll
        for (int n = 0; n < 8; n++) {
            mx0 = fmaxf(mx0, fmaxf(s[n][0], s[n][1]));
            mx1 = fmaxf(mx1, fmaxf(s[n][2], s[n][3]));
        }
        mx0 = fmaxf(mx0, __shfl_xor_sync(0xffffffffu, mx0, 1));
        mx0 = fmaxf(mx0, __shfl_xor_sync(0xffffffffu, mx0, 2));
        mx1 = fmaxf(mx1, __shfl_xor_sync(0xffffffffu, mx1, 1));
        mx1 = fmaxf(mx1, __shfl_xor_sync(0xffffffffu, mx1, 2));

        float mn0 = fmaxf(m0, mx0), mn1 = fmaxf(m1, mx1);
        float al0 = ex2(m0 - mn0), al1 = ex2(m1 - mn1);
        m0 = mn0; m1 = mn1;

        const uint2 w0 = Mb0[t];
        const uint2 w1 = Mb1[t];
        const bool need_mask =
            (w0.x & w0.y & w1.x & w1.y) != 0xffffffffu;

        float rs0 = 0.f, rs1 = 0.f;
        if (!need_mask) {
#pragma unroll
            for (int n = 0; n < 8; n++) {
                s[n][0] = ex2(s[n][0] - mn0);
                s[n][1] = ex2(s[n][1] - mn0);
                s[n][2] = ex2(s[n][2] - mn1);
                s[n][3] = ex2(s[n][3] - mn1);
                rs0 += s[n][0] + s[n][1];
                rs1 += s[n][2] + s[n][3];
            }
        } else {
#pragma unroll
            for (int n = 0; n < 8; n++) {
                const uint32_t wa = (n < 4) ? w0.x : w0.y;
                const uint32_t wb = (n < 4) ? w1.x : w1.y;
                const int sh = (n & 3) * 8 + t4 * 2;
                float e0 = ex2(s[n][0] - mn0);
                float e1 = ex2(s[n][1] - mn0);
                float e2 = ex2(s[n][2] - mn1);
                float e3 = ex2(s[n][3] - mn1);
                s[n][0] = ((wa >> sh) & 1u)       ? e0 : 0.f;
                s[n][1] = ((wa >> (sh + 1)) & 1u) ? e1 : 0.f;
                s[n][2] = ((wb >> sh) & 1u)       ? e2 : 0.f;
                s[n][3] = ((wb >> (sh + 1)) & 1u) ? e3 : 0.f;
                rs0 += s[n][0] + s[n][1];
                rs1 += s[n][2] + s[n][3];
            }
        }
        rs0 += __shfl_xor_sync(0xffffffffu, rs0, 1);
        rs0 += __shfl_xor_sync(0xffffffffu, rs0, 2);
        rs1 += __shfl_xor_sync(0xffffffffu, rs1, 1);
        rs1 += __shfl_xor_sync(0xffffffffu, rs1, 2);
        l0 = l0 * al0 + rs0;
        l1 = l1 * al1 + rs1;
#pragma unroll
        for (int n = 0; n < 8; n++) {
            o[n][0] *= al0; o[n][1] *= al0;
            o[n][2] *= al1; o[n][3] *= al1;
        }

        // ---- O += P @ V
        {
            uint32_t v4[2][4];
            LDSM4T(v4[0], st + vbase[0] + (((0 + vchb) ^ vxor[0]) << 4));
            uint32_t p4[4];
#pragma unroll
            for (int idx = 0; idx < 16; idx++) {
                const int ks = idx >> 2, ng = idx & 3, cur = idx & 1;
                if (ng == 0) {
                    p4[0] = pack2h(s[2 * ks][0],     s[2 * ks][1]);
                    p4[1] = pack2h(s[2 * ks][2],     s[2 * ks][3]);
                    p4[2] = pack2h(s[2 * ks + 1][0], s[2 * ks + 1][1]);
                    p4[3] = pack2h(s[2 * ks + 1][2], s[2 * ks + 1][3]);
                }
                if (idx + 1 < 16) {
                    const int nks = (idx + 1) >> 2, nng = (idx + 1) & 3;
                    LDSM4T(v4[(idx + 1) & 1],
                           st + vbase[nks] + (((2 * nng + vchb) ^ vxor[nks]) << 4));
                }
                MMAF16(o[2 * ng],     p4, v4[cur][0], v4[cur][1]);
                MMAF16(o[2 * ng + 1], p4, v4[cur][2], v4[cur][3]);
            }
        }
    }

    const float inv0 = 1.f / l0, inv1 = 1.f / l1;
#pragma unroll
    for (int n = 0; n < 8; n++) {
        const int col = h * DH_ + n * 8 + t4 * 2;
        size_t o0 = ((size_t)(b * S_ + qr0)) * D_ + col;
        size_t o1 = o0 + (size_t)8 * D_;
        *(uint32_t*)(Of + o0) = pack2h(o[n][0] * inv0, o[n][1] * inv0);
        *(uint32_t*)(Of + o1) = pack2h(o[n][2] * inv1, o[n][3] * inv1);
    }
}

// ---------------------------------------------------------------------------
extern "C" void kernel_launch(void* const* d_in, const int* in_sizes, int n_in,
                              void* d_out, int out_size)
{
    (void)in_sizes; (void)n_in; (void)out_size;
    const float* q_tok  = (const float*)d_in[0];
    const float* kv_tok = (const float*)d_in[1];
    const int*   mask   = (const int*)d_in[2];
    const float* Wq = (const float*)d_in[3];
    const float* bq = (const float*)d_in[4];
    const float* Wk = (const float*)d_in[5];
    const float* bk = (const float*)d_in[6];
    const float* Wv = (const float*)d_in[7];
    const float* bv = (const float*)d_in[8];
    const float* Wo = (const float*)d_in[9];
    const float* bo = (const float*)d_in[10];
    float* out = (float*)d_out;

    __half *af, *bf, *wf, *qf, *kf, *vf, *cf;
    uint2* mb;
    cudaGetSymbolAddress((void**)&af, g_af);
    cudaGetSymbolAddress((void**)&bf, g_bf);
    cudaGetSymbolAddress((void**)&wf, g_wf);
    cudaGetSymbolAddress((void**)&qf, g_qf);
    cudaGetSymbolAddress((void**)&kf, g_kf);
    cudaGetSymbolAddress((void**)&vf, g_vf);
    cudaGetSymbolAddress((void**)&cf, g_cf);
    cudaGetSymbolAddress((void**)&mb, g_mb);

    cudaFuncSetAttribute(gemm_qkv_kernel,
                         cudaFuncAttributeMaxDynamicSharedMemorySize, GEMM_SMEM);
    cudaFuncSetAttribute(gemm_out_kernel,
                         cudaFuncAttributeMaxDynamicSharedMemorySize, GEMM_SMEM);
    cudaFuncSetAttribute(flash_mma_kernel,
                         cudaFuncAttributeMaxDynamicSharedMemorySize, FLASH_SMEM);

    const int nTok = M_ * D_;
    const int nW = D_ * D_;

    dim3 cgrid(nTok / 1024, 6);
    cvt_all_kernel<<<cgrid, 256>>>(q_tok, kv_tok, Wq, Wk, Wv, Wo,
                                   af, bf, wf, nTok, nW);
    pack_mask_kernel<<<M_ / 8, 256>>>(mask, mb);

    dim3 qkvgrid(D_ / 128, M_ / 128, 3);   // (8, 32, 3)
    gemm_qkv_kernel<<<qkvgrid, 256, GEMM_SMEM>>>(
        af, bf, wf, bq, bk, bv, qf, kf, vf);

    dim3 fgrid(H_, S_ / 128, B_);          // (16, 16, 2)
    flash_mma_kernel<<<fgrid, 256, FLASH_SMEM>>>(qf, kf, vf, mb, cf);

    dim3 ogrid(D_ / 128, M_ / 128);
    gemm_out_kernel<<<ogrid, 256, GEMM_SMEM>>>(
        cf, wf + 3 * (size_t)nW, bo, out);
}

// round 17
// speedup vs baseline: 7.0275x; 1.0303x over previous
#include <cuda_runtime.h>
#include <cuda_fp16.h>
#include <cstdint>

#define B_  2
#define S_  2048
#define D_  1024
#define H_  16
#define DH_ 64
#define M_  (B_*S_)   // 4096

// 0.125 * log2(e): folds score scale + exp->exp2 into Q projection output.
#define QSCALE 0.18033688011112042f

// ------------------------------ scratch (allocation-free rule) -------------
__device__ __half g_af[(size_t)M_ * D_];
__device__ __half g_bf[(size_t)M_ * D_];
__device__ __half g_wf[(size_t)4 * D_ * D_];
__device__ __half g_qf[(size_t)M_ * D_];
__device__ __half g_kf[(size_t)M_ * D_];
__device__ __half g_vf[(size_t)M_ * D_];
__device__ __half g_cf[(size_t)M_ * D_];
__device__ uint2  g_mb[(size_t)M_ * 32];

// ------------------------------ helpers ------------------------------------
__device__ __forceinline__ uint32_t smem_u32(const void* p) {
    uint32_t a;
    asm("{ .reg .u64 t; cvta.to.shared.u64 t, %1; cvt.u32.u64 %0, t; }"
        : "=r"(a) : "l"(p));
    return a;
}
__device__ __forceinline__ void cp16(uint32_t s, const void* g) {
    asm volatile("cp.async.cg.shared.global [%0], [%1], 16;" :: "r"(s), "l"(g));
}
#define CP_COMMIT() asm volatile("cp.async.commit_group;" ::: "memory")
#define CP_WAIT1()  asm volatile("cp.async.wait_group 1;" ::: "memory")

#define LDSM4(r, addr) \
    asm volatile("ldmatrix.sync.aligned.m8n8.x4.shared.b16 {%0,%1,%2,%3}, [%4];" \
        : "=r"((r)[0]), "=r"((r)[1]), "=r"((r)[2]), "=r"((r)[3]) : "r"(addr))

#define LDSM4T(r, addr) \
    asm volatile("ldmatrix.sync.aligned.m8n8.x4.trans.shared.b16 {%0,%1,%2,%3}, [%4];" \
        : "=r"((r)[0]), "=r"((r)[1]), "=r"((r)[2]), "=r"((r)[3]) : "r"(addr))

#define MMAF16(d, a, b0, b1) \
    asm volatile("mma.sync.aligned.m16n8k16.row.col.f32.f16.f16.f32 " \
        "{%0,%1,%2,%3}, {%4,%5,%6,%7}, {%8,%9}, {%0,%1,%2,%3};" \
        : "+f"((d)[0]), "+f"((d)[1]), "+f"((d)[2]), "+f"((d)[3]) \
        : "r"((a)[0]), "r"((a)[1]), "r"((a)[2]), "r"((a)[3]), "r"(b0), "r"(b1))

__device__ __forceinline__ uint32_t pack2h(float x, float y) {
    __half2 hh = __floats2half2_rn(x, y);
    return *(uint32_t*)&hh;
}
__device__ __forceinline__ float ex2(float x) {
    float y;
    asm("ex2.approx.ftz.f32 %0, %1;" : "=f"(y) : "f"(x));
    return y;
}

// ------------------------------ fused convert kernel ------------------------
__global__ void __launch_bounds__(256) cvt_all_kernel(
    const float* __restrict__ q, const float* __restrict__ kv,
    const float* __restrict__ w0, const float* __restrict__ w1,
    const float* __restrict__ w2, const float* __restrict__ w3,
    __half* __restrict__ af, __half* __restrict__ bf,
    __half* __restrict__ wf, int nTok, int nW)
{
    const int seg = blockIdx.y;
    const float* src;
    __half* dst;
    int n;
    if (seg == 0)      { src = q;  dst = af; n = nTok; }
    else if (seg == 1) { src = kv; dst = bf; n = nTok; }
    else {
        src = (seg == 2) ? w0 : (seg == 3) ? w1 : (seg == 4) ? w2 : w3;
        dst = wf + (size_t)(seg - 2) * nW;
        n = nW;
    }
    int i = (blockIdx.x * 256 + threadIdx.x) * 4;
    if (i >= n) return;
    float4 v = *(const float4*)(src + i);
    *(uint2*)((char*)dst + (size_t)i * 2) =
        make_uint2(pack2h(v.x, v.y), pack2h(v.z, v.w));
}

__global__ void __launch_bounds__(256) pack_mask_kernel(
    const int* __restrict__ mask, uint2* __restrict__ bits)
{
    int warp = (blockIdx.x * 256 + threadIdx.x) >> 5;
    int lane = threadIdx.x & 31;
    if (warp >= M_) return;
    const int* mrow = mask + (size_t)warp * S_;
#pragma unroll 4
    for (int c = 0; c < 32; c++) {
        int m0 = mrow[c * 64 + lane];
        int m1 = mrow[c * 64 + 32 + lane];
        uint32_t b0 = __ballot_sync(0xffffffffu, m0 != 0);
        uint32_t b1 = __ballot_sync(0xffffffffu, m1 != 0);
        if (lane == 0) bits[(size_t)warp * 32 + c] = make_uint2(b0, b1);
    }
}

// ------------------------------ fp16 GEMM body (3-stage cp.async, 1-pass) --
#define GS_A  0
#define GS_W  8192
#define GSTG  16384
#define GEMM_SMEM (3 * GSTG)   // 49152

__device__ __forceinline__ void gemm_body(
    char* sm,
    const __half* __restrict__ A, const __half* __restrict__ W,
    const float* __restrict__ bias, int omode, float oscale,
    float* __restrict__ Cf, __half* __restrict__ Fh, int bm, int bn)
{
    const uint32_t sb = smem_u32(sm);
    const int tid = threadIdx.x;
    const int wid = tid >> 5, lane = tid & 31;
    const int wm = wid >> 2, wn = wid & 3;

    const int lrow = (lane & 7) + ((lane >> 3) & 1) * 8;
    const int lcb  = lane >> 4;

    float acc[4][4][4];
#pragma unroll
    for (int mt = 0; mt < 4; mt++)
#pragma unroll
        for (int nt = 0; nt < 4; nt++)
#pragma unroll
            for (int e = 0; e < 4; e++) acc[mt][nt][e] = 0.f;

    auto issue = [&](int t) {
        uint32_t st = sb + (uint32_t)(t % 3) * GSTG;
#pragma unroll
        for (int i = 0; i < 2; i++) {
            int f = tid + i * 256;
            int r = f >> 2, cb = f & 3;
            size_t gA = (size_t)(bm + r) * D_ + t * 32 + cb * 8;
            size_t gW = (size_t)(bn + r) * D_ + t * 32 + cb * 8;
            uint32_t so = r * 64 + ((cb ^ ((r >> 1) & 3)) << 4);
            cp16(st + GS_A + so, A + gA);
            cp16(st + GS_W + so, W + gW);
        }
    };

    issue(0); CP_COMMIT();
    issue(1); CP_COMMIT();

    for (int t = 0; t < 32; t++) {
        CP_WAIT1();
        __syncthreads();
        if (t + 2 < 32) issue(t + 2);
        CP_COMMIT();
        const uint32_t st = sb + (uint32_t)(t % 3) * GSTG;

        uint32_t a4[2][4][4], w2[2][2][4];
#pragma unroll
        for (int ks = 0; ks < 2; ks++) {
            const int cb = ks * 2 + lcb;
#pragma unroll
            for (int mt = 0; mt < 4; mt++) {
                int r = wm * 64 + mt * 16 + lrow;
                uint32_t ad = st + r * 64 + ((cb ^ ((r >> 1) & 3)) << 4);
                LDSM4(a4[ks][mt], ad + GS_A);
            }
#pragma unroll
            for (int p = 0; p < 2; p++) {
                int r = wn * 32 + p * 16 + lrow;
                uint32_t ad = st + r * 64 + ((cb ^ ((r >> 1) & 3)) << 4);
                LDSM4(w2[ks][p], ad + GS_W);
            }
        }
#pragma unroll
        for (int ks = 0; ks < 2; ks++)
#pragma unroll
            for (int mt = 0; mt < 4; mt++)
#pragma unroll
                for (int nt = 0; nt < 4; nt++)
                    MMAF16(acc[mt][nt], a4[ks][mt],
                           w2[ks][nt >> 1][nt & 1], w2[ks][nt >> 1][(nt & 1) + 2]);
    }

    const int g = lane >> 2, tig = lane & 3;
#pragma unroll
    for (int mt = 0; mt < 4; mt++) {
#pragma unroll
        for (int nt = 0; nt < 4; nt++) {
            int row = bm + wm * 64 + mt * 16 + g;
            int col = bn + wn * 32 + nt * 8 + tig * 2;
            float2 bv = *(const float2*)&bias[col];
            float v00 = (acc[mt][nt][0] + bv.x) * oscale;
            float v01 = (acc[mt][nt][1] + bv.y) * oscale;
            float v10 = (acc[mt][nt][2] + bv.x) * oscale;
            float v11 = (acc[mt][nt][3] + bv.y) * oscale;
            if (omode == 0) {
                *(float2*)(Cf + (size_t)row * D_ + col) = make_float2(v00, v01);
                *(float2*)(Cf + (size_t)(row + 8) * D_ + col) = make_float2(v10, v11);
            } else {
                *(uint32_t*)(Fh + (size_t)row * D_ + col) = pack2h(v00, v01);
                *(uint32_t*)(Fh + (size_t)(row + 8) * D_ + col) = pack2h(v10, v11);
            }
        }
    }
}

__global__ void __launch_bounds__(256, 2) gemm_qkv_kernel(
    const __half* __restrict__ af, const __half* __restrict__ bf,
    const __half* __restrict__ wf,
    const float* __restrict__ bq, const float* __restrict__ bk,
    const float* __restrict__ bv,
    __half* __restrict__ qf, __half* __restrict__ kf, __half* __restrict__ vf)
{
    extern __shared__ char sm[];
    const int z = blockIdx.z;
    const __half* A = (z == 0) ? af : bf;
    const __half* W = wf + (size_t)z * D_ * D_;
    const float* bias = (z == 0) ? bq : (z == 1) ? bk : bv;
    __half* Fh = (z == 0) ? qf : (z == 1) ? kf : vf;
    const float oscale = (z == 0) ? QSCALE : 1.f;
    gemm_body(sm, A, W, bias, 3, oscale, nullptr, Fh,
              blockIdx.y * 128, blockIdx.x * 128);
}

__global__ void __launch_bounds__(256, 2) gemm_out_kernel(
    const __half* __restrict__ A, const __half* __restrict__ W,
    const float* __restrict__ bias, float* __restrict__ Cf)
{
    extern __shared__ char sm[];
    gemm_body(sm, A, W, bias, 0, 1.f, Cf, nullptr,
              blockIdx.y * 128, blockIdx.x * 128);
}

// ------------------------------ fp16 flash attention ------------------------
// 4 warps / 128 threads per CTA; each warp owns 32 q rows (2 m-tiles of 16).
// Each K/V LDSM fragment now feeds 4 MMAs -> per-SM LDSM traffic halves.
#define FQ  0
#define FSB 16384
#define FK  0
#define FV  8192
#define FSTG 16384
#define FLASH_SMEM (FSB + 3 * FSTG)   // 65536
#define FTHREADS 128

__global__ void __launch_bounds__(FTHREADS, 2) flash_mma_kernel(
    const __half* __restrict__ Qf_,
    const __half* __restrict__ Kf_, const __half* __restrict__ Vf_,
    const uint2* __restrict__ mbits, __half* __restrict__ Of)
{
    extern __shared__ char sm[];
    const uint32_t sb = smem_u32(sm);
    const int tid = threadIdx.x, wid = tid >> 5, lane = tid & 31;
    const int h = blockIdx.x, qt = blockIdx.y, b = blockIdx.z;
    const int qbase = qt * 128;
    const int g = lane >> 2, t4 = lane & 3;

    auto issue_kv = [&](int t) {
        uint32_t st = sb + FSB + (uint32_t)(t % 3) * FSTG;
#pragma unroll
        for (int i = 0; i < 4; i++) {
            int f = tid + i * FTHREADS;
            int r = f >> 3, c = f & 7;
            size_t go = ((size_t)(b * S_ + t * 64 + r)) * D_ + h * DH_ + c * 8;
            uint32_t so = r * 128 + ((c ^ (r & 7)) << 4);
            cp16(st + FK + so, Kf_ + go);
            cp16(st + FV + so, Vf_ + go);
        }
    };

    issue_kv(0); CP_COMMIT();
    issue_kv(1); CP_COMMIT();

    // Q tile (128 x 64 fp16), swizzled 128B rows
#pragma unroll
    for (int i = 0; i < 8; i++) {
        int f = tid + i * FTHREADS;
        int r = f >> 3, c = f & 7;
        size_t go = ((size_t)(b * S_ + qbase + r)) * D_ + h * DH_ + c * 8;
        uint32_t so = r * 128 + ((c ^ (r & 7)) << 4);
        *(uint4*)(sm + FQ + so) = *(const uint4*)(Qf_ + go);
    }
    __syncthreads();

    // Persistent Q fragments: 2 m-tiles x 4 k-steps
    uint32_t qf[2][4][4];
#pragma unroll
    for (int mi = 0; mi < 2; mi++) {
        const int lrow = wid * 32 + mi * 16 + ((lane >> 3) & 1) * 8 + (lane & 7);
        const int lcb  = lane >> 4;
#pragma unroll
        for (int ks = 0; ks < 4; ks++) {
            uint32_t ad = sb + FQ + lrow * 128 + (((2 * ks + lcb) ^ (lrow & 7)) << 4);
            LDSM4(qf[mi][ks], ad);
        }
    }

    float o[2][8][4];
#pragma unroll
    for (int mi = 0; mi < 2; mi++)
#pragma unroll
        for (int n = 0; n < 8; n++)
#pragma unroll
            for (int e = 0; e < 4; e++) o[mi][n][e] = 0.f;
    float m0[2] = {-1e30f, -1e30f}, m1[2] = {-1e30f, -1e30f};
    float l0[2] = {0.f, 0.f}, l1[2] = {0.f, 0.f};

    const uint2* Mb0[2];
    const uint2* Mb1[2];
#pragma unroll
    for (int mi = 0; mi < 2; mi++) {
        const int qr = qbase + wid * 32 + mi * 16 + g;
        Mb0[mi] = mbits + ((size_t)b * S_ + qr) * 32;
        Mb1[mi] = Mb0[mi] + (size_t)8 * 32;
    }

    // Hoisted LDSM address algebra
    const int krow = ((lane >> 4) << 3) + (lane & 7);
    const int kchb = (lane >> 3) & 1;
    const uint32_t kbase = FK + (uint32_t)krow * 128;
    uint32_t kxor[4];
#pragma unroll
    for (int ks = 0; ks < 4; ks++)
        kxor[ks] = (uint32_t)(((2 * ks + kchb) ^ (krow & 7)) << 4);

    const int vrow_b = ((lane >> 3) & 1) * 8 + (lane & 7);
    const int vchb   = lane >> 4;
    uint32_t vbase[4], vxor[4];
#pragma unroll
    for (int i = 0; i < 4; i++) {
        int vrow = i * 16 + vrow_b;
        vbase[i] = FV + (uint32_t)vrow * 128;
        vxor[i]  = (uint32_t)(vrow & 7);
    }

    for (int t = 0; t < S_ / 64; t++) {
        CP_WAIT1();
        __syncthreads();
        if (t + 2 < S_ / 64) issue_kv(t + 2);
        CP_COMMIT();
        const uint32_t st = sb + FSB + (uint32_t)(t % 3) * FSTG;

        // ---- S = Q @ K^T (both m-tiles per K fragment)
        float s[2][8][4];
#pragma unroll
        for (int mi = 0; mi < 2; mi++)
#pragma unroll
            for (int n = 0; n < 8; n++)
#pragma unroll
                for (int e = 0; e < 4; e++) s[mi][n][e] = 0.f;

        {
            uint32_t k4[2][4];
            LDSM4(k4[0], st + kbase + kxor[0]);
#pragma unroll
            for (int idx = 0; idx < 16; idx++) {
                if (idx + 1 < 16) {
                    const int nks = (idx + 1) >> 2, nng = (idx + 1) & 3;
                    LDSM4(k4[(idx + 1) & 1], st + kbase + nng * 2048 + kxor[nks]);
                }
                const int ks = idx >> 2, ng = idx & 3, cur = idx & 1;
                MMAF16(s[0][2 * ng],     qf[0][ks], k4[cur][0], k4[cur][1]);
                MMAF16(s[0][2 * ng + 1], qf[0][ks], k4[cur][2], k4[cur][3]);
                MMAF16(s[1][2 * ng],     qf[1][ks], k4[cur][0], k4[cur][1]);
                MMAF16(s[1][2 * ng + 1], qf[1][ks], k4[cur][2], k4[cur][3]);
            }
        }

        // ---- online softmax per m-tile
        float al0[2], al1[2];
#pragma unroll
        for (int mi = 0; mi < 2; mi++) {
            float mx0 = -1e30f, mx1 = -1e30f;
#pragma unroll
            for (int n = 0; n < 8; n++) {
                mx0 = fmaxf(mx0, fmaxf(s[mi][n][0], s[mi][n][1]));
                mx1 = fmaxf(mx1, fmaxf(s[mi][n][2], s[mi][n][3]));
            }
            mx0 = fmaxf(mx0, __shfl_xor_sync(0xffffffffu, mx0, 1));
            mx0 = fmaxf(mx0, __shfl_xor_sync(0xffffffffu, mx0, 2));
            mx1 = fmaxf(mx1, __shfl_xor_sync(0xffffffffu, mx1, 1));
            mx1 = fmaxf(mx1, __shfl_xor_sync(0xffffffffu, mx1, 2));

            float mn0 = fmaxf(m0[mi], mx0), mn1 = fmaxf(m1[mi], mx1);
            al0[mi] = ex2(m0[mi] - mn0);
            al1[mi] = ex2(m1[mi] - mn1);
            m0[mi] = mn0; m1[mi] = mn1;

            const uint2 w0 = Mb0[mi][t];
            const uint2 w1 = Mb1[mi][t];
            const bool need_mask = (w0.x & w0.y & w1.x & w1.y) != 0xffffffffu;

            float rs0 = 0.f, rs1 = 0.f;
            if (!need_mask) {
#pragma unroll
                for (int n = 0; n < 8; n++) {
                    s[mi][n][0] = ex2(s[mi][n][0] - mn0);
                    s[mi][n][1] = ex2(s[mi][n][1] - mn0);
                    s[mi][n][2] = ex2(s[mi][n][2] - mn1);
                    s[mi][n][3] = ex2(s[mi][n][3] - mn1);
                    rs0 += s[mi][n][0] + s[mi][n][1];
                    rs1 += s[mi][n][2] + s[mi][n][3];
                }
            } else {
#pragma unroll
                for (int n = 0; n < 8; n++) {
                    const uint32_t wa = (n < 4) ? w0.x : w0.y;
                    const uint32_t wb = (n < 4) ? w1.x : w1.y;
                    const int sh = (n & 3) * 8 + t4 * 2;
                    float e0 = ex2(s[mi][n][0] - mn0);
                    float e1 = ex2(s[mi][n][1] - mn0);
                    float e2 = ex2(s[mi][n][2] - mn1);
                    float e3 = ex2(s[mi][n][3] - mn1);
                    s[mi][n][0] = ((wa >> sh) & 1u)       ? e0 : 0.f;
                    s[mi][n][1] = ((wa >> (sh + 1)) & 1u) ? e1 : 0.f;
                    s[mi][n][2] = ((wb >> sh) & 1u)       ? e2 : 0.f;
                    s[mi][n][3] = ((wb >> (sh + 1)) & 1u) ? e3 : 0.f;
                    rs0 += s[mi][n][0] + s[mi][n][1];
                    rs1 += s[mi][n][2] + s[mi][n][3];
                }
            }
            rs0 += __shfl_xor_sync(0xffffffffu, rs0, 1);
            rs0 += __shfl_xor_sync(0xffffffffu, rs0, 2);
            rs1 += __shfl_xor_sync(0xffffffffu, rs1, 1);
            rs1 += __shfl_xor_sync(0xffffffffu, rs1, 2);
            l0[mi] = l0[mi] * al0[mi] + rs0;
            l1[mi] = l1[mi] * al1[mi] + rs1;
#pragma unroll
            for (int n = 0; n < 8; n++) {
                o[mi][n][0] *= al0[mi]; o[mi][n][1] *= al0[mi];
                o[mi][n][2] *= al1[mi]; o[mi][n][3] *= al1[mi];
            }
        }

        // ---- O += P @ V (both m-tiles per V fragment)
        {
            uint32_t v4[2][4];
            LDSM4T(v4[0], st + vbase[0] + (((0 + vchb) ^ vxor[0]) << 4));
            uint32_t p4[2][4];
#pragma unroll
            for (int idx = 0; idx < 16; idx++) {
                const int ks = idx >> 2, ng = idx & 3, cur = idx & 1;
                if (ng == 0) {
#pragma unroll
                    for (int mi = 0; mi < 2; mi++) {
                        p4[mi][0] = pack2h(s[mi][2 * ks][0],     s[mi][2 * ks][1]);
                        p4[mi][1] = pack2h(s[mi][2 * ks][2],     s[mi][2 * ks][3]);
                        p4[mi][2] = pack2h(s[mi][2 * ks + 1][0], s[mi][2 * ks + 1][1]);
                        p4[mi][3] = pack2h(s[mi][2 * ks + 1][2], s[mi][2 * ks + 1][3]);
                    }
                }
                if (idx + 1 < 16) {
                    const int nks = (idx + 1) >> 2, nng = (idx + 1) & 3;
                    LDSM4T(v4[(idx + 1) & 1],
                           st + vbase[nks] + (((2 * nng + vchb) ^ vxor[nks]) << 4));
                }
                MMAF16(o[0][2 * ng],     p4[0], v4[cur][0], v4[cur][1]);
                MMAF16(o[0][2 * ng + 1], p4[0], v4[cur][2], v4[cur][3]);
                MMAF16(o[1][2 * ng],     p4[1], v4[cur][0], v4[cur][1]);
                MMAF16(o[1][2 * ng + 1], p4[1], v4[cur][2], v4[cur][3]);
            }
        }
    }

#pragma unroll
    for (int mi = 0; mi < 2; mi++) {
        const int qr = qbase + wid * 32 + mi * 16 + g;
        const float inv0 = 1.f / l0[mi], inv1 = 1.f / l1[mi];
#pragma unroll
        for (int n = 0; n < 8; n++) {
            const int col = h * DH_ + n * 8 + t4 * 2;
            size_t o0 = ((size_t)(b * S_ + qr)) * D_ + col;
            size_t o1 = o0 + (size_t)8 * D_;
            *(uint32_t*)(Of + o0) = pack2h(o[mi][n][0] * inv0, o[mi][n][1] * inv0);
            *(uint32_t*)(Of + o1) = pack2h(o[mi][n][2] * inv1, o[mi][n][3] * inv1);
        }
    }
}

// ---------------------------------------------------------------------------
extern "C" void kernel_launch(void* const* d_in, const int* in_sizes, int n_in,
                              void* d_out, int out_size)
{
    (void)in_sizes; (void)n_in; (void)out_size;
    const float* q_tok  = (const float*)d_in[0];
    const float* kv_tok = (const float*)d_in[1];
    const int*   mask   = (const int*)d_in[2];
    const float* Wq = (const float*)d_in[3];
    const float* bq = (const float*)d_in[4];
    const float* Wk = (const float*)d_in[5];
    const float* bk = (const float*)d_in[6];
    const float* Wv = (const float*)d_in[7];
    const float* bv = (const float*)d_in[8];
    const float* Wo = (const float*)d_in[9];
    const float* bo = (const float*)d_in[10];
    float* out = (float*)d_out;

    __half *af, *bf, *wf, *qf, *kf, *vf, *cf;
    uint2* mb;
    cudaGetSymbolAddress((void**)&af, g_af);
    cudaGetSymbolAddress((void**)&bf, g_bf);
    cudaGetSymbolAddress((void**)&wf, g_wf);
    cudaGetSymbolAddress((void**)&qf, g_qf);
    cudaGetSymbolAddress((void**)&kf, g_kf);
    cudaGetSymbolAddress((void**)&vf, g_vf);
    cudaGetSymbolAddress((void**)&cf, g_cf);
    cudaGetSymbolAddress((void**)&mb, g_mb);

    cudaFuncSetAttribute(gemm_qkv_kernel,
                         cudaFuncAttributeMaxDynamicSharedMemorySize, GEMM_SMEM);
    cudaFuncSetAttribute(gemm_out_kernel,
                         cudaFuncAttributeMaxDynamicSharedMemorySize, GEMM_SMEM);
    cudaFuncSetAttribute(flash_mma_kernel,
                         cudaFuncAttributeMaxDynamicSharedMemorySize, FLASH_SMEM);

    const int nTok = M_ * D_;
    const int nW = D_ * D_;

    dim3 cgrid(nTok / 1024, 6);
    cvt_all_kernel<<<cgrid, 256>>>(q_tok, kv_tok, Wq, Wk, Wv, Wo,
                                   af, bf, wf, nTok, nW);
    pack_mask_kernel<<<M_ / 8, 256>>>(mask, mb);

    dim3 qkvgrid(D_ / 128, M_ / 128, 3);   // (8, 32, 3)
    gemm_qkv_kernel<<<qkvgrid, 256, GEMM_SMEM>>>(
        af, bf, wf, bq, bk, bv, qf, kf, vf);

    dim3 fgrid(H_, S_ / 128, B_);          // (16, 16, 2)
    flash_mma_kernel<<<fgrid, FTHREADS, FLASH_SMEM>>>(qf, kf, vf, mb, cf);

    dim3 ogrid(D_ / 128, M_ / 128);
    gemm_out_kernel<<<ogrid, 256, GEMM_SMEM>>>(
        cf, wf + 3 * (size_t)nW, bo, out);
}